// round 1
// baseline (speedup 1.0000x reference)
#include <cuda_runtime.h>
#include <cuda_bf16.h>
#include <math.h>

// Problem constants
#define NB 4
#define LL 2048
#define CC 512
#define DIN 1024
#define DS 16
#define DCONV 4
#define DTR 32
#define NT (NB * LL)   // 8192 rows
#define EPSBN 1e-5f

// ---------------- scratch (device globals; no allocation allowed) -------------
__device__ float g_h  [NT * CC];        // 16 MB   relu(BN(x@W_in^T))
__device__ float g_xz [NT * 2 * DIN];   // 64 MB   in_proj output (xm | z)
__device__ float g_xc [NT * DIN];       // 32 MB   conv+silu output
__device__ float g_dbl[NT * (DTR+2*DS)];// 2 MB    x_proj output (dt_low|B|C)
__device__ float g_dt [NT * DIN];       // 32 MB   softplus(dt)
__device__ float g_y  [NT * DIN];       // 32 MB   scan output, gated
__device__ float g_o1 [NT * CC];        // 16 MB   out_proj output

// ---------------- generic tiled GEMM:  C[M,N] = epi( A[M,K] @ W[N,K]^T ) ------
// A rows optionally gathered through rowmap. lda allows strided sub-matrix A.
// epi: 0 = none
//      1 = BN(relu):   v=(v-mean)*rsqrt(var+eps)*gamma+beta; relu
//      2 = softplus(v + bias)
//      3 = BN, + addsrc[m*N+n], relu
#define BM 64
#define BN_ 64
#define BK 16

__global__ __launch_bounds__(256) void gemm_kernel(
    const float* __restrict__ A, int lda,
    const float* __restrict__ W,
    float* __restrict__ Cout,
    int M, int N, int K,
    const int* __restrict__ rowmap,
    int epi,
    const float* __restrict__ p0, const float* __restrict__ p1,
    const float* __restrict__ p2, const float* __restrict__ p3,
    const float* __restrict__ addsrc)
{
    __shared__ __align__(16) float As[BK][BM];
    __shared__ __align__(16) float Ws[BK][BN_];

    const int tid = threadIdx.x;
    const int tx = tid & 15;        // 0..15 -> n
    const int ty = tid >> 4;        // 0..15 -> m
    const int m0 = blockIdx.y * BM;
    const int n0 = blockIdx.x * BN_;

    float acc[4][4] = {};

    for (int k0 = 0; k0 < K; k0 += BK) {
        #pragma unroll
        for (int e = 0; e < 4; e++) {
            int idx  = tid + e * 256;          // 0..1023
            int loc  = idx >> 4;               // 0..63
            int kk   = idx & 15;
            int gm   = m0 + loc;
            int ar   = rowmap ? rowmap[gm] : gm;
            As[kk][loc] = A[(long)ar * lda + k0 + kk];
            Ws[kk][loc] = W[(long)(n0 + loc) * K + k0 + kk];
        }
        __syncthreads();
        #pragma unroll
        for (int kk = 0; kk < BK; kk++) {
            float4 av = *(const float4*)&As[kk][ty * 4];
            float4 wv = *(const float4*)&Ws[kk][tx * 4];
            float a[4] = {av.x, av.y, av.z, av.w};
            float w[4] = {wv.x, wv.y, wv.z, wv.w};
            #pragma unroll
            for (int i = 0; i < 4; i++)
                #pragma unroll
                for (int j = 0; j < 4; j++)
                    acc[i][j] = fmaf(a[i], w[j], acc[i][j]);
        }
        __syncthreads();
    }

    #pragma unroll
    for (int i = 0; i < 4; i++) {
        int m = m0 + ty * 4 + i;
        #pragma unroll
        for (int j = 0; j < 4; j++) {
            int n = n0 + tx * 4 + j;
            float v = acc[i][j];
            if (epi == 1) {
                v = (v - p2[n]) * rsqrtf(p3[n] + EPSBN) * p0[n] + p1[n];
                v = fmaxf(v, 0.f);
            } else if (epi == 2) {
                v += p0[n];
                v = (v > 20.f) ? v : log1pf(expf(v));
            } else if (epi == 3) {
                v = (v - p2[n]) * rsqrtf(p3[n] + EPSBN) * p0[n] + p1[n];
                v += addsrc[(long)m * N + n];
                v = fmaxf(v, 0.f);
            }
            Cout[(long)m * N + n] = v;
        }
    }
}

// ---------------- depthwise causal conv (width 4) + bias + silu ---------------
// xm = xz[:, 0:DIN]; output xc[row, d]
__global__ __launch_bounds__(256) void conv_silu_kernel(
    const float* __restrict__ xz,
    const float* __restrict__ cw,   // (DIN, 1, 4)
    const float* __restrict__ cb,
    float* __restrict__ xc)
{
    int idx = blockIdx.x * blockDim.x + threadIdx.x;  // over NT*DIN
    int d   = idx & (DIN - 1);
    int row = idx >> 10;
    int l   = row & (LL - 1);

    float acc = cb[d];
    #pragma unroll
    for (int j = 0; j < DCONV; j++) {
        int ls = l - (DCONV - 1) + j;
        if (ls >= 0)
            acc = fmaf(cw[d * DCONV + j],
                       xz[(long)(row - (DCONV - 1 - j)) * (2 * DIN) + d], acc);
    }
    // silu
    xc[idx] = acc / (1.f + expf(-acc));
}

// ---------------- selective scan + skip + gate --------------------------------
// grid (DIN/8, NB), block 128 = 8 d-channels x 16 states
__global__ __launch_bounds__(128) void scan_kernel(
    const float* __restrict__ dt,
    const float* __restrict__ dbl,
    const float* __restrict__ xc,
    const float* __restrict__ xz,
    const float* __restrict__ A_log,
    const float* __restrict__ Dp,
    float* __restrict__ y)
{
    const int b  = blockIdx.y;
    const int s  = threadIdx.x & 15;
    const int dl = threadIdx.x >> 4;
    const int d  = blockIdx.x * 8 + dl;

    const float Aa = -expf(A_log[d * DS + s]);
    const float Dd = Dp[d];

    float h = 0.f;
    const long base = (long)b * LL;

    for (int t = 0; t < LL; t++) {
        const long row = base + t;
        float dtv = dt[row * DIN + d];
        float uv  = xc[row * DIN + d];
        float Bv  = dbl[row * 64 + DTR + s];
        float Cv  = dbl[row * 64 + DTR + DS + s];

        float dA = expf(dtv * Aa);
        h = fmaf(dA, h, dtv * Bv * uv);

        float p = h * Cv;
        p += __shfl_xor_sync(0xffffffffu, p, 8, 16);
        p += __shfl_xor_sync(0xffffffffu, p, 4, 16);
        p += __shfl_xor_sync(0xffffffffu, p, 2, 16);
        p += __shfl_xor_sync(0xffffffffu, p, 1, 16);

        if (s == 0) {
            float zv  = xz[row * (2 * DIN) + DIN + d];
            float gate = zv / (1.f + expf(-zv));   // silu(z)
            y[row * DIN + d] = (p + uv * Dd) * gate;
        }
    }
}

// ---------------- launch -------------------------------------------------------
extern "C" void kernel_launch(void* const* d_in, const int* in_sizes, int n_in,
                              void* d_out, int out_size)
{
    // inputs per metadata order
    const float* x          = (const float*)d_in[1];
    const int*   order      = (const int*)  d_in[3];
    const int*   inv        = (const int*)  d_in[4];
    const float* W_in       = (const float*)d_in[5];
    const float* bn_in_g    = (const float*)d_in[6];
    const float* bn_in_b    = (const float*)d_in[7];
    const float* bn_in_m    = (const float*)d_in[8];
    const float* bn_in_v    = (const float*)d_in[9];
    const float* in_proj_w  = (const float*)d_in[10];
    const float* conv_w     = (const float*)d_in[11];
    const float* conv_b     = (const float*)d_in[12];
    const float* x_proj_w   = (const float*)d_in[13];
    const float* dt_proj_w  = (const float*)d_in[14];
    const float* dt_proj_b  = (const float*)d_in[15];
    const float* A_log      = (const float*)d_in[16];
    const float* Dp         = (const float*)d_in[17];
    const float* out_proj_w = (const float*)d_in[18];
    const float* W_out      = (const float*)d_in[19];
    const float* bn_o_g     = (const float*)d_in[20];
    const float* bn_o_b     = (const float*)d_in[21];
    const float* bn_o_m     = (const float*)d_in[22];
    const float* bn_o_v     = (const float*)d_in[23];
    float* out = (float*)d_out;

    float *h, *xz, *xc, *dbl, *dt, *y, *o1;
    cudaGetSymbolAddress((void**)&h,   g_h);
    cudaGetSymbolAddress((void**)&xz,  g_xz);
    cudaGetSymbolAddress((void**)&xc,  g_xc);
    cudaGetSymbolAddress((void**)&dbl, g_dbl);
    cudaGetSymbolAddress((void**)&dt,  g_dt);
    cudaGetSymbolAddress((void**)&y,   g_y);
    cudaGetSymbolAddress((void**)&o1,  g_o1);

    // 1) h = relu(BN(x @ W_in^T))
    gemm_kernel<<<dim3(CC / BN_, NT / BM), 256>>>(
        x, CC, W_in, h, NT, CC, CC, nullptr, 1,
        bn_in_g, bn_in_b, bn_in_m, bn_in_v, nullptr);

    // 2) xz = h[order] @ in_proj_w^T  (gather fused)
    gemm_kernel<<<dim3((2 * DIN) / BN_, NT / BM), 256>>>(
        h, CC, in_proj_w, xz, NT, 2 * DIN, CC, order, 0,
        nullptr, nullptr, nullptr, nullptr, nullptr);

    // 3) xc = silu(causal depthwise conv(xm) + b)
    conv_silu_kernel<<<(NT * DIN) / 256, 256>>>(xz, conv_w, conv_b, xc);

    // 4) dbl = xc @ x_proj_w^T  -> (dt_low | B | C)
    gemm_kernel<<<dim3(64 / BN_, NT / BM), 256>>>(
        xc, DIN, x_proj_w, dbl, NT, 64, DIN, nullptr, 0,
        nullptr, nullptr, nullptr, nullptr, nullptr);

    // 5) dt = softplus(dt_low @ dt_proj_w^T + dt_proj_b)
    gemm_kernel<<<dim3(DIN / BN_, NT / BM), 256>>>(
        dbl, 64, dt_proj_w, dt, NT, DIN, DTR, nullptr, 2,
        dt_proj_b, nullptr, nullptr, nullptr, nullptr);

    // 6) selective scan + D skip + silu(z) gate -> y
    scan_kernel<<<dim3(DIN / 8, NB), 128>>>(dt, dbl, xc, xz, A_log, Dp, y);

    // 7) o1 = y @ out_proj_w^T
    gemm_kernel<<<dim3(CC / BN_, NT / BM), 256>>>(
        y, DIN, out_proj_w, o1, NT, CC, DIN, nullptr, 0,
        nullptr, nullptr, nullptr, nullptr, nullptr);

    // 8) out = relu(BN(o1[inv] @ W_out^T) + x)   (gather + residual fused)
    gemm_kernel<<<dim3(CC / BN_, NT / BM), 256>>>(
        o1, CC, W_out, out, NT, CC, CC, inv, 3,
        bn_o_g, bn_o_b, bn_o_m, bn_o_v, x);
}

// round 3
// speedup vs baseline: 4.6727x; 4.6727x over previous
#include <cuda_runtime.h>
#include <cuda_bf16.h>
#include <math.h>
#include <stdint.h>

// Problem constants
#define NB 4
#define LL 2048
#define CC 512
#define DIN 1024
#define DS 16
#define DCONV 4
#define DTR 32
#define NT (NB * LL)   // 8192 rows
#define EPSBN 1e-5f

// ---------------- scratch (device globals; no allocation allowed) -------------
__device__ __align__(256) float g_h  [NT * CC];
__device__ __align__(256) float g_xz [NT * 2 * DIN];
__device__ __align__(256) float g_xc [NT * DIN];
__device__ __align__(256) float g_dbl[NT * 64];
__device__ __align__(256) float g_dt [NT * DIN];
__device__ __align__(256) float g_o1 [NT * CC];

// bf16 hi/lo split buffers (activations)
__device__ __align__(256) __nv_bfloat16 g_x_hi  [NT * CC],  g_x_lo  [NT * CC];
__device__ __align__(256) __nv_bfloat16 g_hg_hi [NT * CC],  g_hg_lo [NT * CC];
__device__ __align__(256) __nv_bfloat16 g_xc_hi [NT * DIN], g_xc_lo [NT * DIN];
__device__ __align__(256) __nv_bfloat16 g_dbl_hi[NT * 64],  g_dbl_lo[NT * 64];
__device__ __align__(256) __nv_bfloat16 g_y_hi  [NT * DIN], g_y_lo  [NT * DIN];
__device__ __align__(256) __nv_bfloat16 g_og_hi [NT * CC],  g_og_lo [NT * CC];
// weights
__device__ __align__(256) __nv_bfloat16 g_Win_hi [CC * CC],      g_Win_lo [CC * CC];
__device__ __align__(256) __nv_bfloat16 g_ip_hi  [2 * DIN * CC], g_ip_lo  [2 * DIN * CC];
__device__ __align__(256) __nv_bfloat16 g_xp_hi  [64 * DIN],     g_xp_lo  [64 * DIN];
__device__ __align__(256) __nv_bfloat16 g_dtp_hi [DIN * 64],     g_dtp_lo [DIN * 64];
__device__ __align__(256) __nv_bfloat16 g_op_hi  [CC * DIN],     g_op_lo  [CC * DIN];
__device__ __align__(256) __nv_bfloat16 g_Wout_hi[CC * CC],      g_Wout_lo[CC * CC];

// ============================ PTX helpers =====================================
__device__ __forceinline__ uint32_t smem_u32(const void* p) {
    uint32_t a;
    asm("{ .reg .u64 t; cvta.to.shared.u64 t, %1; cvt.u32.u64 %0, t; }"
        : "=r"(a) : "l"(p));
    return a;
}
__device__ __forceinline__ void cpa16(uint32_t d, const void* s) {
    asm volatile("cp.async.cg.shared.global [%0], [%1], 16;" :: "r"(d), "l"(s));
}
#define CP_COMMIT asm volatile("cp.async.commit_group;" ::: "memory")
#define CP_WAIT1  asm volatile("cp.async.wait_group 1;"  ::: "memory")
#define CP_WAIT0  asm volatile("cp.async.wait_group 0;"  ::: "memory")

__device__ __forceinline__ void ldsm4(uint32_t* r, uint32_t a) {
    asm volatile("ldmatrix.sync.aligned.m8n8.x4.shared.b16 {%0,%1,%2,%3}, [%4];"
        : "=r"(r[0]), "=r"(r[1]), "=r"(r[2]), "=r"(r[3]) : "r"(a));
}
__device__ __forceinline__ void mma16816(float* c, const uint32_t* a, const uint32_t* b) {
    asm volatile(
        "mma.sync.aligned.m16n8k16.row.col.f32.bf16.bf16.f32 "
        "{%0,%1,%2,%3}, {%4,%5,%6,%7}, {%8,%9}, {%0,%1,%2,%3};"
        : "+f"(c[0]), "+f"(c[1]), "+f"(c[2]), "+f"(c[3])
        : "r"(a[0]), "r"(a[1]), "r"(a[2]), "r"(a[3]), "r"(b[0]), "r"(b[1]));
}

// =========================== HMMA split-bf16 GEMM =============================
// C[M,N] = epi( A[M,K] @ W[N,K]^T ), A/W given as bf16 hi/lo pairs, K % 32 == 0.
// CTA: 128 x NTILE output, 256 threads = 8 warps (4 m x 2 n), warp 32 x NTILE/2.
// SMEM: rows padded to 40 halves (80B) -> conflict-free ldmatrix.
// epi: 0 none | 1 BN+relu | 2 softplus(v + p0[n]) | 3 BN + addsrc + relu
template <int NTILE>
__device__ __forceinline__ void load_stage(
    uint32_t base, int tid, int m0, int n0, int K, int c,
    const __nv_bfloat16* Ahi, const __nv_bfloat16* Alo,
    const __nv_bfloat16* Whi, const __nv_bfloat16* Wlo)
{
    const int k0 = c * 32;
    #pragma unroll
    for (int half = 0; half < 2; half++) {
        const __nv_bfloat16* gA = half ? Alo : Ahi;
        uint32_t dA = base + (half * 128) * 80;
        #pragma unroll
        for (int e = 0; e < 2; e++) {         // 128 rows x 4 groups / 256 thr
            int t = tid + e * 256;
            int r = t >> 2, g = t & 3;
            cpa16(dA + r * 80 + g * 16, gA + (size_t)(m0 + r) * K + k0 + g * 8);
        }
        const __nv_bfloat16* gW = half ? Wlo : Whi;
        uint32_t dW = base + (256 + half * NTILE) * 80;
        #pragma unroll
        for (int e = 0; e < NTILE / 64; e++) {
            int t = tid + e * 256;
            int r = t >> 2, g = t & 3;
            cpa16(dW + r * 80 + g * 16, gW + (size_t)(n0 + r) * K + k0 + g * 8);
        }
    }
}

template <int NTILE>
__global__ void __launch_bounds__(256) gemm_mma(
    const __nv_bfloat16* __restrict__ Ahi, const __nv_bfloat16* __restrict__ Alo,
    const __nv_bfloat16* __restrict__ Whi, const __nv_bfloat16* __restrict__ Wlo,
    float* __restrict__ Cout, int K, int Ntot, int epi,
    const float* __restrict__ p0, const float* __restrict__ p1,
    const float* __restrict__ p2, const float* __restrict__ p3,
    const float* __restrict__ addsrc)
{
    constexpr int WN = NTILE / 2;       // warp n extent
    constexpr int NT8 = WN / 8;         // n-frags per warp
    constexpr int ROWS = 256 + 2 * NTILE;
    constexpr int STAGE = ROWS * 80;

    extern __shared__ __align__(128) char smraw[];
    const uint32_t sb = smem_u32(smraw);

    const int tid = threadIdx.x;
    const int lane = tid & 31, warp = tid >> 5;
    const int wm = warp & 3, wn = warp >> 2;
    const int m0 = blockIdx.y * 128;
    const int n0 = blockIdx.x * NTILE;

    float acc[2][NT8][4] = {};

    const int nch = K >> 5;
    load_stage<NTILE>(sb, tid, m0, n0, K, 0, Ahi, Alo, Whi, Wlo);
    CP_COMMIT;

    const int lr = lane & 15;
    const int lc = (lane >> 4) << 3;

    for (int c = 0; c < nch; c++) {
        const uint32_t cur = sb + (uint32_t)(c & 1) * STAGE;
        if (c + 1 < nch) {
            load_stage<NTILE>(sb + (uint32_t)((c + 1) & 1) * STAGE,
                              tid, m0, n0, K, c + 1, Ahi, Alo, Whi, Wlo);
            CP_COMMIT;
            CP_WAIT1;
        } else {
            CP_WAIT0;
        }
        __syncthreads();

        #pragma unroll
        for (int kk = 0; kk < 32; kk += 16) {
            uint32_t ah[2][4], al[2][4];
            #pragma unroll
            for (int mt = 0; mt < 2; mt++) {
                uint32_t a = cur + (uint32_t)((wm * 32 + mt * 16 + lr) * 80 + (kk + lc) * 2);
                ldsm4(ah[mt], a);
                ldsm4(al[mt], a + 128 * 80);
            }
            uint32_t wh[NT8][2], wl[NT8][2];
            #pragma unroll
            for (int p = 0; p < NT8 / 2; p++) {
                uint32_t a = cur + (uint32_t)((256 + wn * WN + p * 16 + lr) * 80 + (kk + lc) * 2);
                uint32_t r4[4];
                ldsm4(r4, a);
                wh[2*p][0] = r4[0]; wh[2*p][1] = r4[2];
                wh[2*p+1][0] = r4[1]; wh[2*p+1][1] = r4[3];
                ldsm4(r4, a + NTILE * 80);
                wl[2*p][0] = r4[0]; wl[2*p][1] = r4[2];
                wl[2*p+1][0] = r4[1]; wl[2*p+1][1] = r4[3];
            }
            #pragma unroll
            for (int mt = 0; mt < 2; mt++)
                #pragma unroll
                for (int nt = 0; nt < NT8; nt++) {
                    mma16816(acc[mt][nt], ah[mt], wh[nt]);
                    mma16816(acc[mt][nt], ah[mt], wl[nt]);
                    mma16816(acc[mt][nt], al[mt], wh[nt]);
                }
        }
        __syncthreads();
    }

    // epilogue
    const int g = lane >> 2, tg = lane & 3;
    #pragma unroll
    for (int mt = 0; mt < 2; mt++)
        #pragma unroll
        for (int nt = 0; nt < NT8; nt++)
            #pragma unroll
            for (int rr = 0; rr < 2; rr++) {
                int m = m0 + wm * 32 + mt * 16 + g + rr * 8;
                int n = n0 + wn * WN + nt * 8 + tg * 2;
                float v0 = acc[mt][nt][rr * 2 + 0];
                float v1 = acc[mt][nt][rr * 2 + 1];
                if (epi == 1) {
                    v0 = fmaxf((v0 - p2[n])   * rsqrtf(p3[n]   + EPSBN) * p0[n]   + p1[n],   0.f);
                    v1 = fmaxf((v1 - p2[n+1]) * rsqrtf(p3[n+1] + EPSBN) * p0[n+1] + p1[n+1], 0.f);
                } else if (epi == 2) {
                    v0 += p0[n];   v0 = (v0 > 20.f) ? v0 : log1pf(expf(v0));
                    v1 += p0[n+1]; v1 = (v1 > 20.f) ? v1 : log1pf(expf(v1));
                } else if (epi == 3) {
                    v0 = (v0 - p2[n])   * rsqrtf(p3[n]   + EPSBN) * p0[n]   + p1[n];
                    v1 = (v1 - p2[n+1]) * rsqrtf(p3[n+1] + EPSBN) * p0[n+1] + p1[n+1];
                    v0 = fmaxf(v0 + addsrc[(size_t)m * Ntot + n], 0.f);
                    v1 = fmaxf(v1 + addsrc[(size_t)m * Ntot + n + 1], 0.f);
                }
                *(float2*)&Cout[(size_t)m * Ntot + n] = make_float2(v0, v1);
            }
}

// ====================== fp32 -> bf16 hi/lo split kernels ======================
__global__ void __launch_bounds__(256) split_kernel(
    const float* __restrict__ src, const int* __restrict__ rowmap, int cols,
    __nv_bfloat16* __restrict__ hi, __nv_bfloat16* __restrict__ lo, long total)
{
    long i = (long)blockIdx.x * blockDim.x + threadIdx.x;
    if (i >= total) return;
    float v;
    if (rowmap) {
        long r = i / cols;
        int c = (int)(i - r * cols);
        v = src[(long)rowmap[r] * cols + c];
    } else {
        v = src[i];
    }
    __nv_bfloat16 h = __float2bfloat16(v);
    hi[i] = h;
    lo[i] = __float2bfloat16(v - __bfloat162float(h));
}

// dt_proj_w (1024 x 32) -> zero-padded (1024 x 64) hi/lo
__global__ void __launch_bounds__(256) split_pad_kernel(
    const float* __restrict__ src, __nv_bfloat16* __restrict__ hi,
    __nv_bfloat16* __restrict__ lo)
{
    int i = blockIdx.x * blockDim.x + threadIdx.x;   // over 1024*64
    int r = i >> 6, c = i & 63;
    float v = (c < DTR) ? src[r * DTR + c] : 0.f;
    __nv_bfloat16 h = __float2bfloat16(v);
    hi[i] = h;
    lo[i] = __float2bfloat16(v - __bfloat162float(h));
}

// ---------------- depthwise causal conv (width 4) + bias + silu ---------------
__global__ void __launch_bounds__(256) conv_silu_kernel(
    const float* __restrict__ xz, const float* __restrict__ cw,
    const float* __restrict__ cb, float* __restrict__ xc,
    __nv_bfloat16* __restrict__ xch, __nv_bfloat16* __restrict__ xcl)
{
    int idx = blockIdx.x * blockDim.x + threadIdx.x;  // over NT*DIN
    int d   = idx & (DIN - 1);
    int row = idx >> 10;
    int l   = row & (LL - 1);

    float acc = cb[d];
    #pragma unroll
    for (int j = 0; j < DCONV; j++) {
        int ls = l - (DCONV - 1) + j;
        if (ls >= 0)
            acc = fmaf(cw[d * DCONV + j],
                       xz[(long)(row - (DCONV - 1 - j)) * (2 * DIN) + d], acc);
    }
    float v = acc / (1.f + expf(-acc));   // silu
    xc[idx] = v;
    __nv_bfloat16 h = __float2bfloat16(v);
    xch[idx] = h;
    xcl[idx] = __float2bfloat16(v - __bfloat162float(h));
}

// ---------------- selective scan + skip + gate --------------------------------
// grid (DIN/8, NB), block 128 = 8 d x 16 s. Prefetch 8 steps ahead; batched
// shfl reductions; SMEM-staged coalesced output stores.
#define SCAN_LOAD(T0, FDT, FU, FB, FC, FZ) do { \
    _Pragma("unroll") \
    for (int _i = 0; _i < 8; _i++) { \
        long _row = base + (T0) + _i; \
        FDT[_i] = dt[_row * DIN + d]; \
        FU[_i]  = xc[_row * DIN + d]; \
        FB[_i]  = dbl[_row * 64 + DTR + s]; \
        FC[_i]  = dbl[_row * 64 + DTR + DS + s]; \
        FZ[_i]  = xz[_row * (2 * DIN) + DIN + d]; \
    } \
} while (0)

#define SCAN_COMPUTE(T0, FDT, FU, FB, FC, FZ) do { \
    float _p[8]; \
    _Pragma("unroll") \
    for (int _i = 0; _i < 8; _i++) { \
        float _dA = expf(FDT[_i] * Aa); \
        h = fmaf(_dA, h, FDT[_i] * FB[_i] * FU[_i]); \
        _p[_i] = h * FC[_i]; \
    } \
    _Pragma("unroll") \
    for (int _i = 0; _i < 8; _i++) { \
        _p[_i] += __shfl_xor_sync(0xffffffffu, _p[_i], 8, 16); \
        _p[_i] += __shfl_xor_sync(0xffffffffu, _p[_i], 4, 16); \
        _p[_i] += __shfl_xor_sync(0xffffffffu, _p[_i], 2, 16); \
        _p[_i] += __shfl_xor_sync(0xffffffffu, _p[_i], 1, 16); \
    } \
    if (s == 0) { \
        _Pragma("unroll") \
        for (int _i = 0; _i < 8; _i++) { \
            float _g = FZ[_i] / (1.f + expf(-FZ[_i])); \
            sm_y[_i][dl] = (_p[_i] + FU[_i] * Dd) * _g; \
        } \
    } \
    __syncthreads(); \
    if (threadIdx.x < 64) { \
        int _ti = threadIdx.x >> 3, _dd = threadIdx.x & 7; \
        float _yy = sm_y[_ti][_dd]; \
        long _idx = (base + (T0) + _ti) * DIN + (long)blockIdx.x * 8 + _dd; \
        __nv_bfloat16 _hh = __float2bfloat16(_yy); \
        yh[_idx] = _hh; \
        yl[_idx] = __float2bfloat16(_yy - __bfloat162float(_hh)); \
    } \
    __syncthreads(); \
} while (0)

__global__ void __launch_bounds__(128) scan_kernel(
    const float* __restrict__ dt, const float* __restrict__ dbl,
    const float* __restrict__ xc, const float* __restrict__ xz,
    const float* __restrict__ A_log, const float* __restrict__ Dp,
    __nv_bfloat16* __restrict__ yh, __nv_bfloat16* __restrict__ yl)
{
    __shared__ float sm_y[8][8];
    const int b  = blockIdx.y;
    const int s  = threadIdx.x & 15;
    const int dl = threadIdx.x >> 4;
    const int d  = blockIdx.x * 8 + dl;

    const float Aa = -expf(A_log[d * DS + s]);
    const float Dd = Dp[d];

    float h = 0.f;
    const long base = (long)b * LL;

    float dtA[8], uA[8], BA[8], CA[8], zA[8];
    float dtB[8], uB[8], BB[8], CB[8], zB[8];

    SCAN_LOAD(0, dtA, uA, BA, CA, zA);
    for (int t0 = 0; t0 < LL; t0 += 16) {
        SCAN_LOAD(t0 + 8, dtB, uB, BB, CB, zB);
        SCAN_COMPUTE(t0, dtA, uA, BA, CA, zA);
        if (t0 + 16 < LL) SCAN_LOAD(t0 + 16, dtA, uA, BA, CA, zA);
        SCAN_COMPUTE(t0 + 8, dtB, uB, BB, CB, zB);
    }
}

// ---------------- launch -------------------------------------------------------
extern "C" void kernel_launch(void* const* d_in, const int* in_sizes, int n_in,
                              void* d_out, int out_size)
{
    const float* x          = (const float*)d_in[1];
    const int*   order      = (const int*)  d_in[3];
    const int*   inv        = (const int*)  d_in[4];
    const float* W_in       = (const float*)d_in[5];
    const float* bn_in_g    = (const float*)d_in[6];
    const float* bn_in_b    = (const float*)d_in[7];
    const float* bn_in_m    = (const float*)d_in[8];
    const float* bn_in_v    = (const float*)d_in[9];
    const float* in_proj_w  = (const float*)d_in[10];
    const float* conv_w     = (const float*)d_in[11];
    const float* conv_b     = (const float*)d_in[12];
    const float* x_proj_w   = (const float*)d_in[13];
    const float* dt_proj_w  = (const float*)d_in[14];
    const float* dt_proj_b  = (const float*)d_in[15];
    const float* A_log      = (const float*)d_in[16];
    const float* Dp         = (const float*)d_in[17];
    const float* out_proj_w = (const float*)d_in[18];
    const float* W_out      = (const float*)d_in[19];
    const float* bn_o_g     = (const float*)d_in[20];
    const float* bn_o_b     = (const float*)d_in[21];
    const float* bn_o_m     = (const float*)d_in[22];
    const float* bn_o_v     = (const float*)d_in[23];
    float* out = (float*)d_out;

    float *h, *xz, *xc, *dbl, *dt, *o1;
    cudaGetSymbolAddress((void**)&h,   g_h);
    cudaGetSymbolAddress((void**)&xz,  g_xz);
    cudaGetSymbolAddress((void**)&xc,  g_xc);
    cudaGetSymbolAddress((void**)&dbl, g_dbl);
    cudaGetSymbolAddress((void**)&dt,  g_dt);
    cudaGetSymbolAddress((void**)&o1,  g_o1);

    __nv_bfloat16 *xhi, *xlo, *hgh, *hgl, *xch, *xcl, *dbh, *dbL, *yh, *yl, *ogh, *ogl;
    __nv_bfloat16 *Winh, *Winl, *iph, *ipl, *xph, *xpl, *dtph, *dtpl, *oph, *opl, *Woh, *Wol;
    cudaGetSymbolAddress((void**)&xhi, g_x_hi);   cudaGetSymbolAddress((void**)&xlo, g_x_lo);
    cudaGetSymbolAddress((void**)&hgh, g_hg_hi);  cudaGetSymbolAddress((void**)&hgl, g_hg_lo);
    cudaGetSymbolAddress((void**)&xch, g_xc_hi);  cudaGetSymbolAddress((void**)&xcl, g_xc_lo);
    cudaGetSymbolAddress((void**)&dbh, g_dbl_hi); cudaGetSymbolAddress((void**)&dbL, g_dbl_lo);
    cudaGetSymbolAddress((void**)&yh,  g_y_hi);   cudaGetSymbolAddress((void**)&yl,  g_y_lo);
    cudaGetSymbolAddress((void**)&ogh, g_og_hi);  cudaGetSymbolAddress((void**)&ogl, g_og_lo);
    cudaGetSymbolAddress((void**)&Winh, g_Win_hi); cudaGetSymbolAddress((void**)&Winl, g_Win_lo);
    cudaGetSymbolAddress((void**)&iph,  g_ip_hi);  cudaGetSymbolAddress((void**)&ipl,  g_ip_lo);
    cudaGetSymbolAddress((void**)&xph,  g_xp_hi);  cudaGetSymbolAddress((void**)&xpl,  g_xp_lo);
    cudaGetSymbolAddress((void**)&dtph, g_dtp_hi); cudaGetSymbolAddress((void**)&dtpl, g_dtp_lo);
    cudaGetSymbolAddress((void**)&oph,  g_op_hi);  cudaGetSymbolAddress((void**)&opl,  g_op_lo);
    cudaGetSymbolAddress((void**)&Woh,  g_Wout_hi); cudaGetSymbolAddress((void**)&Wol, g_Wout_lo);

    // dynamic SMEM: (256 + 2*NTILE) rows * 80B * 2 stages
    const int SMEM128 = (256 + 256) * 80 * 2;   // 81920
    const int SMEM64  = (256 + 128) * 80 * 2;   // 61440
    cudaFuncSetAttribute(gemm_mma<128>, cudaFuncAttributeMaxDynamicSharedMemorySize, SMEM128);
    cudaFuncSetAttribute(gemm_mma<64>,  cudaFuncAttributeMaxDynamicSharedMemorySize, SMEM64);

    // --- weight & input splits -------------------------------------------------
    split_kernel<<<(NT * CC + 255) / 256, 256>>>(x, nullptr, CC, xhi, xlo, (long)NT * CC);
    split_kernel<<<(CC * CC + 255) / 256, 256>>>(W_in, nullptr, CC, Winh, Winl, (long)CC * CC);
    split_kernel<<<(2 * DIN * CC + 255) / 256, 256>>>(in_proj_w, nullptr, CC, iph, ipl, (long)2 * DIN * CC);
    split_kernel<<<(64 * DIN + 255) / 256, 256>>>(x_proj_w, nullptr, DIN, xph, xpl, (long)64 * DIN);
    split_pad_kernel<<<(DIN * 64) / 256, 256>>>(dt_proj_w, dtph, dtpl);
    split_kernel<<<(CC * DIN + 255) / 256, 256>>>(out_proj_w, nullptr, DIN, oph, opl, (long)CC * DIN);
    split_kernel<<<(CC * CC + 255) / 256, 256>>>(W_out, nullptr, CC, Woh, Wol, (long)CC * CC);

    // 1) h = relu(BN(x @ W_in^T))
    gemm_mma<128><<<dim3(CC / 128, NT / 128), 256, SMEM128>>>(
        xhi, xlo, Winh, Winl, h, CC, CC, 1, bn_in_g, bn_in_b, bn_in_m, bn_in_v, nullptr);

    // gather h by `order` + split
    split_kernel<<<(NT * CC + 255) / 256, 256>>>(h, order, CC, hgh, hgl, (long)NT * CC);

    // 2) xz = h[order] @ in_proj_w^T
    gemm_mma<128><<<dim3(2 * DIN / 128, NT / 128), 256, SMEM128>>>(
        hgh, hgl, iph, ipl, xz, CC, 2 * DIN, 0, nullptr, nullptr, nullptr, nullptr, nullptr);

    // 3) xc = silu(conv(xm) + b)  (+ bf16 split)
    conv_silu_kernel<<<(NT * DIN) / 256, 256>>>(xz, conv_w, conv_b, xc, xch, xcl);

    // 4) dbl = xc @ x_proj_w^T   (N=64)
    gemm_mma<64><<<dim3(1, NT / 128), 256, SMEM64>>>(
        xch, xcl, xph, xpl, dbl, DIN, 64, 0, nullptr, nullptr, nullptr, nullptr, nullptr);

    // split dbl for dt GEMM
    split_kernel<<<(NT * 64 + 255) / 256, 256>>>(dbl, nullptr, 64, dbh, dbL, (long)NT * 64);

    // 5) dt = softplus(dbl @ dt_proj_pad^T + b)   (K=64, zero-padded weights)
    gemm_mma<128><<<dim3(DIN / 128, NT / 128), 256, SMEM128>>>(
        dbh, dbL, dtph, dtpl, dt, 64, DIN, 2, dt_proj_b, nullptr, nullptr, nullptr, nullptr);

    // 6) selective scan + D skip + silu(z) gate -> y (bf16 split)
    scan_kernel<<<dim3(DIN / 8, NB), 128>>>(dt, dbl, xc, xz, A_log, Dp, yh, yl);

    // 7) o1 = y @ out_proj_w^T
    gemm_mma<128><<<dim3(CC / 128, NT / 128), 256, SMEM128>>>(
        yh, yl, oph, opl, o1, DIN, CC, 0, nullptr, nullptr, nullptr, nullptr, nullptr);

    // gather o1 by `inv` + split
    split_kernel<<<(NT * CC + 255) / 256, 256>>>(o1, inv, CC, ogh, ogl, (long)NT * CC);

    // 8) out = relu(BN(o1[inv] @ W_out^T) + x)
    gemm_mma<128><<<dim3(CC / 128, NT / 128), 256, SMEM128>>>(
        ogh, ogl, Woh, Wol, out, CC, CC, 3, bn_o_g, bn_o_b, bn_o_m, bn_o_v, x);
}

// round 4
// speedup vs baseline: 5.6015x; 1.1988x over previous
#include <cuda_runtime.h>
#include <cuda_fp16.h>
#include <math.h>
#include <stdint.h>

// Problem constants
#define NB 4
#define LL 2048
#define CC 512
#define DIN 1024
#define DS 16
#define DCONV 4
#define DTR 32
#define NT (NB * LL)   // 8192 rows
#define EPSBN 1e-5f

// ---------------- scratch (device globals; no allocation allowed) -------------
__device__ __align__(256) float g_xz [NT * 2 * DIN];   // 64 MB
__device__ __align__(256) float g_xc [NT * DIN];       // 32 MB
__device__ __align__(256) float g_dbl[NT * 64];        // 2 MB
__device__ __align__(256) float g_dt [NT * DIN];       // 32 MB

// fp16 hi/lo activation buffers
__device__ __align__(256) __half g_x_hi [NT * CC],  g_x_lo [NT * CC];
__device__ __align__(256) __half g_hg_hi[NT * CC],  g_hg_lo[NT * CC];
__device__ __align__(256) __half g_xc_hi[NT * DIN], g_xc_lo[NT * DIN];
__device__ __align__(256) __half g_db_hi[NT * 64],  g_db_lo[NT * 64];
__device__ __align__(256) __half g_y_hi [NT * DIN], g_y_lo [NT * DIN];
__device__ __align__(256) __half g_og_hi[NT * CC],  g_og_lo[NT * CC];
// fp16 weights (single precision copy)
__device__ __align__(256) __half g_Win_h[CC * CC];
__device__ __align__(256) __half g_ip_h [2 * DIN * CC];
__device__ __align__(256) __half g_xp_h [64 * DIN];
__device__ __align__(256) __half g_dtp_h[DIN * DTR];
__device__ __align__(256) __half g_op_h [CC * DIN];
__device__ __align__(256) __half g_Wo_h [CC * CC];

// ============================ PTX helpers =====================================
__device__ __forceinline__ uint32_t smem_u32(const void* p) {
    uint32_t a;
    asm("{ .reg .u64 t; cvta.to.shared.u64 t, %1; cvt.u32.u64 %0, t; }"
        : "=r"(a) : "l"(p));
    return a;
}
__device__ __forceinline__ void cpa16(uint32_t d, const void* s) {
    asm volatile("cp.async.cg.shared.global [%0], [%1], 16;" :: "r"(d), "l"(s));
}
#define CP_COMMIT asm volatile("cp.async.commit_group;" ::: "memory")
#define CP_WAIT1  asm volatile("cp.async.wait_group 1;"  ::: "memory")

__device__ __forceinline__ void ldsm4(uint32_t* r, uint32_t a) {
    asm volatile("ldmatrix.sync.aligned.m8n8.x4.shared.b16 {%0,%1,%2,%3}, [%4];"
        : "=r"(r[0]), "=r"(r[1]), "=r"(r[2]), "=r"(r[3]) : "r"(a));
}
__device__ __forceinline__ void mma16816(float* c, const uint32_t* a, const uint32_t* b) {
    asm volatile(
        "mma.sync.aligned.m16n8k16.row.col.f32.f16.f16.f32 "
        "{%0,%1,%2,%3}, {%4,%5,%6,%7}, {%8,%9}, {%0,%1,%2,%3};"
        : "+f"(c[0]), "+f"(c[1]), "+f"(c[2]), "+f"(c[3])
        : "r"(a[0]), "r"(a[1]), "r"(a[2]), "r"(a[3]), "r"(b[0]), "r"(b[1]));
}

// ====================== fp16 2-term HMMA GEMM ================================
// C[M,N] = epi( (Ahi+Alo)[M,K] @ W[N,K]^T ), W fp16-rounded (2 MMA terms).
// CTA: MT x NTILE output, 256 threads = 8 warps (WMW x WNW), 3-stage cp.async.
// SMEM rows padded to 40 halves (80B) -> conflict-free ldmatrix.
// Outputs (any non-null): outF fp32, outHi/outLo fp16 pair. Rows scattered via
// scat (out row = scat[m]).
// epi: 0 none | 1 BN+relu | 2 softplus(v+p0[n]) | 3 BN + addsrc + relu
template <int MT, int NTILE, int WMW, int WNW>
__device__ __forceinline__ void load_stage(
    uint32_t base, int tid, int m0, int n0, int lda, int K, int c,
    const __half* Ahi, const __half* Alo, const __half* W)
{
    const int k0 = c * 32;
    #pragma unroll
    for (int h2 = 0; h2 < 2; h2++) {
        const __half* gA = h2 ? Alo : Ahi;
        uint32_t db = base + (uint32_t)(h2 * MT) * 80;
        #pragma unroll
        for (int e = 0; e < MT * 4 / 256; e++) {
            int t = tid + e * 256;
            int r = t >> 2, g = t & 3;
            cpa16(db + r * 80 + g * 16, gA + (size_t)(m0 + r) * lda + k0 + g * 8);
        }
    }
    uint32_t dw = base + (uint32_t)(2 * MT) * 80;
    #pragma unroll
    for (int e = 0; e < NTILE * 4 / 256; e++) {
        int t = tid + e * 256;
        int r = t >> 2, g = t & 3;
        cpa16(dw + r * 80 + g * 16, W + (size_t)(n0 + r) * K + k0 + g * 8);
    }
}

template <int MT, int NTILE, int WMW, int WNW>
__global__ void __launch_bounds__(256, 2) gemm_fp16(
    const __half* __restrict__ Ahi, const __half* __restrict__ Alo, int lda,
    const __half* __restrict__ W, int K,
    float* __restrict__ outF, __half* __restrict__ outHi, __half* __restrict__ outLo,
    const int* __restrict__ scat, int Ntot, int epi,
    const float* __restrict__ p0, const float* __restrict__ p1,
    const float* __restrict__ p2, const float* __restrict__ p3,
    const float* __restrict__ addsrc)
{
    constexpr int WTM = MT / WMW;          // 32
    constexpr int WTN = NTILE / WNW;
    constexpr int MTFR = WTM / 16;         // 2
    constexpr int NT8 = WTN / 8;
    constexpr int ROWS = 2 * MT + NTILE;
    constexpr int STAGE = ROWS * 80;

    extern __shared__ __align__(128) char smraw[];
    const uint32_t sb = smem_u32(smraw);

    const int tid = threadIdx.x;
    const int lane = tid & 31, warp = tid >> 5;
    const int wm = warp % WMW, wn = warp / WMW;
    const int m0 = blockIdx.y * MT;
    const int n0 = blockIdx.x * NTILE;

    float acc[MTFR][NT8][4] = {};

    const int nch = K >> 5;
    // prologue: stages 0,1
    #pragma unroll
    for (int s = 0; s < 2; s++) {
        if (s < nch)
            load_stage<MT, NTILE, WMW, WNW>(sb + s * STAGE, tid, m0, n0, lda, K, s, Ahi, Alo, W);
        CP_COMMIT;
    }

    const int lr = lane & 15;
    const int lc = (lane >> 4) << 3;

    for (int c = 0; c < nch; c++) {
        CP_WAIT1;
        __syncthreads();
        {
            int cn = c + 2;
            if (cn < nch)
                load_stage<MT, NTILE, WMW, WNW>(sb + (cn % 3) * STAGE, tid, m0, n0, lda, K, cn, Ahi, Alo, W);
            CP_COMMIT;
        }
        const uint32_t cur = sb + (uint32_t)(c % 3) * STAGE;
        #pragma unroll
        for (int kk = 0; kk < 32; kk += 16) {
            uint32_t ah[MTFR][4], al[MTFR][4];
            #pragma unroll
            for (int mt = 0; mt < MTFR; mt++) {
                uint32_t a = cur + (uint32_t)((wm * WTM + mt * 16 + lr) * 80 + (kk + lc) * 2);
                ldsm4(ah[mt], a);
                ldsm4(al[mt], a + MT * 80);
            }
            uint32_t wf[NT8][2];
            #pragma unroll
            for (int p = 0; p < NT8 / 2; p++) {
                uint32_t a = cur + (uint32_t)((2 * MT + wn * WTN + p * 16 + lr) * 80 + (kk + lc) * 2);
                uint32_t r4[4];
                ldsm4(r4, a);
                wf[2*p][0] = r4[0]; wf[2*p][1] = r4[2];
                wf[2*p+1][0] = r4[1]; wf[2*p+1][1] = r4[3];
            }
            #pragma unroll
            for (int mt = 0; mt < MTFR; mt++)
                #pragma unroll
                for (int nt = 0; nt < NT8; nt++) {
                    mma16816(acc[mt][nt], ah[mt], wf[nt]);
                    mma16816(acc[mt][nt], al[mt], wf[nt]);
                }
        }
    }

    // epilogue
    const int g = lane >> 2, tg = lane & 3;
    #pragma unroll
    for (int mt = 0; mt < MTFR; mt++)
        #pragma unroll
        for (int nt = 0; nt < NT8; nt++)
            #pragma unroll
            for (int rr = 0; rr < 2; rr++) {
                int m = m0 + wm * WTM + mt * 16 + g + rr * 8;
                int n = n0 + wn * WTN + nt * 8 + tg * 2;
                int mo = scat ? scat[m] : m;
                float v0 = acc[mt][nt][rr * 2 + 0];
                float v1 = acc[mt][nt][rr * 2 + 1];
                if (epi == 1) {
                    v0 = fmaxf((v0 - p2[n])   * rsqrtf(p3[n]   + EPSBN) * p0[n]   + p1[n],   0.f);
                    v1 = fmaxf((v1 - p2[n+1]) * rsqrtf(p3[n+1] + EPSBN) * p0[n+1] + p1[n+1], 0.f);
                } else if (epi == 2) {
                    v0 += p0[n];   v0 = (v0 > 20.f) ? v0 : log1pf(expf(v0));
                    v1 += p0[n+1]; v1 = (v1 > 20.f) ? v1 : log1pf(expf(v1));
                } else if (epi == 3) {
                    v0 = (v0 - p2[n])   * rsqrtf(p3[n]   + EPSBN) * p0[n]   + p1[n];
                    v1 = (v1 - p2[n+1]) * rsqrtf(p3[n+1] + EPSBN) * p0[n+1] + p1[n+1];
                    v0 = fmaxf(v0 + addsrc[(size_t)mo * Ntot + n], 0.f);
                    v1 = fmaxf(v1 + addsrc[(size_t)mo * Ntot + n + 1], 0.f);
                }
                const size_t ob = (size_t)mo * Ntot + n;
                if (outF) *(float2*)&outF[ob] = make_float2(v0, v1);
                if (outHi) {
                    __half h0 = __float2half_rn(v0), h1 = __float2half_rn(v1);
                    *(__half2*)&outHi[ob] = __halves2half2(h0, h1);
                    *(__half2*)&outLo[ob] = __halves2half2(
                        __float2half_rn(v0 - __half2float(h0)),
                        __float2half_rn(v1 - __half2float(h1)));
                }
            }
}

// ====================== prep kernels ==========================================
// x fp32 -> fp16 hi/lo
__global__ void __launch_bounds__(256) split_x_kernel(
    const float* __restrict__ src, __half* __restrict__ hi, __half* __restrict__ lo)
{
    int i = blockIdx.x * blockDim.x + threadIdx.x;   // over NT*CC
    float v = src[i];
    __half h = __float2half_rn(v);
    hi[i] = h;
    lo[i] = __float2half_rn(v - __half2float(h));
}

// all weights fp32 -> fp16 (single), one launch
__global__ void __launch_bounds__(256) prep_weights_kernel(
    const float* __restrict__ Win, const float* __restrict__ ip,
    const float* __restrict__ xp,  const float* __restrict__ dtp,
    const float* __restrict__ op,  const float* __restrict__ Wo,
    __half* __restrict__ dWin, __half* __restrict__ dip,
    __half* __restrict__ dxp,  __half* __restrict__ ddtp,
    __half* __restrict__ dop,  __half* __restrict__ dWo)
{
    const int s0 = CC * CC, s1 = 2 * DIN * CC, s2 = 64 * DIN,
              s3 = DIN * DTR, s4 = CC * DIN;
    int i = blockIdx.x * blockDim.x + threadIdx.x;
    if (i < s0) { dWin[i] = __float2half_rn(Win[i]); return; } i -= s0;
    if (i < s1) { dip[i]  = __float2half_rn(ip[i]);  return; } i -= s1;
    if (i < s2) { dxp[i]  = __float2half_rn(xp[i]);  return; } i -= s2;
    if (i < s3) { ddtp[i] = __float2half_rn(dtp[i]); return; } i -= s3;
    if (i < s4) { dop[i]  = __float2half_rn(op[i]);  return; } i -= s4;
    dWo[i] = __float2half_rn(Wo[i]);
}

// ---------------- depthwise causal conv (width 4) + bias + silu ---------------
__global__ void __launch_bounds__(256) conv_silu_kernel(
    const float* __restrict__ xz, const float* __restrict__ cw,
    const float* __restrict__ cb, float* __restrict__ xc,
    __half* __restrict__ xch, __half* __restrict__ xcl)
{
    int idx = blockIdx.x * blockDim.x + threadIdx.x;  // over NT*DIN
    int d   = idx & (DIN - 1);
    int row = idx >> 10;
    int l   = row & (LL - 1);

    float acc = cb[d];
    #pragma unroll
    for (int j = 0; j < DCONV; j++) {
        int ls = l - (DCONV - 1) + j;
        if (ls >= 0)
            acc = fmaf(cw[d * DCONV + j],
                       xz[(long)(row - (DCONV - 1 - j)) * (2 * DIN) + d], acc);
    }
    float v = acc / (1.f + expf(-acc));   // silu
    xc[idx] = v;
    __half h = __float2half_rn(v);
    xch[idx] = h;
    xcl[idx] = __float2half_rn(v - __half2float(h));
}

// ---------------- selective scan + skip + gate --------------------------------
#define SCAN_LOAD(T0, FDT, FU, FB, FC, FZ) do { \
    _Pragma("unroll") \
    for (int _i = 0; _i < 8; _i++) { \
        long _row = base + (T0) + _i; \
        FDT[_i] = dt[_row * DIN + d]; \
        FU[_i]  = xc[_row * DIN + d]; \
        FB[_i]  = dbl[_row * 64 + DTR + s]; \
        FC[_i]  = dbl[_row * 64 + DTR + DS + s]; \
        FZ[_i]  = xz[_row * (2 * DIN) + DIN + d]; \
    } \
} while (0)

#define SCAN_COMPUTE(T0, FDT, FU, FB, FC, FZ) do { \
    float _p[8]; \
    _Pragma("unroll") \
    for (int _i = 0; _i < 8; _i++) { \
        float _dA = expf(FDT[_i] * Aa); \
        h = fmaf(_dA, h, FDT[_i] * FB[_i] * FU[_i]); \
        _p[_i] = h * FC[_i]; \
    } \
    _Pragma("unroll") \
    for (int _i = 0; _i < 8; _i++) { \
        _p[_i] += __shfl_xor_sync(0xffffffffu, _p[_i], 8, 16); \
        _p[_i] += __shfl_xor_sync(0xffffffffu, _p[_i], 4, 16); \
        _p[_i] += __shfl_xor_sync(0xffffffffu, _p[_i], 2, 16); \
        _p[_i] += __shfl_xor_sync(0xffffffffu, _p[_i], 1, 16); \
    } \
    if (s == 0) { \
        _Pragma("unroll") \
        for (int _i = 0; _i < 8; _i++) { \
            float _g = FZ[_i] / (1.f + expf(-FZ[_i])); \
            sm_y[_i][dl] = (_p[_i] + FU[_i] * Dd) * _g; \
        } \
    } \
    __syncthreads(); \
    if (threadIdx.x < 64) { \
        int _ti = threadIdx.x >> 3, _dd = threadIdx.x & 7; \
        float _yy = sm_y[_ti][_dd]; \
        long _idx = (base + (T0) + _ti) * DIN + (long)blockIdx.x * 8 + _dd; \
        __half _hh = __float2half_rn(_yy); \
        yh[_idx] = _hh; \
        yl[_idx] = __float2half_rn(_yy - __half2float(_hh)); \
    } \
    __syncthreads(); \
} while (0)

__global__ void __launch_bounds__(128) scan_kernel(
    const float* __restrict__ dt, const float* __restrict__ dbl,
    const float* __restrict__ xc, const float* __restrict__ xz,
    const float* __restrict__ A_log, const float* __restrict__ Dp,
    __half* __restrict__ yh, __half* __restrict__ yl)
{
    __shared__ float sm_y[8][8];
    const int b  = blockIdx.y;
    const int s  = threadIdx.x & 15;
    const int dl = threadIdx.x >> 4;
    const int d  = blockIdx.x * 8 + dl;

    const float Aa = -expf(A_log[d * DS + s]);
    const float Dd = Dp[d];

    float h = 0.f;
    const long base = (long)b * LL;

    float dtA[8], uA[8], BA[8], CA[8], zA[8];
    float dtB[8], uB[8], BB[8], CB[8], zB[8];

    SCAN_LOAD(0, dtA, uA, BA, CA, zA);
    for (int t0 = 0; t0 < LL; t0 += 16) {
        SCAN_LOAD(t0 + 8, dtB, uB, BB, CB, zB);
        SCAN_COMPUTE(t0, dtA, uA, BA, CA, zA);
        if (t0 + 16 < LL) SCAN_LOAD(t0 + 16, dtA, uA, BA, CA, zA);
        SCAN_COMPUTE(t0 + 8, dtB, uB, BB, CB, zB);
    }
}

// ---------------- launch -------------------------------------------------------
extern "C" void kernel_launch(void* const* d_in, const int* in_sizes, int n_in,
                              void* d_out, int out_size)
{
    const float* x          = (const float*)d_in[1];
    const int*   order      = (const int*)  d_in[3];
    const int*   inv        = (const int*)  d_in[4];
    const float* W_in       = (const float*)d_in[5];
    const float* bn_in_g    = (const float*)d_in[6];
    const float* bn_in_b    = (const float*)d_in[7];
    const float* bn_in_m    = (const float*)d_in[8];
    const float* bn_in_v    = (const float*)d_in[9];
    const float* in_proj_w  = (const float*)d_in[10];
    const float* conv_w     = (const float*)d_in[11];
    const float* conv_b     = (const float*)d_in[12];
    const float* x_proj_w   = (const float*)d_in[13];
    const float* dt_proj_w  = (const float*)d_in[14];
    const float* dt_proj_b  = (const float*)d_in[15];
    const float* A_log      = (const float*)d_in[16];
    const float* Dp         = (const float*)d_in[17];
    const float* out_proj_w = (const float*)d_in[18];
    const float* W_out      = (const float*)d_in[19];
    const float* bn_o_g     = (const float*)d_in[20];
    const float* bn_o_b     = (const float*)d_in[21];
    const float* bn_o_m     = (const float*)d_in[22];
    const float* bn_o_v     = (const float*)d_in[23];
    float* out = (float*)d_out;

    float *xz, *xc, *dbl, *dt;
    cudaGetSymbolAddress((void**)&xz,  g_xz);
    cudaGetSymbolAddress((void**)&xc,  g_xc);
    cudaGetSymbolAddress((void**)&dbl, g_dbl);
    cudaGetSymbolAddress((void**)&dt,  g_dt);

    __half *xhi, *xlo, *hgh, *hgl, *xch, *xcl, *dbh, *dbL, *yh, *yl, *ogh, *ogl;
    __half *Winh, *iph, *xph, *dtph, *oph, *Woh;
    cudaGetSymbolAddress((void**)&xhi, g_x_hi);   cudaGetSymbolAddress((void**)&xlo, g_x_lo);
    cudaGetSymbolAddress((void**)&hgh, g_hg_hi);  cudaGetSymbolAddress((void**)&hgl, g_hg_lo);
    cudaGetSymbolAddress((void**)&xch, g_xc_hi);  cudaGetSymbolAddress((void**)&xcl, g_xc_lo);
    cudaGetSymbolAddress((void**)&dbh, g_db_hi);  cudaGetSymbolAddress((void**)&dbL, g_db_lo);
    cudaGetSymbolAddress((void**)&yh,  g_y_hi);   cudaGetSymbolAddress((void**)&yl,  g_y_lo);
    cudaGetSymbolAddress((void**)&ogh, g_og_hi);  cudaGetSymbolAddress((void**)&ogl, g_og_lo);
    cudaGetSymbolAddress((void**)&Winh, g_Win_h);
    cudaGetSymbolAddress((void**)&iph,  g_ip_h);
    cudaGetSymbolAddress((void**)&xph,  g_xp_h);
    cudaGetSymbolAddress((void**)&dtph, g_dtp_h);
    cudaGetSymbolAddress((void**)&oph,  g_op_h);
    cudaGetSymbolAddress((void**)&Woh,  g_Wo_h);

    // dynamic SMEM: 3 stages x (2*MT + NTILE) rows x 80B
    const int SMEM_BIG   = 3 * (2 * 128 + 128) * 80;   // 92160
    const int SMEM_SMALL = 3 * (2 * 64 + 64) * 80;     // 46080
    cudaFuncSetAttribute((const void*)gemm_fp16<128,128,4,2>,
                         cudaFuncAttributeMaxDynamicSharedMemorySize, SMEM_BIG);
    cudaFuncSetAttribute((const void*)gemm_fp16<64,64,2,4>,
                         cudaFuncAttributeMaxDynamicSharedMemorySize, SMEM_SMALL);

    // prep: x split + weight fp16 conversion
    split_x_kernel<<<NT * CC / 256, 256>>>(x, xhi, xlo);
    {
        const int total = CC*CC + 2*DIN*CC + 64*DIN + DIN*DTR + CC*DIN + CC*CC;
        prep_weights_kernel<<<(total + 255) / 256, 256>>>(
            W_in, in_proj_w, x_proj_w, dt_proj_w, out_proj_w, W_out,
            Winh, iph, xph, dtph, oph, Woh);
    }

    // 1) hg = split(relu(BN(x @ W_in^T))) scattered by inv  ==  split(h[order])
    gemm_fp16<128,128,4,2><<<dim3(CC/128, NT/128), 256, SMEM_BIG>>>(
        xhi, xlo, CC, Winh, CC, nullptr, hgh, hgl, inv, CC, 1,
        bn_in_g, bn_in_b, bn_in_m, bn_in_v, nullptr);

    // 2) xz = hg @ in_proj_w^T   (fp32)
    gemm_fp16<128,128,4,2><<<dim3(2*DIN/128, NT/128), 256, SMEM_BIG>>>(
        hgh, hgl, CC, iph, CC, xz, nullptr, nullptr, nullptr, 2*DIN, 0,
        nullptr, nullptr, nullptr, nullptr, nullptr);

    // 3) xc = silu(conv(xm) + b)  (fp32 + fp16 pair)
    conv_silu_kernel<<<(NT * DIN) / 256, 256>>>(xz, conv_w, conv_b, xc, xch, xcl);

    // 4) dbl = xc @ x_proj_w^T   (fp32 + fp16 pair), N=64
    gemm_fp16<64,64,2,4><<<dim3(1, NT/64), 256, SMEM_SMALL>>>(
        xch, xcl, DIN, xph, DIN, dbl, dbh, dbL, nullptr, 64, 0,
        nullptr, nullptr, nullptr, nullptr, nullptr);

    // 5) dt = softplus(dt_low @ dt_proj_w^T + b), K=32 (lda=64 into dbl)
    gemm_fp16<128,128,4,2><<<dim3(DIN/128, NT/128), 256, SMEM_BIG>>>(
        dbh, dbL, 64, dtph, DTR, dt, nullptr, nullptr, nullptr, DIN, 2,
        dt_proj_b, nullptr, nullptr, nullptr, nullptr);

    // 6) selective scan + D skip + silu(z) gate -> y (fp16 pair)
    scan_kernel<<<dim3(DIN / 8, NB), 128>>>(dt, dbl, xc, xz, A_log, Dp, yh, yl);

    // 7) og = split(y @ out_proj_w^T) scattered by order == split(o1[inv])
    gemm_fp16<128,128,4,2><<<dim3(CC/128, NT/128), 256, SMEM_BIG>>>(
        yh, yl, DIN, oph, DIN, nullptr, ogh, ogl, order, CC, 0,
        nullptr, nullptr, nullptr, nullptr, nullptr);

    // 8) out = relu(BN(og @ W_out^T) + x)
    gemm_fp16<128,128,4,2><<<dim3(CC/128, NT/128), 256, SMEM_BIG>>>(
        ogh, ogl, CC, Woh, CC, out, nullptr, nullptr, nullptr, CC, 3,
        bn_o_g, bn_o_b, bn_o_m, bn_o_v, x);
}

// round 5
// speedup vs baseline: 6.2353x; 1.1132x over previous
#include <cuda_runtime.h>
#include <cuda_fp16.h>
#include <math.h>
#include <stdint.h>

// Problem constants
#define NB 4
#define LL 2048
#define CC 512
#define DIN 1024
#define DS 16
#define DCONV 4
#define DTR 32
#define NT (NB * LL)   // 8192 rows
#define EPSBN 1e-5f

// ---------------- scratch (device globals; no allocation allowed) -------------
__device__ __align__(256) float g_xc [NT * DIN];       // 32 MB (scan input u)
__device__ __align__(256) float g_dbl[NT * 64];        // 2 MB  (dt_low|B|C)
__device__ __align__(256) float g_dt [NT * DIN];       // 32 MB

// fp16 activations (single precision)
__device__ __align__(256) __half g_x16 [NT * CC];
__device__ __align__(256) __half g_hg16[NT * CC];
__device__ __align__(256) __half g_xz16[NT * 2 * DIN];
__device__ __align__(256) __half g_xc16[NT * DIN];
__device__ __align__(256) __half g_db16[NT * 64];
__device__ __align__(256) __half g_y16 [NT * DIN];
__device__ __align__(256) __half g_og16[NT * CC];
// fp16 weights
__device__ __align__(256) __half g_Win_h[CC * CC];
__device__ __align__(256) __half g_ip_h [2 * DIN * CC];
__device__ __align__(256) __half g_xp_h [64 * DIN];
__device__ __align__(256) __half g_dtp_h[DIN * DTR];
__device__ __align__(256) __half g_op_h [CC * DIN];
__device__ __align__(256) __half g_Wo_h [CC * CC];

// ============================ PTX helpers =====================================
__device__ __forceinline__ uint32_t smem_u32(const void* p) {
    uint32_t a;
    asm("{ .reg .u64 t; cvta.to.shared.u64 t, %1; cvt.u32.u64 %0, t; }"
        : "=r"(a) : "l"(p));
    return a;
}
__device__ __forceinline__ void cpa16(uint32_t d, const void* s) {
    asm volatile("cp.async.cg.shared.global [%0], [%1], 16;" :: "r"(d), "l"(s));
}
#define CP_COMMIT asm volatile("cp.async.commit_group;" ::: "memory")
#define CP_WAIT2  asm volatile("cp.async.wait_group 2;"  ::: "memory")

__device__ __forceinline__ void ldsm4(uint32_t* r, uint32_t a) {
    asm volatile("ldmatrix.sync.aligned.m8n8.x4.shared.b16 {%0,%1,%2,%3}, [%4];"
        : "=r"(r[0]), "=r"(r[1]), "=r"(r[2]), "=r"(r[3]) : "r"(a));
}
__device__ __forceinline__ void mma16816(float* c, const uint32_t* a, const uint32_t* b) {
    asm volatile(
        "mma.sync.aligned.m16n8k16.row.col.f32.f16.f16.f32 "
        "{%0,%1,%2,%3}, {%4,%5,%6,%7}, {%8,%9}, {%0,%1,%2,%3};"
        : "+f"(c[0]), "+f"(c[1]), "+f"(c[2]), "+f"(c[3])
        : "r"(a[0]), "r"(a[1]), "r"(a[2]), "r"(a[3]), "r"(b[0]), "r"(b[1]));
}

// ====================== single-term fp16 HMMA GEMM ============================
// C[M,N] = epi( A[M,K] @ W[N,K]^T ), A/W fp16. CTA MT x NTILE, 256 thr, 8 warps
// (WMW x WNW), 4-stage cp.async pipeline. SMEM rows padded to 40 halves (80B).
// Outputs: outF fp32 and/or outH fp16; rows scattered via scat.
// epi: 0 none | 1 BN+relu | 2 softplus(v+p0[n]) | 3 BN + addsrc + relu
template <int MT, int NTILE>
__device__ __forceinline__ void load_stage(
    uint32_t base, int tid, int m0, int n0, int lda, int K, int c,
    const __half* A, const __half* W)
{
    const int k0 = c * 32;
    #pragma unroll
    for (int e = 0; e < MT * 4 / 256; e++) {
        int t = tid + e * 256;
        int r = t >> 2, g = t & 3;
        cpa16(base + r * 80 + g * 16, A + (size_t)(m0 + r) * lda + k0 + g * 8);
    }
    uint32_t dw = base + (uint32_t)MT * 80;
    #pragma unroll
    for (int e = 0; e < NTILE * 4 / 256; e++) {
        int t = tid + e * 256;
        int r = t >> 2, g = t & 3;
        cpa16(dw + r * 80 + g * 16, W + (size_t)(n0 + r) * K + k0 + g * 8);
    }
}

template <int MT, int NTILE, int WMW, int WNW>
__global__ void __launch_bounds__(256, 2) gemm_fp16(
    const __half* __restrict__ A, int lda,
    const __half* __restrict__ W, int K,
    float* __restrict__ outF, __half* __restrict__ outH,
    const int* __restrict__ scat, int Ntot, int epi,
    const float* __restrict__ p0, const float* __restrict__ p1,
    const float* __restrict__ p2, const float* __restrict__ p3,
    const float* __restrict__ addsrc)
{
    constexpr int WTM = MT / WMW;
    constexpr int WTN = NTILE / WNW;
    constexpr int MTFR = WTM / 16;
    constexpr int NT8 = WTN / 8;
    constexpr int STAGE = (MT + NTILE) * 80;

    extern __shared__ __align__(128) char smraw[];
    const uint32_t sb = smem_u32(smraw);

    const int tid = threadIdx.x;
    const int lane = tid & 31, warp = tid >> 5;
    const int wm = warp % WMW, wn = warp / WMW;
    const int m0 = blockIdx.y * MT;
    const int n0 = blockIdx.x * NTILE;

    float acc[MTFR][NT8][4] = {};

    const int nch = K >> 5;
    #pragma unroll
    for (int s = 0; s < 3; s++) {
        if (s < nch)
            load_stage<MT, NTILE>(sb + s * STAGE, tid, m0, n0, lda, K, s, A, W);
        CP_COMMIT;
    }

    const int lr = lane & 15;
    const int lc = (lane >> 4) << 3;

    for (int c = 0; c < nch; c++) {
        CP_WAIT2;
        __syncthreads();
        {
            int cn = c + 3;
            if (cn < nch)
                load_stage<MT, NTILE>(sb + (cn & 3) * STAGE, tid, m0, n0, lda, K, cn, A, W);
            CP_COMMIT;
        }
        const uint32_t cur = sb + (uint32_t)(c & 3) * STAGE;
        #pragma unroll
        for (int kk = 0; kk < 32; kk += 16) {
            uint32_t af[MTFR][4];
            #pragma unroll
            for (int mt = 0; mt < MTFR; mt++)
                ldsm4(af[mt], cur + (uint32_t)((wm * WTM + mt * 16 + lr) * 80 + (kk + lc) * 2));
            uint32_t wf[NT8][2];
            #pragma unroll
            for (int p = 0; p < NT8 / 2; p++) {
                uint32_t a = cur + (uint32_t)((MT + wn * WTN + p * 16 + lr) * 80 + (kk + lc) * 2);
                uint32_t r4[4];
                ldsm4(r4, a);
                wf[2*p][0] = r4[0]; wf[2*p][1] = r4[2];
                wf[2*p+1][0] = r4[1]; wf[2*p+1][1] = r4[3];
            }
            #pragma unroll
            for (int mt = 0; mt < MTFR; mt++)
                #pragma unroll
                for (int nt = 0; nt < NT8; nt++)
                    mma16816(acc[mt][nt], af[mt], wf[nt]);
        }
    }

    // epilogue
    const int g = lane >> 2, tg = lane & 3;
    #pragma unroll
    for (int mt = 0; mt < MTFR; mt++)
        #pragma unroll
        for (int nt = 0; nt < NT8; nt++)
            #pragma unroll
            for (int rr = 0; rr < 2; rr++) {
                int m = m0 + wm * WTM + mt * 16 + g + rr * 8;
                int n = n0 + wn * WTN + nt * 8 + tg * 2;
                int mo = scat ? scat[m] : m;
                float v0 = acc[mt][nt][rr * 2 + 0];
                float v1 = acc[mt][nt][rr * 2 + 1];
                if (epi == 1) {
                    v0 = fmaxf((v0 - p2[n])   * rsqrtf(p3[n]   + EPSBN) * p0[n]   + p1[n],   0.f);
                    v1 = fmaxf((v1 - p2[n+1]) * rsqrtf(p3[n+1] + EPSBN) * p0[n+1] + p1[n+1], 0.f);
                } else if (epi == 2) {
                    v0 += p0[n];   v0 = (v0 > 20.f) ? v0 : log1pf(expf(v0));
                    v1 += p0[n+1]; v1 = (v1 > 20.f) ? v1 : log1pf(expf(v1));
                } else if (epi == 3) {
                    v0 = (v0 - p2[n])   * rsqrtf(p3[n]   + EPSBN) * p0[n]   + p1[n];
                    v1 = (v1 - p2[n+1]) * rsqrtf(p3[n+1] + EPSBN) * p0[n+1] + p1[n+1];
                    v0 = fmaxf(v0 + addsrc[(size_t)mo * Ntot + n], 0.f);
                    v1 = fmaxf(v1 + addsrc[(size_t)mo * Ntot + n + 1], 0.f);
                }
                const size_t ob = (size_t)mo * Ntot + n;
                if (outF) *(float2*)&outF[ob] = make_float2(v0, v1);
                if (outH)
                    *(__half2*)&outH[ob] =
                        __halves2half2(__float2half_rn(v0), __float2half_rn(v1));
            }
}

// ====================== prep kernels ==========================================
__global__ void __launch_bounds__(256) tofp16_x_kernel(
    const float* __restrict__ src, __half* __restrict__ dst)
{
    int i = blockIdx.x * blockDim.x + threadIdx.x;   // over NT*CC
    dst[i] = __float2half_rn(src[i]);
}

__global__ void __launch_bounds__(256) prep_weights_kernel(
    const float* __restrict__ Win, const float* __restrict__ ip,
    const float* __restrict__ xp,  const float* __restrict__ dtp,
    const float* __restrict__ op,  const float* __restrict__ Wo,
    __half* __restrict__ dWin, __half* __restrict__ dip,
    __half* __restrict__ dxp,  __half* __restrict__ ddtp,
    __half* __restrict__ dop,  __half* __restrict__ dWo)
{
    const int s0 = CC * CC, s1 = 2 * DIN * CC, s2 = 64 * DIN,
              s3 = DIN * DTR, s4 = CC * DIN;
    int i = blockIdx.x * blockDim.x + threadIdx.x;
    if (i < s0) { dWin[i] = __float2half_rn(Win[i]); return; } i -= s0;
    if (i < s1) { dip[i]  = __float2half_rn(ip[i]);  return; } i -= s1;
    if (i < s2) { dxp[i]  = __float2half_rn(xp[i]);  return; } i -= s2;
    if (i < s3) { ddtp[i] = __float2half_rn(dtp[i]); return; } i -= s3;
    if (i < s4) { dop[i]  = __float2half_rn(op[i]);  return; } i -= s4;
    dWo[i] = __float2half_rn(Wo[i]);
}

// ---------------- depthwise causal conv (width 4) + bias + silu ---------------
__global__ void __launch_bounds__(256) conv_silu_kernel(
    const __half* __restrict__ xz, const float* __restrict__ cw,
    const float* __restrict__ cb, float* __restrict__ xc,
    __half* __restrict__ xch)
{
    int idx = blockIdx.x * blockDim.x + threadIdx.x;  // over NT*DIN
    int d   = idx & (DIN - 1);
    int row = idx >> 10;
    int l   = row & (LL - 1);

    float acc = cb[d];
    #pragma unroll
    for (int j = 0; j < DCONV; j++) {
        int ls = l - (DCONV - 1) + j;
        if (ls >= 0)
            acc = fmaf(cw[d * DCONV + j],
                       __half2float(xz[(long)(row - (DCONV - 1 - j)) * (2 * DIN) + d]), acc);
    }
    float v = acc / (1.f + expf(-acc));   // silu
    xc[idx]  = v;
    xch[idx] = __float2half_rn(v);
}

// ---------------- selective scan + skip + gate --------------------------------
#define SCAN_LOAD(T0, FDT, FU, FB, FC, FZ) do { \
    _Pragma("unroll") \
    for (int _i = 0; _i < 8; _i++) { \
        long _row = base + (T0) + _i; \
        FDT[_i] = dt[_row * DIN + d]; \
        FU[_i]  = xc[_row * DIN + d]; \
        FB[_i]  = dbl[_row * 64 + DTR + s]; \
        FC[_i]  = dbl[_row * 64 + DTR + DS + s]; \
        FZ[_i]  = __half2float(xz[_row * (2 * DIN) + DIN + d]); \
    } \
} while (0)

#define SCAN_COMPUTE(T0, FDT, FU, FB, FC, FZ) do { \
    float _p[8]; \
    _Pragma("unroll") \
    for (int _i = 0; _i < 8; _i++) { \
        float _dA = expf(FDT[_i] * Aa); \
        h = fmaf(_dA, h, FDT[_i] * FB[_i] * FU[_i]); \
        _p[_i] = h * FC[_i]; \
    } \
    _Pragma("unroll") \
    for (int _i = 0; _i < 8; _i++) { \
        _p[_i] += __shfl_xor_sync(0xffffffffu, _p[_i], 8, 16); \
        _p[_i] += __shfl_xor_sync(0xffffffffu, _p[_i], 4, 16); \
        _p[_i] += __shfl_xor_sync(0xffffffffu, _p[_i], 2, 16); \
        _p[_i] += __shfl_xor_sync(0xffffffffu, _p[_i], 1, 16); \
    } \
    if (s == 0) { \
        _Pragma("unroll") \
        for (int _i = 0; _i < 8; _i++) { \
            float _g = FZ[_i] / (1.f + expf(-FZ[_i])); \
            sm_y[_i][dl] = (_p[_i] + FU[_i] * Dd) * _g; \
        } \
    } \
    __syncthreads(); \
    if (threadIdx.x < 64) { \
        int _ti = threadIdx.x >> 3, _dd = threadIdx.x & 7; \
        long _idx = (base + (T0) + _ti) * DIN + (long)blockIdx.x * 8 + _dd; \
        yh[_idx] = __float2half_rn(sm_y[_ti][_dd]); \
    } \
    __syncthreads(); \
} while (0)

__global__ void __launch_bounds__(128) scan_kernel(
    const float* __restrict__ dt, const float* __restrict__ dbl,
    const float* __restrict__ xc, const __half* __restrict__ xz,
    const float* __restrict__ A_log, const float* __restrict__ Dp,
    __half* __restrict__ yh)
{
    __shared__ float sm_y[8][8];
    const int b  = blockIdx.y;
    const int s  = threadIdx.x & 15;
    const int dl = threadIdx.x >> 4;
    const int d  = blockIdx.x * 8 + dl;

    const float Aa = -expf(A_log[d * DS + s]);
    const float Dd = Dp[d];

    float h = 0.f;
    const long base = (long)b * LL;

    float dtA[8], uA[8], BA[8], CA[8], zA[8];
    float dtB[8], uB[8], BB[8], CB[8], zB[8];

    SCAN_LOAD(0, dtA, uA, BA, CA, zA);
    for (int t0 = 0; t0 < LL; t0 += 16) {
        SCAN_LOAD(t0 + 8, dtB, uB, BB, CB, zB);
        SCAN_COMPUTE(t0, dtA, uA, BA, CA, zA);
        if (t0 + 16 < LL) SCAN_LOAD(t0 + 16, dtA, uA, BA, CA, zA);
        SCAN_COMPUTE(t0 + 8, dtB, uB, BB, CB, zB);
    }
}

// ---------------- launch -------------------------------------------------------
extern "C" void kernel_launch(void* const* d_in, const int* in_sizes, int n_in,
                              void* d_out, int out_size)
{
    const float* x          = (const float*)d_in[1];
    const int*   order      = (const int*)  d_in[3];
    const int*   inv        = (const int*)  d_in[4];
    const float* W_in       = (const float*)d_in[5];
    const float* bn_in_g    = (const float*)d_in[6];
    const float* bn_in_b    = (const float*)d_in[7];
    const float* bn_in_m    = (const float*)d_in[8];
    const float* bn_in_v    = (const float*)d_in[9];
    const float* in_proj_w  = (const float*)d_in[10];
    const float* conv_w     = (const float*)d_in[11];
    const float* conv_b     = (const float*)d_in[12];
    const float* x_proj_w   = (const float*)d_in[13];
    const float* dt_proj_w  = (const float*)d_in[14];
    const float* dt_proj_b  = (const float*)d_in[15];
    const float* A_log      = (const float*)d_in[16];
    const float* Dp         = (const float*)d_in[17];
    const float* out_proj_w = (const float*)d_in[18];
    const float* W_out      = (const float*)d_in[19];
    const float* bn_o_g     = (const float*)d_in[20];
    const float* bn_o_b     = (const float*)d_in[21];
    const float* bn_o_m     = (const float*)d_in[22];
    const float* bn_o_v     = (const float*)d_in[23];
    float* out = (float*)d_out;

    float *xc, *dbl, *dt;
    cudaGetSymbolAddress((void**)&xc,  g_xc);
    cudaGetSymbolAddress((void**)&dbl, g_dbl);
    cudaGetSymbolAddress((void**)&dt,  g_dt);

    __half *x16, *hg16, *xz16, *xc16, *db16, *y16, *og16;
    __half *Winh, *iph, *xph, *dtph, *oph, *Woh;
    cudaGetSymbolAddress((void**)&x16,  g_x16);
    cudaGetSymbolAddress((void**)&hg16, g_hg16);
    cudaGetSymbolAddress((void**)&xz16, g_xz16);
    cudaGetSymbolAddress((void**)&xc16, g_xc16);
    cudaGetSymbolAddress((void**)&db16, g_db16);
    cudaGetSymbolAddress((void**)&y16,  g_y16);
    cudaGetSymbolAddress((void**)&og16, g_og16);
    cudaGetSymbolAddress((void**)&Winh, g_Win_h);
    cudaGetSymbolAddress((void**)&iph,  g_ip_h);
    cudaGetSymbolAddress((void**)&xph,  g_xp_h);
    cudaGetSymbolAddress((void**)&dtph, g_dtp_h);
    cudaGetSymbolAddress((void**)&oph,  g_op_h);
    cudaGetSymbolAddress((void**)&Woh,  g_Wo_h);

    // dynamic SMEM: 4 stages x (MT + NTILE) rows x 80B
    const int SMEM_BIG   = 4 * (128 + 128) * 80;   // 81920
    const int SMEM_SMALL = 4 * (64 + 64) * 80;     // 40960
    cudaFuncSetAttribute((const void*)gemm_fp16<128,128,4,2>,
                         cudaFuncAttributeMaxDynamicSharedMemorySize, SMEM_BIG);
    cudaFuncSetAttribute((const void*)gemm_fp16<64,64,2,4>,
                         cudaFuncAttributeMaxDynamicSharedMemorySize, SMEM_SMALL);

    // prep
    tofp16_x_kernel<<<NT * CC / 256, 256>>>(x, x16);
    {
        const int total = CC*CC + 2*DIN*CC + 64*DIN + DIN*DTR + CC*DIN + CC*CC;
        prep_weights_kernel<<<(total + 255) / 256, 256>>>(
            W_in, in_proj_w, x_proj_w, dt_proj_w, out_proj_w, W_out,
            Winh, iph, xph, dtph, oph, Woh);
    }

    // 1) hg = fp16(relu(BN(x @ W_in^T))) scattered by inv  ==  h[order]
    gemm_fp16<128,128,4,2><<<dim3(CC/128, NT/128), 256, SMEM_BIG>>>(
        x16, CC, Winh, CC, nullptr, hg16, inv, CC, 1,
        bn_in_g, bn_in_b, bn_in_m, bn_in_v, nullptr);

    // 2) xz = hg @ in_proj_w^T   (fp16)
    gemm_fp16<128,128,4,2><<<dim3(2*DIN/128, NT/128), 256, SMEM_BIG>>>(
        hg16, CC, iph, CC, nullptr, xz16, nullptr, 2*DIN, 0,
        nullptr, nullptr, nullptr, nullptr, nullptr);

    // 3) xc = silu(conv(xm) + b)   (fp32 + fp16)
    conv_silu_kernel<<<(NT * DIN) / 256, 256>>>(xz16, conv_w, conv_b, xc, xc16);

    // 4) dbl = xc @ x_proj_w^T   (fp32 + fp16), N=64
    gemm_fp16<64,64,2,4><<<dim3(1, NT/64), 256, SMEM_SMALL>>>(
        xc16, DIN, xph, DIN, dbl, db16, nullptr, 64, 0,
        nullptr, nullptr, nullptr, nullptr, nullptr);

    // 5) dt = softplus(dt_low @ dt_proj_w^T + b), K=32 (lda=64 into db16)
    gemm_fp16<128,128,4,2><<<dim3(DIN/128, NT/128), 256, SMEM_BIG>>>(
        db16, 64, dtph, DTR, dt, nullptr, nullptr, DIN, 2,
        dt_proj_b, nullptr, nullptr, nullptr, nullptr);

    // 6) selective scan + D skip + silu(z) gate -> y (fp16)
    scan_kernel<<<dim3(DIN / 8, NB), 128>>>(dt, dbl, xc, xz16, A_log, Dp, y16);

    // 7) og = fp16(y @ out_proj_w^T) scattered by order == o1[inv]
    gemm_fp16<128,128,4,2><<<dim3(CC/128, NT/128), 256, SMEM_BIG>>>(
        y16, DIN, oph, DIN, nullptr, og16, order, CC, 0,
        nullptr, nullptr, nullptr, nullptr, nullptr);

    // 8) out = relu(BN(og @ W_out^T) + x)
    gemm_fp16<128,128,4,2><<<dim3(CC/128, NT/128), 256, SMEM_BIG>>>(
        og16, CC, Woh, CC, out, nullptr, nullptr, CC, 3,
        bn_o_g, bn_o_b, bn_o_m, bn_o_v, x);
}

// round 6
// speedup vs baseline: 7.7347x; 1.2405x over previous
#include <cuda_runtime.h>
#include <cuda_fp16.h>
#include <math.h>
#include <stdint.h>

// Problem constants
#define NB 4
#define LL 2048
#define CC 512
#define DIN 1024
#define DS 16
#define DCONV 4
#define DTR 32
#define NT (NB * LL)   // 8192 rows
#define EPSBN 1e-5f

// ---------------- scratch (device globals; no allocation allowed) -------------
__device__ __align__(256) float g_xc [NT * DIN];       // 32 MB (scan input u)
__device__ __align__(256) float g_dbl[NT * 64];        // 2 MB  (dt_low|B|C)
__device__ __align__(256) float g_dt [NT * DIN];       // 32 MB

// fp16 activations (single precision)
__device__ __align__(256) __half g_x16 [NT * CC];
__device__ __align__(256) __half g_hg16[NT * CC];
__device__ __align__(256) __half g_xz16[NT * 2 * DIN];
__device__ __align__(256) __half g_xc16[NT * DIN];
__device__ __align__(256) __half g_db16[NT * 64];
__device__ __align__(256) __half g_y16 [NT * DIN];
__device__ __align__(256) __half g_og16[NT * CC];
// fp16 weights
__device__ __align__(256) __half g_Win_h[CC * CC];
__device__ __align__(256) __half g_ip_h [2 * DIN * CC];
__device__ __align__(256) __half g_xp_h [64 * DIN];
__device__ __align__(256) __half g_dtp_h[DIN * DTR];
__device__ __align__(256) __half g_op_h [CC * DIN];
__device__ __align__(256) __half g_Wo_h [CC * CC];

// ============================ PTX helpers =====================================
__device__ __forceinline__ uint32_t smem_u32(const void* p) {
    uint32_t a;
    asm("{ .reg .u64 t; cvta.to.shared.u64 t, %1; cvt.u32.u64 %0, t; }"
        : "=r"(a) : "l"(p));
    return a;
}
__device__ __forceinline__ void cpa16(uint32_t d, const void* s) {
    asm volatile("cp.async.cg.shared.global [%0], [%1], 16;" :: "r"(d), "l"(s));
}
#define CP_COMMIT asm volatile("cp.async.commit_group;" ::: "memory")
#define CP_WAIT2  asm volatile("cp.async.wait_group 2;"  ::: "memory")

__device__ __forceinline__ void ldsm4(uint32_t* r, uint32_t a) {
    asm volatile("ldmatrix.sync.aligned.m8n8.x4.shared.b16 {%0,%1,%2,%3}, [%4];"
        : "=r"(r[0]), "=r"(r[1]), "=r"(r[2]), "=r"(r[3]) : "r"(a));
}
__device__ __forceinline__ void mma16816(float* c, const uint32_t* a, const uint32_t* b) {
    asm volatile(
        "mma.sync.aligned.m16n8k16.row.col.f32.f16.f16.f32 "
        "{%0,%1,%2,%3}, {%4,%5,%6,%7}, {%8,%9}, {%0,%1,%2,%3};"
        : "+f"(c[0]), "+f"(c[1]), "+f"(c[2]), "+f"(c[3])
        : "r"(a[0]), "r"(a[1]), "r"(a[2]), "r"(a[3]), "r"(b[0]), "r"(b[1]));
}

// ====================== single-term fp16 HMMA GEMM ============================
// C[M,N] = epi( A[M,K] @ W[N,K]^T ), A/W fp16. CTA MT x NTILE, 256 thr, 8 warps
// (WMW x WNW), 4-stage cp.async pipeline. SMEM rows padded to 40 halves (80B).
// epi: 0 none | 1 BN+relu | 2 softplus(v+p0[n]) | 3 BN + addsrc + relu
template <int MT, int NTILE>
__device__ __forceinline__ void load_stage(
    uint32_t base, int tid, int m0, int n0, int lda, int K, int c,
    const __half* A, const __half* W)
{
    const int k0 = c * 32;
    #pragma unroll
    for (int e = 0; e < MT * 4 / 256; e++) {
        int t = tid + e * 256;
        int r = t >> 2, g = t & 3;
        cpa16(base + r * 80 + g * 16, A + (size_t)(m0 + r) * lda + k0 + g * 8);
    }
    uint32_t dw = base + (uint32_t)MT * 80;
    #pragma unroll
    for (int e = 0; e < NTILE * 4 / 256; e++) {
        int t = tid + e * 256;
        int r = t >> 2, g = t & 3;
        cpa16(dw + r * 80 + g * 16, W + (size_t)(n0 + r) * K + k0 + g * 8);
    }
}

template <int MT, int NTILE, int WMW, int WNW>
__global__ void __launch_bounds__(256, 2) gemm_fp16(
    const __half* __restrict__ A, int lda,
    const __half* __restrict__ W, int K,
    float* __restrict__ outF, __half* __restrict__ outH,
    const int* __restrict__ scat, int Ntot, int epi,
    const float* __restrict__ p0, const float* __restrict__ p1,
    const float* __restrict__ p2, const float* __restrict__ p3,
    const float* __restrict__ addsrc)
{
    constexpr int WTM = MT / WMW;
    constexpr int WTN = NTILE / WNW;
    constexpr int MTFR = WTM / 16;
    constexpr int NT8 = WTN / 8;
    constexpr int STAGE = (MT + NTILE) * 80;

    extern __shared__ __align__(128) char smraw[];
    const uint32_t sb = smem_u32(smraw);

    const int tid = threadIdx.x;
    const int lane = tid & 31, warp = tid >> 5;
    const int wm = warp % WMW, wn = warp / WMW;
    const int m0 = blockIdx.y * MT;
    const int n0 = blockIdx.x * NTILE;

    float acc[MTFR][NT8][4] = {};

    const int nch = K >> 5;
    #pragma unroll
    for (int s = 0; s < 3; s++) {
        if (s < nch)
            load_stage<MT, NTILE>(sb + s * STAGE, tid, m0, n0, lda, K, s, A, W);
        CP_COMMIT;
    }

    const int lr = lane & 15;
    const int lc = (lane >> 4) << 3;

    for (int c = 0; c < nch; c++) {
        CP_WAIT2;
        __syncthreads();
        {
            int cn = c + 3;
            if (cn < nch)
                load_stage<MT, NTILE>(sb + (cn & 3) * STAGE, tid, m0, n0, lda, K, cn, A, W);
            CP_COMMIT;
        }
        const uint32_t cur = sb + (uint32_t)(c & 3) * STAGE;
        #pragma unroll
        for (int kk = 0; kk < 32; kk += 16) {
            uint32_t af[MTFR][4];
            #pragma unroll
            for (int mt = 0; mt < MTFR; mt++)
                ldsm4(af[mt], cur + (uint32_t)((wm * WTM + mt * 16 + lr) * 80 + (kk + lc) * 2));
            uint32_t wf[NT8][2];
            #pragma unroll
            for (int p = 0; p < NT8 / 2; p++) {
                uint32_t a = cur + (uint32_t)((MT + wn * WTN + p * 16 + lr) * 80 + (kk + lc) * 2);
                uint32_t r4[4];
                ldsm4(r4, a);
                wf[2*p][0] = r4[0]; wf[2*p][1] = r4[2];
                wf[2*p+1][0] = r4[1]; wf[2*p+1][1] = r4[3];
            }
            #pragma unroll
            for (int mt = 0; mt < MTFR; mt++)
                #pragma unroll
                for (int nt = 0; nt < NT8; nt++)
                    mma16816(acc[mt][nt], af[mt], wf[nt]);
        }
    }

    // epilogue
    const int g = lane >> 2, tg = lane & 3;
    #pragma unroll
    for (int mt = 0; mt < MTFR; mt++)
        #pragma unroll
        for (int nt = 0; nt < NT8; nt++)
            #pragma unroll
            for (int rr = 0; rr < 2; rr++) {
                int m = m0 + wm * WTM + mt * 16 + g + rr * 8;
                int n = n0 + wn * WTN + nt * 8 + tg * 2;
                int mo = scat ? scat[m] : m;
                float v0 = acc[mt][nt][rr * 2 + 0];
                float v1 = acc[mt][nt][rr * 2 + 1];
                if (epi == 1) {
                    v0 = fmaxf((v0 - p2[n])   * rsqrtf(p3[n]   + EPSBN) * p0[n]   + p1[n],   0.f);
                    v1 = fmaxf((v1 - p2[n+1]) * rsqrtf(p3[n+1] + EPSBN) * p0[n+1] + p1[n+1], 0.f);
                } else if (epi == 2) {
                    v0 += p0[n];   v0 = (v0 > 20.f) ? v0 : __logf(1.f + __expf(v0));
                    v1 += p0[n+1]; v1 = (v1 > 20.f) ? v1 : __logf(1.f + __expf(v1));
                } else if (epi == 3) {
                    v0 = (v0 - p2[n])   * rsqrtf(p3[n]   + EPSBN) * p0[n]   + p1[n];
                    v1 = (v1 - p2[n+1]) * rsqrtf(p3[n+1] + EPSBN) * p0[n+1] + p1[n+1];
                    v0 = fmaxf(v0 + addsrc[(size_t)mo * Ntot + n], 0.f);
                    v1 = fmaxf(v1 + addsrc[(size_t)mo * Ntot + n + 1], 0.f);
                }
                const size_t ob = (size_t)mo * Ntot + n;
                if (outF) *(float2*)&outF[ob] = make_float2(v0, v1);
                if (outH)
                    *(__half2*)&outH[ob] =
                        __halves2half2(__float2half_rn(v0), __float2half_rn(v1));
            }
}

// ====================== prep kernels ==========================================
__global__ void __launch_bounds__(256) tofp16_x_kernel(
    const float* __restrict__ src, __half* __restrict__ dst)
{
    int i = blockIdx.x * blockDim.x + threadIdx.x;   // over NT*CC
    dst[i] = __float2half_rn(src[i]);
}

__global__ void __launch_bounds__(256) prep_weights_kernel(
    const float* __restrict__ Win, const float* __restrict__ ip,
    const float* __restrict__ xp,  const float* __restrict__ dtp,
    const float* __restrict__ op,  const float* __restrict__ Wo,
    __half* __restrict__ dWin, __half* __restrict__ dip,
    __half* __restrict__ dxp,  __half* __restrict__ ddtp,
    __half* __restrict__ dop,  __half* __restrict__ dWo)
{
    const int s0 = CC * CC, s1 = 2 * DIN * CC, s2 = 64 * DIN,
              s3 = DIN * DTR, s4 = CC * DIN;
    int i = blockIdx.x * blockDim.x + threadIdx.x;
    if (i < s0) { dWin[i] = __float2half_rn(Win[i]); return; } i -= s0;
    if (i < s1) { dip[i]  = __float2half_rn(ip[i]);  return; } i -= s1;
    if (i < s2) { dxp[i]  = __float2half_rn(xp[i]);  return; } i -= s2;
    if (i < s3) { ddtp[i] = __float2half_rn(dtp[i]); return; } i -= s3;
    if (i < s4) { dop[i]  = __float2half_rn(op[i]);  return; } i -= s4;
    dWo[i] = __float2half_rn(Wo[i]);
}

// ---------------- depthwise causal conv (width 4) + bias + silu ---------------
__global__ void __launch_bounds__(256) conv_silu_kernel(
    const __half* __restrict__ xz, const float* __restrict__ cw,
    const float* __restrict__ cb, float* __restrict__ xc,
    __half* __restrict__ xch)
{
    int idx = blockIdx.x * blockDim.x + threadIdx.x;  // over NT*DIN
    int d   = idx & (DIN - 1);
    int row = idx >> 10;
    int l   = row & (LL - 1);

    float acc = cb[d];
    #pragma unroll
    for (int j = 0; j < DCONV; j++) {
        int ls = l - (DCONV - 1) + j;
        if (ls >= 0)
            acc = fmaf(cw[d * DCONV + j],
                       __half2float(xz[(long)(row - (DCONV - 1 - j)) * (2 * DIN) + d]), acc);
    }
    float v = __fdividef(acc, 1.f + __expf(-acc));   // silu
    xc[idx]  = v;
    xch[idx] = __float2half_rn(v);
}

// ---------------- selective scan + skip + gate --------------------------------
#define SCAN_LOAD(T0, FDT, FU, FB, FC, FZ) do { \
    _Pragma("unroll") \
    for (int _i = 0; _i < 8; _i++) { \
        long _row = base + (T0) + _i; \
        FDT[_i] = dt[_row * DIN + d]; \
        FU[_i]  = xc[_row * DIN + d]; \
        FB[_i]  = dbl[_row * 64 + DTR + s]; \
        FC[_i]  = dbl[_row * 64 + DTR + DS + s]; \
        FZ[_i]  = __half2float(xz[_row * (2 * DIN) + DIN + d]); \
    } \
} while (0)

#define SCAN_COMPUTE(T0, FDT, FU, FB, FC, FZ) do { \
    float _p[8]; \
    _Pragma("unroll") \
    for (int _i = 0; _i < 8; _i++) { \
        float _dA = __expf(FDT[_i] * Aa); \
        h = fmaf(_dA, h, FDT[_i] * FB[_i] * FU[_i]); \
        _p[_i] = h * FC[_i]; \
    } \
    _Pragma("unroll") \
    for (int _i = 0; _i < 8; _i++) { \
        _p[_i] += __shfl_xor_sync(0xffffffffu, _p[_i], 8, 16); \
        _p[_i] += __shfl_xor_sync(0xffffffffu, _p[_i], 4, 16); \
        _p[_i] += __shfl_xor_sync(0xffffffffu, _p[_i], 2, 16); \
        _p[_i] += __shfl_xor_sync(0xffffffffu, _p[_i], 1, 16); \
    } \
    if (s == 0) { \
        _Pragma("unroll") \
        for (int _i = 0; _i < 8; _i++) { \
            float _g = __fdividef(FZ[_i], 1.f + __expf(-FZ[_i])); \
            sm_y[_i][dl] = (_p[_i] + FU[_i] * Dd) * _g; \
        } \
    } \
    __syncthreads(); \
    if (threadIdx.x < 64) { \
        int _ti = threadIdx.x >> 3, _dd = threadIdx.x & 7; \
        long _idx = (base + (T0) + _ti) * DIN + (long)blockIdx.x * 8 + _dd; \
        yh[_idx] = __float2half_rn(sm_y[_ti][_dd]); \
    } \
    __syncthreads(); \
} while (0)

__global__ void __launch_bounds__(128) scan_kernel(
    const float* __restrict__ dt, const float* __restrict__ dbl,
    const float* __restrict__ xc, const __half* __restrict__ xz,
    const float* __restrict__ A_log, const float* __restrict__ Dp,
    __half* __restrict__ yh)
{
    __shared__ float sm_y[8][8];
    const int b  = blockIdx.y;
    const int s  = threadIdx.x & 15;
    const int dl = threadIdx.x >> 4;
    const int d  = blockIdx.x * 8 + dl;

    const float Aa = -expf(A_log[d * DS + s]);   // once; keep accurate
    const float Dd = Dp[d];

    float h = 0.f;
    const long base = (long)b * LL;

    float dtA[8], uA[8], BA[8], CA[8], zA[8];
    float dtB[8], uB[8], BB[8], CB[8], zB[8];

    SCAN_LOAD(0, dtA, uA, BA, CA, zA);
    for (int t0 = 0; t0 < LL; t0 += 16) {
        SCAN_LOAD(t0 + 8, dtB, uB, BB, CB, zB);
        SCAN_COMPUTE(t0, dtA, uA, BA, CA, zA);
        if (t0 + 16 < LL) SCAN_LOAD(t0 + 16, dtA, uA, BA, CA, zA);
        SCAN_COMPUTE(t0 + 8, dtB, uB, BB, CB, zB);
    }
}

// ---------------- launch -------------------------------------------------------
extern "C" void kernel_launch(void* const* d_in, const int* in_sizes, int n_in,
                              void* d_out, int out_size)
{
    const float* x          = (const float*)d_in[1];
    const int*   order      = (const int*)  d_in[3];
    const int*   inv        = (const int*)  d_in[4];
    const float* W_in       = (const float*)d_in[5];
    const float* bn_in_g    = (const float*)d_in[6];
    const float* bn_in_b    = (const float*)d_in[7];
    const float* bn_in_m    = (const float*)d_in[8];
    const float* bn_in_v    = (const float*)d_in[9];
    const float* in_proj_w  = (const float*)d_in[10];
    const float* conv_w     = (const float*)d_in[11];
    const float* conv_b     = (const float*)d_in[12];
    const float* x_proj_w   = (const float*)d_in[13];
    const float* dt_proj_w  = (const float*)d_in[14];
    const float* dt_proj_b  = (const float*)d_in[15];
    const float* A_log      = (const float*)d_in[16];
    const float* Dp         = (const float*)d_in[17];
    const float* out_proj_w = (const float*)d_in[18];
    const float* W_out      = (const float*)d_in[19];
    const float* bn_o_g     = (const float*)d_in[20];
    const float* bn_o_b     = (const float*)d_in[21];
    const float* bn_o_m     = (const float*)d_in[22];
    const float* bn_o_v     = (const float*)d_in[23];
    float* out = (float*)d_out;

    float *xc, *dbl, *dt;
    cudaGetSymbolAddress((void**)&xc,  g_xc);
    cudaGetSymbolAddress((void**)&dbl, g_dbl);
    cudaGetSymbolAddress((void**)&dt,  g_dt);

    __half *x16, *hg16, *xz16, *xc16, *db16, *y16, *og16;
    __half *Winh, *iph, *xph, *dtph, *oph, *Woh;
    cudaGetSymbolAddress((void**)&x16,  g_x16);
    cudaGetSymbolAddress((void**)&hg16, g_hg16);
    cudaGetSymbolAddress((void**)&xz16, g_xz16);
    cudaGetSymbolAddress((void**)&xc16, g_xc16);
    cudaGetSymbolAddress((void**)&db16, g_db16);
    cudaGetSymbolAddress((void**)&y16,  g_y16);
    cudaGetSymbolAddress((void**)&og16, g_og16);
    cudaGetSymbolAddress((void**)&Winh, g_Win_h);
    cudaGetSymbolAddress((void**)&iph,  g_ip_h);
    cudaGetSymbolAddress((void**)&xph,  g_xp_h);
    cudaGetSymbolAddress((void**)&dtph, g_dtp_h);
    cudaGetSymbolAddress((void**)&oph,  g_op_h);
    cudaGetSymbolAddress((void**)&Woh,  g_Wo_h);

    const int SMEM_BIG   = 4 * (128 + 128) * 80;   // 81920
    const int SMEM_SMALL = 4 * (64 + 64) * 80;     // 40960
    cudaFuncSetAttribute((const void*)gemm_fp16<128,128,4,2>,
                         cudaFuncAttributeMaxDynamicSharedMemorySize, SMEM_BIG);
    cudaFuncSetAttribute((const void*)gemm_fp16<64,64,2,4>,
                         cudaFuncAttributeMaxDynamicSharedMemorySize, SMEM_SMALL);

    // prep
    tofp16_x_kernel<<<NT * CC / 256, 256>>>(x, x16);
    {
        const int total = CC*CC + 2*DIN*CC + 64*DIN + DIN*DTR + CC*DIN + CC*CC;
        prep_weights_kernel<<<(total + 255) / 256, 256>>>(
            W_in, in_proj_w, x_proj_w, dt_proj_w, out_proj_w, W_out,
            Winh, iph, xph, dtph, oph, Woh);
    }

    // 1) hg = fp16(relu(BN(x @ W_in^T))) scattered by inv  ==  h[order]
    gemm_fp16<128,128,4,2><<<dim3(CC/128, NT/128), 256, SMEM_BIG>>>(
        x16, CC, Winh, CC, nullptr, hg16, inv, CC, 1,
        bn_in_g, bn_in_b, bn_in_m, bn_in_v, nullptr);

    // 2) xz = hg @ in_proj_w^T   (fp16)
    gemm_fp16<128,128,4,2><<<dim3(2*DIN/128, NT/128), 256, SMEM_BIG>>>(
        hg16, CC, iph, CC, nullptr, xz16, nullptr, 2*DIN, 0,
        nullptr, nullptr, nullptr, nullptr, nullptr);

    // 3) xc = silu(conv(xm) + b)   (fp32 + fp16)
    conv_silu_kernel<<<(NT * DIN) / 256, 256>>>(xz16, conv_w, conv_b, xc, xc16);

    // 4) dbl = xc @ x_proj_w^T   (fp32 + fp16), N=64
    gemm_fp16<64,64,2,4><<<dim3(1, NT/64), 256, SMEM_SMALL>>>(
        xc16, DIN, xph, DIN, dbl, db16, nullptr, 64, 0,
        nullptr, nullptr, nullptr, nullptr, nullptr);

    // 5) dt = softplus(dt_low @ dt_proj_w^T + b), K=32 (lda=64 into db16)
    gemm_fp16<128,128,4,2><<<dim3(DIN/128, NT/128), 256, SMEM_BIG>>>(
        db16, 64, dtph, DTR, dt, nullptr, nullptr, DIN, 2,
        dt_proj_b, nullptr, nullptr, nullptr, nullptr);

    // 6) selective scan + D skip + silu(z) gate -> y (fp16)
    scan_kernel<<<dim3(DIN / 8, NB), 128>>>(dt, dbl, xc, xz16, A_log, Dp, y16);

    // 7) og = fp16(y @ out_proj_w^T) scattered by order == o1[inv]
    gemm_fp16<128,128,4,2><<<dim3(CC/128, NT/128), 256, SMEM_BIG>>>(
        y16, DIN, oph, DIN, nullptr, og16, order, CC, 0,
        nullptr, nullptr, nullptr, nullptr, nullptr);

    // 8) out = relu(BN(og @ W_out^T) + x)
    gemm_fp16<128,128,4,2><<<dim3(CC/128, NT/128), 256, SMEM_BIG>>>(
        og16, CC, Woh, CC, out, nullptr, nullptr, CC, 3,
        bn_o_g, bn_o_b, bn_o_m, bn_o_v, x);
}

// round 7
// speedup vs baseline: 8.0198x; 1.0369x over previous
#include <cuda_runtime.h>
#include <cuda_fp16.h>
#include <math.h>
#include <stdint.h>

// Problem constants
#define NB 4
#define LL 2048
#define CC 512
#define DIN 1024
#define DS 16
#define DCONV 4
#define DTR 32
#define NT (NB * LL)   // 8192 rows
#define EPSBN 1e-5f

// ---------------- scratch (device globals; no allocation allowed) -------------
// fp16 activations
__device__ __align__(256) __half  g_x16 [NT * CC];
__device__ __align__(256) __half  g_hg16[NT * CC];
__device__ __align__(256) __half  g_xz16[NT * 2 * DIN];
__device__ __align__(256) __half  g_xc16[NT * DIN];
__device__ __align__(256) __half  g_db16[NT * 64];
__device__ __align__(256) __half  g_dt16[NT * DIN];
__device__ __align__(256) __half2 g_uz16[NT * DIN];   // {u, z}
__device__ __align__(256) __half2 g_bc16[NT * DS];    // {B_s, C_s}
__device__ __align__(256) __half  g_y16 [NT * DIN];
__device__ __align__(256) __half  g_og16[NT * CC];
// fp16 weights
__device__ __align__(256) __half g_Win_h[CC * CC];
__device__ __align__(256) __half g_ip_h [2 * DIN * CC];
__device__ __align__(256) __half g_xp_h [64 * DIN];
__device__ __align__(256) __half g_dtp_h[DIN * DTR];
__device__ __align__(256) __half g_op_h [CC * DIN];
__device__ __align__(256) __half g_Wo_h [CC * CC];

// ============================ PTX helpers =====================================
__device__ __forceinline__ uint32_t smem_u32(const void* p) {
    uint32_t a;
    asm("{ .reg .u64 t; cvta.to.shared.u64 t, %1; cvt.u32.u64 %0, t; }"
        : "=r"(a) : "l"(p));
    return a;
}
__device__ __forceinline__ void cpa16(uint32_t d, const void* s) {
    asm volatile("cp.async.cg.shared.global [%0], [%1], 16;" :: "r"(d), "l"(s));
}
#define CP_COMMIT asm volatile("cp.async.commit_group;" ::: "memory")
#define CP_WAIT2  asm volatile("cp.async.wait_group 2;"  ::: "memory")

__device__ __forceinline__ void ldsm4(uint32_t* r, uint32_t a) {
    asm volatile("ldmatrix.sync.aligned.m8n8.x4.shared.b16 {%0,%1,%2,%3}, [%4];"
        : "=r"(r[0]), "=r"(r[1]), "=r"(r[2]), "=r"(r[3]) : "r"(a));
}
__device__ __forceinline__ void mma16816(float* c, const uint32_t* a, const uint32_t* b) {
    asm volatile(
        "mma.sync.aligned.m16n8k16.row.col.f32.f16.f16.f32 "
        "{%0,%1,%2,%3}, {%4,%5,%6,%7}, {%8,%9}, {%0,%1,%2,%3};"
        : "+f"(c[0]), "+f"(c[1]), "+f"(c[2]), "+f"(c[3])
        : "r"(a[0]), "r"(a[1]), "r"(a[2]), "r"(a[3]), "r"(b[0]), "r"(b[1]));
}

// ====================== single-term fp16 HMMA GEMM ============================
// C[M,N] = epi( A[M,K] @ W[N,K]^T ). CTA MT x NTILE, 256 thr, 8 warps
// (WMW x WNW), 4-stage cp.async pipeline. SMEM rows padded to 40 halves (80B).
// epi: 0 none | 1 BN+relu | 2 softplus(v+p0[n]) | 3 BN + addsrc + relu
template <int MT, int NTILE>
__device__ __forceinline__ void load_stage(
    uint32_t base, int tid, int m0, int n0, int lda, int K, int c,
    const __half* A, const __half* W)
{
    const int k0 = c * 32;
    #pragma unroll
    for (int e = 0; e < MT * 4 / 256; e++) {
        int t = tid + e * 256;
        int r = t >> 2, g = t & 3;
        cpa16(base + r * 80 + g * 16, A + (size_t)(m0 + r) * lda + k0 + g * 8);
    }
    uint32_t dw = base + (uint32_t)MT * 80;
    #pragma unroll
    for (int e = 0; e < NTILE * 4 / 256; e++) {
        int t = tid + e * 256;
        int r = t >> 2, g = t & 3;
        cpa16(dw + r * 80 + g * 16, W + (size_t)(n0 + r) * K + k0 + g * 8);
    }
}

template <int MT, int NTILE, int WMW, int WNW>
__global__ void __launch_bounds__(256, 2) gemm_fp16(
    const __half* __restrict__ A, int lda,
    const __half* __restrict__ W, int K,
    float* __restrict__ outF, __half* __restrict__ outH,
    const int* __restrict__ scat, int Ntot, int epi,
    const float* __restrict__ p0, const float* __restrict__ p1,
    const float* __restrict__ p2, const float* __restrict__ p3,
    const float* __restrict__ addsrc)
{
    constexpr int WTM = MT / WMW;
    constexpr int WTN = NTILE / WNW;
    constexpr int MTFR = WTM / 16;
    constexpr int NT8 = WTN / 8;
    constexpr int STAGE = (MT + NTILE) * 80;

    extern __shared__ __align__(128) char smraw[];
    const uint32_t sb = smem_u32(smraw);

    const int tid = threadIdx.x;
    const int lane = tid & 31, warp = tid >> 5;
    const int wm = warp % WMW, wn = warp / WMW;
    const int m0 = blockIdx.y * MT;
    const int n0 = blockIdx.x * NTILE;

    float acc[MTFR][NT8][4] = {};

    const int nch = K >> 5;
    #pragma unroll
    for (int s = 0; s < 3; s++) {
        if (s < nch)
            load_stage<MT, NTILE>(sb + s * STAGE, tid, m0, n0, lda, K, s, A, W);
        CP_COMMIT;
    }

    const int lr = lane & 15;
    const int lc = (lane >> 4) << 3;

    for (int c = 0; c < nch; c++) {
        CP_WAIT2;
        __syncthreads();
        {
            int cn = c + 3;
            if (cn < nch)
                load_stage<MT, NTILE>(sb + (cn & 3) * STAGE, tid, m0, n0, lda, K, cn, A, W);
            CP_COMMIT;
        }
        const uint32_t cur = sb + (uint32_t)(c & 3) * STAGE;
        #pragma unroll
        for (int kk = 0; kk < 32; kk += 16) {
            uint32_t af[MTFR][4];
            #pragma unroll
            for (int mt = 0; mt < MTFR; mt++)
                ldsm4(af[mt], cur + (uint32_t)((wm * WTM + mt * 16 + lr) * 80 + (kk + lc) * 2));
            uint32_t wf[NT8][2];
            #pragma unroll
            for (int p = 0; p < NT8 / 2; p++) {
                uint32_t a = cur + (uint32_t)((MT + wn * WTN + p * 16 + lr) * 80 + (kk + lc) * 2);
                uint32_t r4[4];
                ldsm4(r4, a);
                wf[2*p][0] = r4[0]; wf[2*p][1] = r4[2];
                wf[2*p+1][0] = r4[1]; wf[2*p+1][1] = r4[3];
            }
            #pragma unroll
            for (int mt = 0; mt < MTFR; mt++)
                #pragma unroll
                for (int nt = 0; nt < NT8; nt++)
                    mma16816(acc[mt][nt], af[mt], wf[nt]);
        }
    }

    // epilogue
    const int g = lane >> 2, tg = lane & 3;
    #pragma unroll
    for (int mt = 0; mt < MTFR; mt++)
        #pragma unroll
        for (int nt = 0; nt < NT8; nt++)
            #pragma unroll
            for (int rr = 0; rr < 2; rr++) {
                int m = m0 + wm * WTM + mt * 16 + g + rr * 8;
                int n = n0 + wn * WTN + nt * 8 + tg * 2;
                int mo = scat ? scat[m] : m;
                float v0 = acc[mt][nt][rr * 2 + 0];
                float v1 = acc[mt][nt][rr * 2 + 1];
                if (epi == 1) {
                    v0 = fmaxf((v0 - p2[n])   * rsqrtf(p3[n]   + EPSBN) * p0[n]   + p1[n],   0.f);
                    v1 = fmaxf((v1 - p2[n+1]) * rsqrtf(p3[n+1] + EPSBN) * p0[n+1] + p1[n+1], 0.f);
                } else if (epi == 2) {
                    v0 += p0[n];   v0 = (v0 > 20.f) ? v0 : __logf(1.f + __expf(v0));
                    v1 += p0[n+1]; v1 = (v1 > 20.f) ? v1 : __logf(1.f + __expf(v1));
                } else if (epi == 3) {
                    v0 = (v0 - p2[n])   * rsqrtf(p3[n]   + EPSBN) * p0[n]   + p1[n];
                    v1 = (v1 - p2[n+1]) * rsqrtf(p3[n+1] + EPSBN) * p0[n+1] + p1[n+1];
                    v0 = fmaxf(v0 + addsrc[(size_t)mo * Ntot + n], 0.f);
                    v1 = fmaxf(v1 + addsrc[(size_t)mo * Ntot + n + 1], 0.f);
                }
                const size_t ob = (size_t)mo * Ntot + n;
                if (outF) *(float2*)&outF[ob] = make_float2(v0, v1);
                if (outH)
                    *(__half2*)&outH[ob] =
                        __halves2half2(__float2half_rn(v0), __float2half_rn(v1));
            }
}

// ====================== prep kernels ==========================================
__global__ void __launch_bounds__(256) tofp16_x_kernel(
    const float* __restrict__ src, __half* __restrict__ dst)
{
    int i = blockIdx.x * blockDim.x + threadIdx.x;   // over NT*CC
    dst[i] = __float2half_rn(src[i]);
}

__global__ void __launch_bounds__(256) prep_weights_kernel(
    const float* __restrict__ Win, const float* __restrict__ ip,
    const float* __restrict__ xp,  const float* __restrict__ dtp,
    const float* __restrict__ op,  const float* __restrict__ Wo,
    __half* __restrict__ dWin, __half* __restrict__ dip,
    __half* __restrict__ dxp,  __half* __restrict__ ddtp,
    __half* __restrict__ dop,  __half* __restrict__ dWo)
{
    const int s0 = CC * CC, s1 = 2 * DIN * CC, s2 = 64 * DIN,
              s3 = DIN * DTR, s4 = CC * DIN;
    int i = blockIdx.x * blockDim.x + threadIdx.x;
    if (i < s0) { dWin[i] = __float2half_rn(Win[i]); return; } i -= s0;
    if (i < s1) { dip[i]  = __float2half_rn(ip[i]);  return; } i -= s1;
    if (i < s2) { dxp[i]  = __float2half_rn(xp[i]);  return; } i -= s2;
    if (i < s3) { ddtp[i] = __float2half_rn(dtp[i]); return; } i -= s3;
    if (i < s4) { dop[i]  = __float2half_rn(op[i]);  return; } i -= s4;
    dWo[i] = __float2half_rn(Wo[i]);
}

// BC pack: db16[row][32+s], db16[row][48+s] -> bc16[row][s] = {B, C}
__global__ void __launch_bounds__(256) pack_bc_kernel(
    const __half* __restrict__ db16, __half2* __restrict__ bc16)
{
    int i = blockIdx.x * blockDim.x + threadIdx.x;   // over NT*DS
    int s = i & (DS - 1), row = i >> 4;
    bc16[i] = __halves2half2(db16[row * 64 + DTR + s], db16[row * 64 + DTR + DS + s]);
}

// ---------------- depthwise causal conv (width 4) + bias + silu ---------------
// Writes xc16 (GEMM4 input) and packed {u, z} for the scan.
__global__ void __launch_bounds__(256) conv_silu_kernel(
    const __half* __restrict__ xz, const float* __restrict__ cw,
    const float* __restrict__ cb, __half* __restrict__ xch,
    __half2* __restrict__ uz)
{
    int idx = blockIdx.x * blockDim.x + threadIdx.x;  // over NT*DIN
    int d   = idx & (DIN - 1);
    int row = idx >> 10;
    int l   = row & (LL - 1);

    float acc = cb[d];
    #pragma unroll
    for (int j = 0; j < DCONV; j++) {
        int ls = l - (DCONV - 1) + j;
        if (ls >= 0)
            acc = fmaf(cw[d * DCONV + j],
                       __half2float(xz[(long)(row - (DCONV - 1 - j)) * (2 * DIN) + d]), acc);
    }
    float v = __fdividef(acc, 1.f + __expf(-acc));   // silu(u)
    __half z = xz[(long)row * (2 * DIN) + DIN + d];
    xch[idx] = __float2half_rn(v);
    uz[idx]  = __halves2half2(__float2half_rn(v), z);
}

// ---------------- selective scan + skip + gate --------------------------------
// 3 LDG per step: dt16 (b16 broadcast), uz (b32 broadcast), bc (b32 per-s).
#define SCAN_LOAD(T0, FDT, FU, FB, FC, FZ) do { \
    _Pragma("unroll") \
    for (int _i = 0; _i < 8; _i++) { \
        long _row = base + (T0) + _i; \
        FDT[_i] = __half2float(dt16[_row * DIN + d]); \
        float2 _uz = __half22float2(uz[_row * DIN + d]); \
        FU[_i] = _uz.x; FZ[_i] = _uz.y; \
        float2 _bc = __half22float2(bc[_row * DS + s]); \
        FB[_i] = _bc.x; FC[_i] = _bc.y; \
    } \
} while (0)

#define SCAN_COMPUTE(T0, FDT, FU, FB, FC, FZ) do { \
    float _p[8]; \
    _Pragma("unroll") \
    for (int _i = 0; _i < 8; _i++) { \
        float _dA = __expf(FDT[_i] * Aa); \
        h = fmaf(_dA, h, FDT[_i] * FB[_i] * FU[_i]); \
        _p[_i] = h * FC[_i]; \
    } \
    _Pragma("unroll") \
    for (int _i = 0; _i < 8; _i++) { \
        _p[_i] += __shfl_xor_sync(0xffffffffu, _p[_i], 8, 16); \
        _p[_i] += __shfl_xor_sync(0xffffffffu, _p[_i], 4, 16); \
        _p[_i] += __shfl_xor_sync(0xffffffffu, _p[_i], 2, 16); \
        _p[_i] += __shfl_xor_sync(0xffffffffu, _p[_i], 1, 16); \
    } \
    if (s == 0) { \
        _Pragma("unroll") \
        for (int _i = 0; _i < 8; _i++) { \
            float _g = __fdividef(FZ[_i], 1.f + __expf(-FZ[_i])); \
            sm_y[_i][dl] = (_p[_i] + FU[_i] * Dd) * _g; \
        } \
    } \
    __syncthreads(); \
    if (threadIdx.x < 64) { \
        int _ti = threadIdx.x >> 3, _dd = threadIdx.x & 7; \
        long _idx = (base + (T0) + _ti) * DIN + (long)blockIdx.x * 8 + _dd; \
        yh[_idx] = __float2half_rn(sm_y[_ti][_dd]); \
    } \
    __syncthreads(); \
} while (0)

__global__ void __launch_bounds__(128) scan_kernel(
    const __half* __restrict__ dt16, const __half2* __restrict__ bc,
    const __half2* __restrict__ uz,
    const float* __restrict__ A_log, const float* __restrict__ Dp,
    __half* __restrict__ yh)
{
    __shared__ float sm_y[8][8];
    const int b  = blockIdx.y;
    const int s  = threadIdx.x & 15;
    const int dl = threadIdx.x >> 4;
    const int d  = blockIdx.x * 8 + dl;

    const float Aa = -expf(A_log[d * DS + s]);
    const float Dd = Dp[d];

    float h = 0.f;
    const long base = (long)b * LL;

    float dtA[8], uA[8], BA[8], CA[8], zA[8];
    float dtB[8], uB[8], BB[8], CB[8], zB[8];

    SCAN_LOAD(0, dtA, uA, BA, CA, zA);
    for (int t0 = 0; t0 < LL; t0 += 16) {
        SCAN_LOAD(t0 + 8, dtB, uB, BB, CB, zB);
        SCAN_COMPUTE(t0, dtA, uA, BA, CA, zA);
        if (t0 + 16 < LL) SCAN_LOAD(t0 + 16, dtA, uA, BA, CA, zA);
        SCAN_COMPUTE(t0 + 8, dtB, uB, BB, CB, zB);
    }
}

// ---------------- launch -------------------------------------------------------
extern "C" void kernel_launch(void* const* d_in, const int* in_sizes, int n_in,
                              void* d_out, int out_size)
{
    const float* x          = (const float*)d_in[1];
    const int*   order      = (const int*)  d_in[3];
    const int*   inv        = (const int*)  d_in[4];
    const float* W_in       = (const float*)d_in[5];
    const float* bn_in_g    = (const float*)d_in[6];
    const float* bn_in_b    = (const float*)d_in[7];
    const float* bn_in_m    = (const float*)d_in[8];
    const float* bn_in_v    = (const float*)d_in[9];
    const float* in_proj_w  = (const float*)d_in[10];
    const float* conv_w     = (const float*)d_in[11];
    const float* conv_b     = (const float*)d_in[12];
    const float* x_proj_w   = (const float*)d_in[13];
    const float* dt_proj_w  = (const float*)d_in[14];
    const float* dt_proj_b  = (const float*)d_in[15];
    const float* A_log      = (const float*)d_in[16];
    const float* Dp         = (const float*)d_in[17];
    const float* out_proj_w = (const float*)d_in[18];
    const float* W_out      = (const float*)d_in[19];
    const float* bn_o_g     = (const float*)d_in[20];
    const float* bn_o_b     = (const float*)d_in[21];
    const float* bn_o_m     = (const float*)d_in[22];
    const float* bn_o_v     = (const float*)d_in[23];
    float* out = (float*)d_out;

    __half *x16, *hg16, *xz16, *xc16, *db16, *dt16, *y16, *og16;
    __half2 *uz16, *bc16;
    __half *Winh, *iph, *xph, *dtph, *oph, *Woh;
    cudaGetSymbolAddress((void**)&x16,  g_x16);
    cudaGetSymbolAddress((void**)&hg16, g_hg16);
    cudaGetSymbolAddress((void**)&xz16, g_xz16);
    cudaGetSymbolAddress((void**)&xc16, g_xc16);
    cudaGetSymbolAddress((void**)&db16, g_db16);
    cudaGetSymbolAddress((void**)&dt16, g_dt16);
    cudaGetSymbolAddress((void**)&uz16, g_uz16);
    cudaGetSymbolAddress((void**)&bc16, g_bc16);
    cudaGetSymbolAddress((void**)&y16,  g_y16);
    cudaGetSymbolAddress((void**)&og16, g_og16);
    cudaGetSymbolAddress((void**)&Winh, g_Win_h);
    cudaGetSymbolAddress((void**)&iph,  g_ip_h);
    cudaGetSymbolAddress((void**)&xph,  g_xp_h);
    cudaGetSymbolAddress((void**)&dtph, g_dtp_h);
    cudaGetSymbolAddress((void**)&oph,  g_op_h);
    cudaGetSymbolAddress((void**)&Woh,  g_Wo_h);

    const int SMEM_BIG   = 4 * (128 + 128) * 80;   // 81920
    const int SMEM_SMALL = 4 * (64 + 64) * 80;     // 40960
    cudaFuncSetAttribute((const void*)gemm_fp16<128,128,4,2>,
                         cudaFuncAttributeMaxDynamicSharedMemorySize, SMEM_BIG);
    cudaFuncSetAttribute((const void*)gemm_fp16<64,64,2,4>,
                         cudaFuncAttributeMaxDynamicSharedMemorySize, SMEM_SMALL);

    // prep
    tofp16_x_kernel<<<NT * CC / 256, 256>>>(x, x16);
    {
        const int total = CC*CC + 2*DIN*CC + 64*DIN + DIN*DTR + CC*DIN + CC*CC;
        prep_weights_kernel<<<(total + 255) / 256, 256>>>(
            W_in, in_proj_w, x_proj_w, dt_proj_w, out_proj_w, W_out,
            Winh, iph, xph, dtph, oph, Woh);
    }

    // 1) hg = fp16(relu(BN(x @ W_in^T))) scattered by inv  ==  h[order]
    gemm_fp16<128,128,4,2><<<dim3(CC/128, NT/128), 256, SMEM_BIG>>>(
        x16, CC, Winh, CC, nullptr, hg16, inv, CC, 1,
        bn_in_g, bn_in_b, bn_in_m, bn_in_v, nullptr);

    // 2) xz = hg @ in_proj_w^T   (fp16)
    gemm_fp16<128,128,4,2><<<dim3(2*DIN/128, NT/128), 256, SMEM_BIG>>>(
        hg16, CC, iph, CC, nullptr, xz16, nullptr, 2*DIN, 0,
        nullptr, nullptr, nullptr, nullptr, nullptr);

    // 3) xc16 + packed {u,z}
    conv_silu_kernel<<<(NT * DIN) / 256, 256>>>(xz16, conv_w, conv_b, xc16, uz16);

    // 4) db16 = fp16(xc @ x_proj_w^T), N=64
    gemm_fp16<64,64,2,4><<<dim3(1, NT/64), 256, SMEM_SMALL>>>(
        xc16, DIN, xph, DIN, nullptr, db16, nullptr, 64, 0,
        nullptr, nullptr, nullptr, nullptr, nullptr);

    // 4b) pack {B,C}
    pack_bc_kernel<<<NT * DS / 256, 256>>>(db16, bc16);

    // 5) dt16 = fp16(softplus(dt_low @ dt_proj_w^T + b)), K=32 (lda=64 into db16)
    gemm_fp16<128,128,4,2><<<dim3(DIN/128, NT/128), 256, SMEM_BIG>>>(
        db16, 64, dtph, DTR, nullptr, dt16, nullptr, DIN, 2,
        dt_proj_b, nullptr, nullptr, nullptr, nullptr);

    // 6) selective scan + D skip + silu(z) gate -> y (fp16)
    scan_kernel<<<dim3(DIN / 8, NB), 128>>>(dt16, bc16, uz16, A_log, Dp, y16);

    // 7) og = fp16(y @ out_proj_w^T) scattered by order == o1[inv]
    gemm_fp16<128,128,4,2><<<dim3(CC/128, NT/128), 256, SMEM_BIG>>>(
        y16, DIN, oph, DIN, nullptr, og16, order, CC, 0,
        nullptr, nullptr, nullptr, nullptr, nullptr);

    // 8) out = relu(BN(og @ W_out^T) + x)
    gemm_fp16<128,128,4,2><<<dim3(CC/128, NT/128), 256, SMEM_BIG>>>(
        og16, CC, Woh, CC, out, nullptr, nullptr, CC, 3,
        bn_o_g, bn_o_b, bn_o_m, bn_o_v, x);
}

// round 8
// speedup vs baseline: 9.2540x; 1.1539x over previous
#include <cuda_runtime.h>
#include <cuda_fp16.h>
#include <math.h>
#include <stdint.h>

// Problem constants
#define NB 4
#define LL 2048
#define CC 512
#define DIN 1024
#define DS 16
#define DCONV 4
#define DTR 32
#define NT (NB * LL)   // 8192 rows
#define EPSBN 1e-5f

// ---------------- scratch (device globals; no allocation allowed) -------------
__device__ __align__(256) __half  g_x16 [NT * CC];
__device__ __align__(256) __half  g_hg16[NT * CC];
__device__ __align__(256) __half  g_xz16[NT * 2 * DIN];
__device__ __align__(256) __half  g_xc16[NT * DIN];
__device__ __align__(256) __half  g_db16[NT * 64];
__device__ __align__(256) __half  g_dt16[NT * DIN];
__device__ __align__(256) __half2 g_uz16[NT * DIN];   // {silu(u), silu(z)}
__device__ __align__(256) __half2 g_bc16[NT * DS];    // {B_s, C_s}
__device__ __align__(256) __half  g_y16 [NT * DIN];
__device__ __align__(256) __half  g_og16[NT * CC];
// fp16 weights
__device__ __align__(256) __half g_Win_h[CC * CC];
__device__ __align__(256) __half g_ip_h [2 * DIN * CC];
__device__ __align__(256) __half g_xp_h [64 * DIN];
__device__ __align__(256) __half g_dtp_h[DIN * DTR];
__device__ __align__(256) __half g_op_h [CC * DIN];
__device__ __align__(256) __half g_Wo_h [CC * CC];

// ============================ PTX helpers =====================================
__device__ __forceinline__ uint32_t smem_u32(const void* p) {
    uint32_t a;
    asm("{ .reg .u64 t; cvta.to.shared.u64 t, %1; cvt.u32.u64 %0, t; }"
        : "=r"(a) : "l"(p));
    return a;
}
__device__ __forceinline__ void cpa16(uint32_t d, const void* s) {
    asm volatile("cp.async.cg.shared.global [%0], [%1], 16;" :: "r"(d), "l"(s));
}
#define CP_COMMIT asm volatile("cp.async.commit_group;" ::: "memory")
#define CP_WAIT1  asm volatile("cp.async.wait_group 1;"  ::: "memory")
#define CP_WAIT2  asm volatile("cp.async.wait_group 2;"  ::: "memory")

__device__ __forceinline__ void ldsm4(uint32_t* r, uint32_t a) {
    asm volatile("ldmatrix.sync.aligned.m8n8.x4.shared.b16 {%0,%1,%2,%3}, [%4];"
        : "=r"(r[0]), "=r"(r[1]), "=r"(r[2]), "=r"(r[3]) : "r"(a));
}
__device__ __forceinline__ void mma16816(float* c, const uint32_t* a, const uint32_t* b) {
    asm volatile(
        "mma.sync.aligned.m16n8k16.row.col.f32.f16.f16.f32 "
        "{%0,%1,%2,%3}, {%4,%5,%6,%7}, {%8,%9}, {%0,%1,%2,%3};"
        : "+f"(c[0]), "+f"(c[1]), "+f"(c[2]), "+f"(c[3])
        : "r"(a[0]), "r"(a[1]), "r"(a[2]), "r"(a[3]), "r"(b[0]), "r"(b[1]));
}

// ====================== single-term fp16 HMMA GEMM ============================
// (unchanged from round 7 — known good at ~250 TF/s)
template <int MT, int NTILE>
__device__ __forceinline__ void load_stage(
    uint32_t base, int tid, int m0, int n0, int lda, int K, int c,
    const __half* A, const __half* W)
{
    const int k0 = c * 32;
    #pragma unroll
    for (int e = 0; e < MT * 4 / 256; e++) {
        int t = tid + e * 256;
        int r = t >> 2, g = t & 3;
        cpa16(base + r * 80 + g * 16, A + (size_t)(m0 + r) * lda + k0 + g * 8);
    }
    uint32_t dw = base + (uint32_t)MT * 80;
    #pragma unroll
    for (int e = 0; e < NTILE * 4 / 256; e++) {
        int t = tid + e * 256;
        int r = t >> 2, g = t & 3;
        cpa16(dw + r * 80 + g * 16, W + (size_t)(n0 + r) * K + k0 + g * 8);
    }
}

template <int MT, int NTILE, int WMW, int WNW>
__global__ void __launch_bounds__(256, 2) gemm_fp16(
    const __half* __restrict__ A, int lda,
    const __half* __restrict__ W, int K,
    float* __restrict__ outF, __half* __restrict__ outH,
    const int* __restrict__ scat, int Ntot, int epi,
    const float* __restrict__ p0, const float* __restrict__ p1,
    const float* __restrict__ p2, const float* __restrict__ p3,
    const float* __restrict__ addsrc)
{
    constexpr int WTM = MT / WMW;
    constexpr int WTN = NTILE / WNW;
    constexpr int MTFR = WTM / 16;
    constexpr int NT8 = WTN / 8;
    constexpr int STAGE = (MT + NTILE) * 80;

    extern __shared__ __align__(128) char smraw[];
    const uint32_t sb = smem_u32(smraw);

    const int tid = threadIdx.x;
    const int lane = tid & 31, warp = tid >> 5;
    const int wm = warp % WMW, wn = warp / WMW;
    const int m0 = blockIdx.y * MT;
    const int n0 = blockIdx.x * NTILE;

    float acc[MTFR][NT8][4] = {};

    const int nch = K >> 5;
    #pragma unroll
    for (int s = 0; s < 3; s++) {
        if (s < nch)
            load_stage<MT, NTILE>(sb + s * STAGE, tid, m0, n0, lda, K, s, A, W);
        CP_COMMIT;
    }

    const int lr = lane & 15;
    const int lc = (lane >> 4) << 3;

    for (int c = 0; c < nch; c++) {
        CP_WAIT2;
        __syncthreads();
        {
            int cn = c + 3;
            if (cn < nch)
                load_stage<MT, NTILE>(sb + (cn & 3) * STAGE, tid, m0, n0, lda, K, cn, A, W);
            CP_COMMIT;
        }
        const uint32_t cur = sb + (uint32_t)(c & 3) * STAGE;
        #pragma unroll
        for (int kk = 0; kk < 32; kk += 16) {
            uint32_t af[MTFR][4];
            #pragma unroll
            for (int mt = 0; mt < MTFR; mt++)
                ldsm4(af[mt], cur + (uint32_t)((wm * WTM + mt * 16 + lr) * 80 + (kk + lc) * 2));
            uint32_t wf[NT8][2];
            #pragma unroll
            for (int p = 0; p < NT8 / 2; p++) {
                uint32_t a = cur + (uint32_t)((MT + wn * WTN + p * 16 + lr) * 80 + (kk + lc) * 2);
                uint32_t r4[4];
                ldsm4(r4, a);
                wf[2*p][0] = r4[0]; wf[2*p][1] = r4[2];
                wf[2*p+1][0] = r4[1]; wf[2*p+1][1] = r4[3];
            }
            #pragma unroll
            for (int mt = 0; mt < MTFR; mt++)
                #pragma unroll
                for (int nt = 0; nt < NT8; nt++)
                    mma16816(acc[mt][nt], af[mt], wf[nt]);
        }
    }

    const int g = lane >> 2, tg = lane & 3;
    #pragma unroll
    for (int mt = 0; mt < MTFR; mt++)
        #pragma unroll
        for (int nt = 0; nt < NT8; nt++)
            #pragma unroll
            for (int rr = 0; rr < 2; rr++) {
                int m = m0 + wm * WTM + mt * 16 + g + rr * 8;
                int n = n0 + wn * WTN + nt * 8 + tg * 2;
                int mo = scat ? scat[m] : m;
                float v0 = acc[mt][nt][rr * 2 + 0];
                float v1 = acc[mt][nt][rr * 2 + 1];
                if (epi == 1) {
                    v0 = fmaxf((v0 - p2[n])   * rsqrtf(p3[n]   + EPSBN) * p0[n]   + p1[n],   0.f);
                    v1 = fmaxf((v1 - p2[n+1]) * rsqrtf(p3[n+1] + EPSBN) * p0[n+1] + p1[n+1], 0.f);
                } else if (epi == 2) {
                    v0 += p0[n];   v0 = (v0 > 20.f) ? v0 : __logf(1.f + __expf(v0));
                    v1 += p0[n+1]; v1 = (v1 > 20.f) ? v1 : __logf(1.f + __expf(v1));
                } else if (epi == 3) {
                    v0 = (v0 - p2[n])   * rsqrtf(p3[n]   + EPSBN) * p0[n]   + p1[n];
                    v1 = (v1 - p2[n+1]) * rsqrtf(p3[n+1] + EPSBN) * p0[n+1] + p1[n+1];
                    v0 = fmaxf(v0 + addsrc[(size_t)mo * Ntot + n], 0.f);
                    v1 = fmaxf(v1 + addsrc[(size_t)mo * Ntot + n + 1], 0.f);
                }
                const size_t ob = (size_t)mo * Ntot + n;
                if (outF) *(float2*)&outF[ob] = make_float2(v0, v1);
                if (outH)
                    *(__half2*)&outH[ob] =
                        __halves2half2(__float2half_rn(v0), __float2half_rn(v1));
            }
}

// ====================== prep (x + all weights -> fp16), one launch ============
__global__ void __launch_bounds__(256) prep_all_kernel(
    const float* __restrict__ x,
    const float* __restrict__ Win, const float* __restrict__ ip,
    const float* __restrict__ xp,  const float* __restrict__ dtp,
    const float* __restrict__ op,  const float* __restrict__ Wo,
    __half* __restrict__ dx,
    __half* __restrict__ dWin, __half* __restrict__ dip,
    __half* __restrict__ dxp,  __half* __restrict__ ddtp,
    __half* __restrict__ dop,  __half* __restrict__ dWo)
{
    const int sx = NT * CC, s0 = CC * CC, s1 = 2 * DIN * CC, s2 = 64 * DIN,
              s3 = DIN * DTR, s4 = CC * DIN;
    int i = blockIdx.x * blockDim.x + threadIdx.x;
    if (i < sx) { dx[i]   = __float2half_rn(x[i]);   return; } i -= sx;
    if (i < s0) { dWin[i] = __float2half_rn(Win[i]); return; } i -= s0;
    if (i < s1) { dip[i]  = __float2half_rn(ip[i]);  return; } i -= s1;
    if (i < s2) { dxp[i]  = __float2half_rn(xp[i]);  return; } i -= s2;
    if (i < s3) { ddtp[i] = __float2half_rn(dtp[i]); return; } i -= s3;
    if (i < s4) { dop[i]  = __float2half_rn(op[i]);  return; } i -= s4;
    dWo[i] = __float2half_rn(Wo[i]);
}

// BC pack: db16[row][32+s], db16[row][48+s] -> bc16[row][s] = {B, C}
__global__ void __launch_bounds__(256) pack_bc_kernel(
    const __half* __restrict__ db16, __half2* __restrict__ bc16)
{
    int i = blockIdx.x * blockDim.x + threadIdx.x;   // over NT*DS
    int s = i & (DS - 1), row = i >> 4;
    bc16[i] = __halves2half2(db16[row * 64 + DTR + s], db16[row * 64 + DTR + DS + s]);
}

// ---------------- depthwise causal conv + bias + silu; pack {u, gate} ---------
__global__ void __launch_bounds__(256) conv_silu_kernel(
    const __half* __restrict__ xz, const float* __restrict__ cw,
    const float* __restrict__ cb, __half* __restrict__ xch,
    __half2* __restrict__ uz)
{
    int idx = blockIdx.x * blockDim.x + threadIdx.x;  // over NT*DIN
    int d   = idx & (DIN - 1);
    int row = idx >> 10;
    int l   = row & (LL - 1);

    float acc = cb[d];
    #pragma unroll
    for (int j = 0; j < DCONV; j++) {
        int ls = l - (DCONV - 1) + j;
        if (ls >= 0)
            acc = fmaf(cw[d * DCONV + j],
                       __half2float(xz[(long)(row - (DCONV - 1 - j)) * (2 * DIN) + d]), acc);
    }
    float v = __fdividef(acc, 1.f + __expf(-acc));   // silu(u)
    float zf = __half2float(xz[(long)row * (2 * DIN) + DIN + d]);
    float gate = __fdividef(zf, 1.f + __expf(-zf));  // silu(z), precomputed
    xch[idx] = __float2half_rn(v);
    uz[idx]  = __halves2half2(__float2half_rn(v), __float2half_rn(gate));
}

// ---------------- selective scan: cp.async staged, 3-buffer pipeline ----------
// Block: 256 thr = 8 warps; warp = 2 d x 16 s; block covers 16 d-channels.
// Stage = 32 timesteps. Prefetch depth 2 stages (>=1500 cyc). 2 barriers/stage.
#define SDIM 16
#define SSTEP 32

__global__ void __launch_bounds__(256) scan_kernel(
    const __half* __restrict__ dtg, const __half2* __restrict__ bcg,
    const __half2* __restrict__ uzg,
    const float* __restrict__ A_log, const float* __restrict__ Dp,
    __half* __restrict__ yh)
{
    __shared__ __align__(16) __half  s_dt[3][SSTEP][SDIM];
    __shared__ __align__(16) __half2 s_uz[3][SSTEP][SDIM];
    __shared__ __align__(16) __half2 s_bc[3][SSTEP][DS];
    __shared__ __align__(16) __half  s_y[SSTEP][SDIM];

    const int tid  = threadIdx.x;
    const int warp = tid >> 5, lane = tid & 31;
    const int s    = lane & 15, dh = lane >> 4;
    const int dl   = warp * 2 + dh;
    const int d0   = blockIdx.x * SDIM;
    const int d    = d0 + dl;
    const long rbase = (long)blockIdx.y * LL;

    const float Aa = -expf(A_log[d * DS + s]);
    const float Dd = Dp[d];

    auto stage_load = [&](int st, int buf) {
        const long row0 = rbase + (long)st * SSTEP;
        #pragma unroll
        for (int j0 = 0; j0 < 320; j0 += 256) {
            int j = tid + j0;
            if (j < 64) {
                int r = j >> 1, q = j & 1;
                cpa16(smem_u32(&s_dt[buf][r][q * 8]),
                      dtg + (row0 + r) * DIN + d0 + q * 8);
            } else if (j < 192) {
                int u = j - 64; int r = u >> 2, q = u & 3;
                cpa16(smem_u32(&s_uz[buf][r][q * 4]),
                      uzg + (row0 + r) * DIN + d0 + q * 4);
            } else if (j < 320) {
                int v = j - 192; int r = v >> 2, q = v & 3;
                cpa16(smem_u32(&s_bc[buf][r][q * 4]),
                      bcg + (row0 + r) * DS + q * 4);
            }
        }
    };

    stage_load(0, 0); CP_COMMIT;
    stage_load(1, 1); CP_COMMIT;

    float h = 0.f;
    const int NST = LL / SSTEP;   // 64
    for (int ts = 0; ts < NST; ts++) {
        CP_WAIT1;
        __syncthreads();
        const int buf = ts % 3;
        if (ts + 2 < NST) stage_load(ts + 2, (ts + 2) % 3);
        CP_COMMIT;

        #pragma unroll
        for (int t8 = 0; t8 < SSTEP; t8 += 8) {
            float p8[8], g8[8];
            #pragma unroll
            for (int i = 0; i < 8; i++) {
                const int t = t8 + i;
                float  dtv = __half2float(s_dt[buf][t][dl]);
                float2 uzv = __half22float2(s_uz[buf][t][dl]);
                float2 bcv = __half22float2(s_bc[buf][t][s]);
                float dA = __expf(dtv * Aa);
                h = fmaf(dA, h, dtv * bcv.x * uzv.x);
                float p = h * bcv.y;
                if (s == 0) p = fmaf(uzv.x, Dd, p);   // fold u*D into the sum
                p8[i] = p;
                g8[i] = uzv.y;
            }
            #pragma unroll
            for (int i = 0; i < 8; i++) {
                p8[i] += __shfl_xor_sync(0xffffffffu, p8[i], 8, 16);
                p8[i] += __shfl_xor_sync(0xffffffffu, p8[i], 4, 16);
                p8[i] += __shfl_xor_sync(0xffffffffu, p8[i], 2, 16);
                p8[i] += __shfl_xor_sync(0xffffffffu, p8[i], 1, 16);
            }
            if (s == 0) {
                #pragma unroll
                for (int i = 0; i < 8; i++)
                    s_y[t8 + i][dl] = __float2half_rn(p8[i] * g8[i]);
            }
        }
        __syncthreads();
        // flush y: 256 threads x one u32 (32 rows x 32B, coalesced)
        {
            int r = tid >> 3, w = tid & 7;
            uint32_t val = ((const uint32_t*)&s_y[r][0])[w];
            *(uint32_t*)(yh + (rbase + ts * SSTEP + r) * DIN + d0 + w * 2) = val;
        }
    }
}

// ---------------- launch -------------------------------------------------------
extern "C" void kernel_launch(void* const* d_in, const int* in_sizes, int n_in,
                              void* d_out, int out_size)
{
    const float* x          = (const float*)d_in[1];
    const int*   order      = (const int*)  d_in[3];
    const int*   inv        = (const int*)  d_in[4];
    const float* W_in       = (const float*)d_in[5];
    const float* bn_in_g    = (const float*)d_in[6];
    const float* bn_in_b    = (const float*)d_in[7];
    const float* bn_in_m    = (const float*)d_in[8];
    const float* bn_in_v    = (const float*)d_in[9];
    const float* in_proj_w  = (const float*)d_in[10];
    const float* conv_w     = (const float*)d_in[11];
    const float* conv_b     = (const float*)d_in[12];
    const float* x_proj_w   = (const float*)d_in[13];
    const float* dt_proj_w  = (const float*)d_in[14];
    const float* dt_proj_b  = (const float*)d_in[15];
    const float* A_log      = (const float*)d_in[16];
    const float* Dp         = (const float*)d_in[17];
    const float* out_proj_w = (const float*)d_in[18];
    const float* W_out      = (const float*)d_in[19];
    const float* bn_o_g     = (const float*)d_in[20];
    const float* bn_o_b     = (const float*)d_in[21];
    const float* bn_o_m     = (const float*)d_in[22];
    const float* bn_o_v     = (const float*)d_in[23];
    float* out = (float*)d_out;

    __half *x16, *hg16, *xz16, *xc16, *db16, *dt16, *y16, *og16;
    __half2 *uz16, *bc16;
    __half *Winh, *iph, *xph, *dtph, *oph, *Woh;
    cudaGetSymbolAddress((void**)&x16,  g_x16);
    cudaGetSymbolAddress((void**)&hg16, g_hg16);
    cudaGetSymbolAddress((void**)&xz16, g_xz16);
    cudaGetSymbolAddress((void**)&xc16, g_xc16);
    cudaGetSymbolAddress((void**)&db16, g_db16);
    cudaGetSymbolAddress((void**)&dt16, g_dt16);
    cudaGetSymbolAddress((void**)&uz16, g_uz16);
    cudaGetSymbolAddress((void**)&bc16, g_bc16);
    cudaGetSymbolAddress((void**)&y16,  g_y16);
    cudaGetSymbolAddress((void**)&og16, g_og16);
    cudaGetSymbolAddress((void**)&Winh, g_Win_h);
    cudaGetSymbolAddress((void**)&iph,  g_ip_h);
    cudaGetSymbolAddress((void**)&xph,  g_xp_h);
    cudaGetSymbolAddress((void**)&dtph, g_dtp_h);
    cudaGetSymbolAddress((void**)&oph,  g_op_h);
    cudaGetSymbolAddress((void**)&Woh,  g_Wo_h);

    const int SMEM_BIG   = 4 * (128 + 128) * 80;   // 81920
    const int SMEM_SMALL = 4 * (64 + 64) * 80;     // 40960
    cudaFuncSetAttribute((const void*)gemm_fp16<128,128,4,2>,
                         cudaFuncAttributeMaxDynamicSharedMemorySize, SMEM_BIG);
    cudaFuncSetAttribute((const void*)gemm_fp16<64,64,2,4>,
                         cudaFuncAttributeMaxDynamicSharedMemorySize, SMEM_SMALL);

    // prep (x + weights) in one launch
    {
        const int total = NT*CC + CC*CC + 2*DIN*CC + 64*DIN + DIN*DTR + CC*DIN + CC*CC;
        prep_all_kernel<<<(total + 255) / 256, 256>>>(
            x, W_in, in_proj_w, x_proj_w, dt_proj_w, out_proj_w, W_out,
            x16, Winh, iph, xph, dtph, oph, Woh);
    }

    // 1) hg = fp16(relu(BN(x @ W_in^T))) scattered by inv  ==  h[order]
    gemm_fp16<128,128,4,2><<<dim3(CC/128, NT/128), 256, SMEM_BIG>>>(
        x16, CC, Winh, CC, nullptr, hg16, inv, CC, 1,
        bn_in_g, bn_in_b, bn_in_m, bn_in_v, nullptr);

    // 2) xz = hg @ in_proj_w^T   (fp16)
    gemm_fp16<128,128,4,2><<<dim3(2*DIN/128, NT/128), 256, SMEM_BIG>>>(
        hg16, CC, iph, CC, nullptr, xz16, nullptr, 2*DIN, 0,
        nullptr, nullptr, nullptr, nullptr, nullptr);

    // 3) xc16 + packed {u, gate}
    conv_silu_kernel<<<(NT * DIN) / 256, 256>>>(xz16, conv_w, conv_b, xc16, uz16);

    // 4) db16 = fp16(xc @ x_proj_w^T), N=64
    gemm_fp16<64,64,2,4><<<dim3(1, NT/64), 256, SMEM_SMALL>>>(
        xc16, DIN, xph, DIN, nullptr, db16, nullptr, 64, 0,
        nullptr, nullptr, nullptr, nullptr, nullptr);

    // 4b) pack {B,C}
    pack_bc_kernel<<<NT * DS / 256, 256>>>(db16, bc16);

    // 5) dt16 = fp16(softplus(dt_low @ dt_proj_w^T + b)), K=32 (lda=64)
    gemm_fp16<128,128,4,2><<<dim3(DIN/128, NT/128), 256, SMEM_BIG>>>(
        db16, 64, dtph, DTR, nullptr, dt16, nullptr, DIN, 2,
        dt_proj_b, nullptr, nullptr, nullptr, nullptr);

    // 6) selective scan (cp.async staged) -> y (fp16)
    scan_kernel<<<dim3(DIN / SDIM, NB), 256>>>(dt16, bc16, uz16, A_log, Dp, y16);

    // 7) og = fp16(y @ out_proj_w^T) scattered by order == o1[inv]
    gemm_fp16<128,128,4,2><<<dim3(CC/128, NT/128), 256, SMEM_BIG>>>(
        y16, DIN, oph, DIN, nullptr, og16, order, CC, 0,
        nullptr, nullptr, nullptr, nullptr, nullptr);

    // 8) out = relu(BN(og @ W_out^T) + x)
    gemm_fp16<128,128,4,2><<<dim3(CC/128, NT/128), 256, SMEM_BIG>>>(
        og16, CC, Woh, CC, out, nullptr, nullptr, CC, 3,
        bn_o_g, bn_o_b, bn_o_m, bn_o_v, x);
}

// round 9
// speedup vs baseline: 9.6447x; 1.0422x over previous
#include <cuda_runtime.h>
#include <cuda_fp16.h>
#include <math.h>
#include <stdint.h>

// Problem constants
#define NB 4
#define LL 2048
#define CC 512
#define DIN 1024
#define DS 16
#define DCONV 4
#define DTR 32
#define NT (NB * LL)   // 8192 rows
#define EPSBN 1e-5f

// ---------------- scratch (device globals; no allocation allowed) -------------
__device__ __align__(256) __half  g_x16 [NT * CC];
__device__ __align__(256) __half  g_hg16[NT * CC];
__device__ __align__(256) __half  g_xz16[NT * 2 * DIN];
__device__ __align__(256) __half  g_xc16[NT * DIN];
__device__ __align__(256) __half  g_db16[NT * 64];
__device__ __align__(256) __half  g_dt16[NT * DIN];
__device__ __align__(256) __half2 g_uz16[NT * DIN];   // {silu(u), silu(z)}
__device__ __align__(256) __half2 g_bc16[NT * DS];    // {B_s, C_s}
__device__ __align__(256) __half  g_y16 [NT * DIN];
__device__ __align__(256) __half  g_og16[NT * CC];
// fp16 weights
__device__ __align__(256) __half g_Win_h[CC * CC];
__device__ __align__(256) __half g_ip_h [2 * DIN * CC];
__device__ __align__(256) __half g_xp_h [64 * DIN];
__device__ __align__(256) __half g_dtp_h[DIN * DTR];
__device__ __align__(256) __half g_op_h [CC * DIN];
__device__ __align__(256) __half g_Wo_h [CC * CC];

// ============================ PTX helpers =====================================
__device__ __forceinline__ uint32_t smem_u32(const void* p) {
    uint32_t a;
    asm("{ .reg .u64 t; cvta.to.shared.u64 t, %1; cvt.u32.u64 %0, t; }"
        : "=r"(a) : "l"(p));
    return a;
}
__device__ __forceinline__ void cpa16(uint32_t d, const void* s) {
    asm volatile("cp.async.cg.shared.global [%0], [%1], 16;" :: "r"(d), "l"(s));
}
#define CP_COMMIT asm volatile("cp.async.commit_group;" ::: "memory")
#define CP_WAIT1  asm volatile("cp.async.wait_group 1;"  ::: "memory")
#define CP_WAIT2  asm volatile("cp.async.wait_group 2;"  ::: "memory")

__device__ __forceinline__ void ldsm4(uint32_t* r, uint32_t a) {
    asm volatile("ldmatrix.sync.aligned.m8n8.x4.shared.b16 {%0,%1,%2,%3}, [%4];"
        : "=r"(r[0]), "=r"(r[1]), "=r"(r[2]), "=r"(r[3]) : "r"(a));
}
__device__ __forceinline__ void mma16816(float* c, const uint32_t* a, const uint32_t* b) {
    asm volatile(
        "mma.sync.aligned.m16n8k16.row.col.f32.f16.f16.f32 "
        "{%0,%1,%2,%3}, {%4,%5,%6,%7}, {%8,%9}, {%0,%1,%2,%3};"
        : "+f"(c[0]), "+f"(c[1]), "+f"(c[2]), "+f"(c[3])
        : "r"(a[0]), "r"(a[1]), "r"(a[2]), "r"(a[3]), "r"(b[0]), "r"(b[1]));
}

// ====================== single-term fp16 HMMA GEMM ============================
// (unchanged — known good)
template <int MT, int NTILE>
__device__ __forceinline__ void load_stage(
    uint32_t base, int tid, int m0, int n0, int lda, int K, int c,
    const __half* A, const __half* W)
{
    const int k0 = c * 32;
    #pragma unroll
    for (int e = 0; e < MT * 4 / 256; e++) {
        int t = tid + e * 256;
        int r = t >> 2, g = t & 3;
        cpa16(base + r * 80 + g * 16, A + (size_t)(m0 + r) * lda + k0 + g * 8);
    }
    uint32_t dw = base + (uint32_t)MT * 80;
    #pragma unroll
    for (int e = 0; e < NTILE * 4 / 256; e++) {
        int t = tid + e * 256;
        int r = t >> 2, g = t & 3;
        cpa16(dw + r * 80 + g * 16, W + (size_t)(n0 + r) * K + k0 + g * 8);
    }
}

template <int MT, int NTILE, int WMW, int WNW>
__global__ void __launch_bounds__(256, 2) gemm_fp16(
    const __half* __restrict__ A, int lda,
    const __half* __restrict__ W, int K,
    float* __restrict__ outF, __half* __restrict__ outH,
    const int* __restrict__ scat, int Ntot, int epi,
    const float* __restrict__ p0, const float* __restrict__ p1,
    const float* __restrict__ p2, const float* __restrict__ p3,
    const float* __restrict__ addsrc)
{
    constexpr int WTM = MT / WMW;
    constexpr int WTN = NTILE / WNW;
    constexpr int MTFR = WTM / 16;
    constexpr int NT8 = WTN / 8;
    constexpr int STAGE = (MT + NTILE) * 80;

    extern __shared__ __align__(128) char smraw[];
    const uint32_t sb = smem_u32(smraw);

    const int tid = threadIdx.x;
    const int lane = tid & 31, warp = tid >> 5;
    const int wm = warp % WMW, wn = warp / WMW;
    const int m0 = blockIdx.y * MT;
    const int n0 = blockIdx.x * NTILE;

    float acc[MTFR][NT8][4] = {};

    const int nch = K >> 5;
    #pragma unroll
    for (int s = 0; s < 3; s++) {
        if (s < nch)
            load_stage<MT, NTILE>(sb + s * STAGE, tid, m0, n0, lda, K, s, A, W);
        CP_COMMIT;
    }

    const int lr = lane & 15;
    const int lc = (lane >> 4) << 3;

    for (int c = 0; c < nch; c++) {
        CP_WAIT2;
        __syncthreads();
        {
            int cn = c + 3;
            if (cn < nch)
                load_stage<MT, NTILE>(sb + (cn & 3) * STAGE, tid, m0, n0, lda, K, cn, A, W);
            CP_COMMIT;
        }
        const uint32_t cur = sb + (uint32_t)(c & 3) * STAGE;
        #pragma unroll
        for (int kk = 0; kk < 32; kk += 16) {
            uint32_t af[MTFR][4];
            #pragma unroll
            for (int mt = 0; mt < MTFR; mt++)
                ldsm4(af[mt], cur + (uint32_t)((wm * WTM + mt * 16 + lr) * 80 + (kk + lc) * 2));
            uint32_t wf[NT8][2];
            #pragma unroll
            for (int p = 0; p < NT8 / 2; p++) {
                uint32_t a = cur + (uint32_t)((MT + wn * WTN + p * 16 + lr) * 80 + (kk + lc) * 2);
                uint32_t r4[4];
                ldsm4(r4, a);
                wf[2*p][0] = r4[0]; wf[2*p][1] = r4[2];
                wf[2*p+1][0] = r4[1]; wf[2*p+1][1] = r4[3];
            }
            #pragma unroll
            for (int mt = 0; mt < MTFR; mt++)
                #pragma unroll
                for (int nt = 0; nt < NT8; nt++)
                    mma16816(acc[mt][nt], af[mt], wf[nt]);
        }
    }

    const int g = lane >> 2, tg = lane & 3;
    #pragma unroll
    for (int mt = 0; mt < MTFR; mt++)
        #pragma unroll
        for (int nt = 0; nt < NT8; nt++)
            #pragma unroll
            for (int rr = 0; rr < 2; rr++) {
                int m = m0 + wm * WTM + mt * 16 + g + rr * 8;
                int n = n0 + wn * WTN + nt * 8 + tg * 2;
                int mo = scat ? scat[m] : m;
                float v0 = acc[mt][nt][rr * 2 + 0];
                float v1 = acc[mt][nt][rr * 2 + 1];
                if (epi == 1) {
                    v0 = fmaxf((v0 - p2[n])   * rsqrtf(p3[n]   + EPSBN) * p0[n]   + p1[n],   0.f);
                    v1 = fmaxf((v1 - p2[n+1]) * rsqrtf(p3[n+1] + EPSBN) * p0[n+1] + p1[n+1], 0.f);
                } else if (epi == 2) {
                    v0 += p0[n];   v0 = (v0 > 20.f) ? v0 : __logf(1.f + __expf(v0));
                    v1 += p0[n+1]; v1 = (v1 > 20.f) ? v1 : __logf(1.f + __expf(v1));
                } else if (epi == 3) {
                    v0 = (v0 - p2[n])   * rsqrtf(p3[n]   + EPSBN) * p0[n]   + p1[n];
                    v1 = (v1 - p2[n+1]) * rsqrtf(p3[n+1] + EPSBN) * p0[n+1] + p1[n+1];
                    v0 = fmaxf(v0 + addsrc[(size_t)mo * Ntot + n], 0.f);
                    v1 = fmaxf(v1 + addsrc[(size_t)mo * Ntot + n + 1], 0.f);
                }
                const size_t ob = (size_t)mo * Ntot + n;
                if (outF) *(float2*)&outF[ob] = make_float2(v0, v1);
                if (outH)
                    *(__half2*)&outH[ob] =
                        __halves2half2(__float2half_rn(v0), __float2half_rn(v1));
            }
}

// ====================== prep (x + all weights -> fp16), one launch ============
__global__ void __launch_bounds__(256) prep_all_kernel(
    const float* __restrict__ x,
    const float* __restrict__ Win, const float* __restrict__ ip,
    const float* __restrict__ xp,  const float* __restrict__ dtp,
    const float* __restrict__ op,  const float* __restrict__ Wo,
    __half* __restrict__ dx,
    __half* __restrict__ dWin, __half* __restrict__ dip,
    __half* __restrict__ dxp,  __half* __restrict__ ddtp,
    __half* __restrict__ dop,  __half* __restrict__ dWo)
{
    const int sx = NT * CC, s0 = CC * CC, s1 = 2 * DIN * CC, s2 = 64 * DIN,
              s3 = DIN * DTR, s4 = CC * DIN;
    int i = blockIdx.x * blockDim.x + threadIdx.x;
    if (i < sx) { dx[i]   = __float2half_rn(x[i]);   return; } i -= sx;
    if (i < s0) { dWin[i] = __float2half_rn(Win[i]); return; } i -= s0;
    if (i < s1) { dip[i]  = __float2half_rn(ip[i]);  return; } i -= s1;
    if (i < s2) { dxp[i]  = __float2half_rn(xp[i]);  return; } i -= s2;
    if (i < s3) { ddtp[i] = __float2half_rn(dtp[i]); return; } i -= s3;
    if (i < s4) { dop[i]  = __float2half_rn(op[i]);  return; } i -= s4;
    dWo[i] = __float2half_rn(Wo[i]);
}

// BC pack: db16[row][32+s], db16[row][48+s] -> bc16[row][s] = {B, C}
__global__ void __launch_bounds__(256) pack_bc_kernel(
    const __half* __restrict__ db16, __half2* __restrict__ bc16)
{
    int i = blockIdx.x * blockDim.x + threadIdx.x;   // over NT*DS
    int s = i & (DS - 1), row = i >> 4;
    bc16[i] = __halves2half2(db16[row * 64 + DTR + s], db16[row * 64 + DTR + DS + s]);
}

// ---------------- depthwise causal conv + bias + silu (half2, 2 ch/thread) ----
__global__ void __launch_bounds__(256) conv_silu_kernel(
    const __half2* __restrict__ xz2,   // rows of DIN half2 (= 2*DIN halves)
    const float* __restrict__ cw, const float* __restrict__ cb,
    __half2* __restrict__ xch2, __half2* __restrict__ uz)
{
    int idx = blockIdx.x * blockDim.x + threadIdx.x;  // over NT*DIN/2
    int dp  = idx & (DIN / 2 - 1);                    // half2 channel pair
    int d   = dp * 2;
    int row = idx >> 9;
    int l   = row & (LL - 1);

    float ax = cb[d], ay = cb[d + 1];
    #pragma unroll
    for (int j = 0; j < DCONV; j++) {
        int ls = l - (DCONV - 1) + j;
        if (ls >= 0) {
            float2 v = __half22float2(xz2[(long)(row - (DCONV - 1 - j)) * DIN + dp]);
            ax = fmaf(cw[d * DCONV + j],       v.x, ax);
            ay = fmaf(cw[(d + 1) * DCONV + j], v.y, ay);
        }
    }
    float ux = __fdividef(ax, 1.f + __expf(-ax));
    float uy = __fdividef(ay, 1.f + __expf(-ay));
    float2 zf = __half22float2(xz2[(long)row * DIN + DIN / 2 + dp]);
    float gx = __fdividef(zf.x, 1.f + __expf(-zf.x));
    float gy = __fdividef(zf.y, 1.f + __expf(-zf.y));

    xch2[idx] = __halves2half2(__float2half_rn(ux), __float2half_rn(uy));
    // two consecutive uz entries, one 8B store
    __half2 a = __halves2half2(__float2half_rn(ux), __float2half_rn(gx));
    __half2 b = __halves2half2(__float2half_rn(uy), __float2half_rn(gy));
    uint2 pk = make_uint2(*(uint32_t*)&a, *(uint32_t*)&b);
    *(uint2*)&uz[(long)row * DIN + d] = pk;
}

// ---------------- selective scan: 128-thr blocks, 64-step stages, 1 barrier ---
// Block: 128 thr = 4 warps; warp = 2 d x 16 s; block covers 8 d-channels.
// Grid (DIN/8=128, NB) = 512 blocks -> 3-4 blocks/SM, balanced.
#define SD 8
#define ST 64

__global__ void __launch_bounds__(128) scan_kernel(
    const __half* __restrict__ dtg, const __half2* __restrict__ bcg,
    const __half2* __restrict__ uzg,
    const float* __restrict__ A_log, const float* __restrict__ Dp,
    __half* __restrict__ yh)
{
    __shared__ __align__(16) __half  s_dt[3][ST][SD];
    __shared__ __align__(16) __half2 s_uz[3][ST][SD];
    __shared__ __align__(16) __half2 s_bc[3][ST][DS];
    __shared__ __align__(16) __half  s_y[2][ST][SD];

    const int tid  = threadIdx.x;
    const int warp = tid >> 5, lane = tid & 31;
    const int s    = lane & 15, dh = lane >> 4;
    const int dl   = warp * 2 + dh;
    const int d0   = blockIdx.x * SD;
    const int d    = d0 + dl;
    const long rbase = (long)blockIdx.y * LL;

    const float Aa = -expf(A_log[d * DS + s]);
    const float Dd = Dp[d];

    auto stage_load = [&](int st, int buf) {
        const long row0 = rbase + (long)st * ST;
        for (int j = tid; j < 448; j += 128) {
            if (j < 64) {                              // dt: 64 rows x 16B
                int r = j;
                cpa16(smem_u32(&s_dt[buf][r][0]), dtg + (row0 + r) * DIN + d0);
            } else if (j < 192) {                      // uz: 64 rows x 2 x 16B
                int u = j - 64; int r = u >> 1, q = u & 1;
                cpa16(smem_u32(&s_uz[buf][r][q * 4]),
                      uzg + (row0 + r) * DIN + d0 + q * 4);
            } else {                                   // bc: 64 rows x 4 x 16B
                int v = j - 192; int r = v >> 2, q = v & 3;
                cpa16(smem_u32(&s_bc[buf][r][q * 4]),
                      bcg + (row0 + r) * DS + q * 4);
            }
        }
    };
    auto flush_y = [&](int st, int yb) {
        const long row0 = rbase + (long)st * ST;
        #pragma unroll
        for (int j0 = 0; j0 < 256; j0 += 128) {
            int j = tid + j0;
            int r = j >> 2, w = j & 3;                 // 64 rows x 4 u32
            uint32_t val = ((const uint32_t*)&s_y[yb][r][0])[w];
            *(uint32_t*)(yh + (row0 + r) * DIN + d0 + w * 2) = val;
        }
    };

    stage_load(0, 0); CP_COMMIT;
    stage_load(1, 1); CP_COMMIT;

    float h = 0.f;
    const int NST = LL / ST;   // 32
    for (int ts = 0; ts < NST; ts++) {
        CP_WAIT1;
        __syncthreads();                       // cp.async buf ready + prev s_y done
        if (ts > 0) flush_y(ts - 1, (ts - 1) & 1);
        const int buf = ts % 3;
        if (ts + 2 < NST) stage_load(ts + 2, (ts + 2) % 3);
        CP_COMMIT;

        const int yb = ts & 1;
        #pragma unroll
        for (int t8 = 0; t8 < ST; t8 += 8) {
            float p8[8], g8[8];
            #pragma unroll
            for (int i = 0; i < 8; i++) {
                const int t = t8 + i;
                float  dtv = __half2float(s_dt[buf][t][dl]);
                float2 uzv = __half22float2(s_uz[buf][t][dl]);
                float2 bcv = __half22float2(s_bc[buf][t][s]);
                float dA = __expf(dtv * Aa);
                h = fmaf(dA, h, dtv * bcv.x * uzv.x);
                float p = h * bcv.y;
                if (s == 0) p = fmaf(uzv.x, Dd, p);
                p8[i] = p;
                g8[i] = uzv.y;
            }
            #pragma unroll
            for (int i = 0; i < 8; i++) {
                p8[i] += __shfl_xor_sync(0xffffffffu, p8[i], 8, 16);
                p8[i] += __shfl_xor_sync(0xffffffffu, p8[i], 4, 16);
                p8[i] += __shfl_xor_sync(0xffffffffu, p8[i], 2, 16);
                p8[i] += __shfl_xor_sync(0xffffffffu, p8[i], 1, 16);
            }
            if (s == 0) {
                #pragma unroll
                for (int i = 0; i < 8; i++)
                    s_y[yb][t8 + i][dl] = __float2half_rn(p8[i] * g8[i]);
            }
        }
    }
    __syncthreads();
    flush_y(NST - 1, (NST - 1) & 1);
}

// ---------------- launch -------------------------------------------------------
extern "C" void kernel_launch(void* const* d_in, const int* in_sizes, int n_in,
                              void* d_out, int out_size)
{
    const float* x          = (const float*)d_in[1];
    const int*   order      = (const int*)  d_in[3];
    const int*   inv        = (const int*)  d_in[4];
    const float* W_in       = (const float*)d_in[5];
    const float* bn_in_g    = (const float*)d_in[6];
    const float* bn_in_b    = (const float*)d_in[7];
    const float* bn_in_m    = (const float*)d_in[8];
    const float* bn_in_v    = (const float*)d_in[9];
    const float* in_proj_w  = (const float*)d_in[10];
    const float* conv_w     = (const float*)d_in[11];
    const float* conv_b     = (const float*)d_in[12];
    const float* x_proj_w   = (const float*)d_in[13];
    const float* dt_proj_w  = (const float*)d_in[14];
    const float* dt_proj_b  = (const float*)d_in[15];
    const float* A_log      = (const float*)d_in[16];
    const float* Dp         = (const float*)d_in[17];
    const float* out_proj_w = (const float*)d_in[18];
    const float* W_out      = (const float*)d_in[19];
    const float* bn_o_g     = (const float*)d_in[20];
    const float* bn_o_b     = (const float*)d_in[21];
    const float* bn_o_m     = (const float*)d_in[22];
    const float* bn_o_v     = (const float*)d_in[23];
    float* out = (float*)d_out;

    __half *x16, *hg16, *xz16, *xc16, *db16, *dt16, *y16, *og16;
    __half2 *uz16, *bc16;
    __half *Winh, *iph, *xph, *dtph, *oph, *Woh;
    cudaGetSymbolAddress((void**)&x16,  g_x16);
    cudaGetSymbolAddress((void**)&hg16, g_hg16);
    cudaGetSymbolAddress((void**)&xz16, g_xz16);
    cudaGetSymbolAddress((void**)&xc16, g_xc16);
    cudaGetSymbolAddress((void**)&db16, g_db16);
    cudaGetSymbolAddress((void**)&dt16, g_dt16);
    cudaGetSymbolAddress((void**)&uz16, g_uz16);
    cudaGetSymbolAddress((void**)&bc16, g_bc16);
    cudaGetSymbolAddress((void**)&y16,  g_y16);
    cudaGetSymbolAddress((void**)&og16, g_og16);
    cudaGetSymbolAddress((void**)&Winh, g_Win_h);
    cudaGetSymbolAddress((void**)&iph,  g_ip_h);
    cudaGetSymbolAddress((void**)&xph,  g_xp_h);
    cudaGetSymbolAddress((void**)&dtph, g_dtp_h);
    cudaGetSymbolAddress((void**)&oph,  g_op_h);
    cudaGetSymbolAddress((void**)&Woh,  g_Wo_h);

    const int SMEM_BIG   = 4 * (128 + 128) * 80;   // 81920
    const int SMEM_SMALL = 4 * (64 + 64) * 80;     // 40960
    cudaFuncSetAttribute((const void*)gemm_fp16<128,128,4,2>,
                         cudaFuncAttributeMaxDynamicSharedMemorySize, SMEM_BIG);
    cudaFuncSetAttribute((const void*)gemm_fp16<64,64,2,4>,
                         cudaFuncAttributeMaxDynamicSharedMemorySize, SMEM_SMALL);

    // prep (x + weights) in one launch
    {
        const int total = NT*CC + CC*CC + 2*DIN*CC + 64*DIN + DIN*DTR + CC*DIN + CC*CC;
        prep_all_kernel<<<(total + 255) / 256, 256>>>(
            x, W_in, in_proj_w, x_proj_w, dt_proj_w, out_proj_w, W_out,
            x16, Winh, iph, xph, dtph, oph, Woh);
    }

    // 1) hg = fp16(relu(BN(x @ W_in^T))) scattered by inv  ==  h[order]
    gemm_fp16<128,128,4,2><<<dim3(CC/128, NT/128), 256, SMEM_BIG>>>(
        x16, CC, Winh, CC, nullptr, hg16, inv, CC, 1,
        bn_in_g, bn_in_b, bn_in_m, bn_in_v, nullptr);

    // 2) xz = hg @ in_proj_w^T   (fp16)
    gemm_fp16<128,128,4,2><<<dim3(2*DIN/128, NT/128), 256, SMEM_BIG>>>(
        hg16, CC, iph, CC, nullptr, xz16, nullptr, 2*DIN, 0,
        nullptr, nullptr, nullptr, nullptr, nullptr);

    // 3) xc16 + packed {u, gate}   (half2, 2 channels/thread)
    conv_silu_kernel<<<(NT * DIN / 2) / 256, 256>>>(
        (const __half2*)xz16, conv_w, conv_b, (__half2*)xc16, uz16);

    // 4) db16 = fp16(xc @ x_proj_w^T), N=64
    gemm_fp16<64,64,2,4><<<dim3(1, NT/64), 256, SMEM_SMALL>>>(
        xc16, DIN, xph, DIN, nullptr, db16, nullptr, 64, 0,
        nullptr, nullptr, nullptr, nullptr, nullptr);

    // 4b) pack {B,C}
    pack_bc_kernel<<<NT * DS / 256, 256>>>(db16, bc16);

    // 5) dt16 = fp16(softplus(dt_low @ dt_proj_w^T + b)), K=32 (lda=64)
    gemm_fp16<128,128,4,2><<<dim3(DIN/128, NT/128), 256, SMEM_BIG>>>(
        db16, 64, dtph, DTR, nullptr, dt16, nullptr, DIN, 2,
        dt_proj_b, nullptr, nullptr, nullptr, nullptr);

    // 6) selective scan (cp.async staged, balanced grid) -> y (fp16)
    scan_kernel<<<dim3(DIN / SD, NB), 128>>>(dt16, bc16, uz16, A_log, Dp, y16);

    // 7) og = fp16(y @ out_proj_w^T) scattered by order == o1[inv]
    gemm_fp16<128,128,4,2><<<dim3(CC/128, NT/128), 256, SMEM_BIG>>>(
        y16, DIN, oph, DIN, nullptr, og16, order, CC, 0,
        nullptr, nullptr, nullptr, nullptr, nullptr);

    // 8) out = relu(BN(og @ W_out^T) + x)
    gemm_fp16<128,128,4,2><<<dim3(CC/128, NT/128), 256, SMEM_BIG>>>(
        og16, CC, Woh, CC, out, nullptr, nullptr, CC, 3,
        bn_o_g, bn_o_b, bn_o_m, bn_o_v, x);
}

// round 10
// speedup vs baseline: 10.6842x; 1.1078x over previous
#include <cuda_runtime.h>
#include <cuda_fp16.h>
#include <math.h>
#include <stdint.h>

// Problem constants
#define NB 4
#define LL 2048
#define CC 512
#define DIN 1024
#define DS 16
#define DCONV 4
#define DTR 32
#define NT (NB * LL)   // 8192 rows
#define EPSBN 1e-5f

// ---------------- scratch (device globals; no allocation allowed) -------------
__device__ __align__(256) __half  g_x16 [NT * CC];
__device__ __align__(256) __half  g_hg16[NT * CC];
__device__ __align__(256) __half  g_xz16[NT * 2 * DIN];
__device__ __align__(256) __half  g_xc16[NT * DIN];
__device__ __align__(256) __half  g_db16[NT * 64];
__device__ __align__(256) __half  g_dt16[NT * DIN];
__device__ __align__(256) __half2 g_uz16[NT * DIN];   // {silu(u), silu(z)}
__device__ __align__(256) __half2 g_bc16[NT * DS];    // {B_s, C_s}
__device__ __align__(256) __half  g_y16 [NT * DIN];
__device__ __align__(256) __half  g_og16[NT * CC];
// fp16 weights
__device__ __align__(256) __half g_Win_h[CC * CC];
__device__ __align__(256) __half g_ip_h [2 * DIN * CC];
__device__ __align__(256) __half g_xp_h [64 * DIN];
__device__ __align__(256) __half g_dtp_h[DIN * DTR];
__device__ __align__(256) __half g_op_h [CC * DIN];
__device__ __align__(256) __half g_Wo_h [CC * CC];

// ============================ PTX helpers =====================================
__device__ __forceinline__ uint32_t smem_u32(const void* p) {
    uint32_t a;
    asm("{ .reg .u64 t; cvta.to.shared.u64 t, %1; cvt.u32.u64 %0, t; }"
        : "=r"(a) : "l"(p));
    return a;
}
__device__ __forceinline__ void cpa16(uint32_t d, const void* s) {
    asm volatile("cp.async.cg.shared.global [%0], [%1], 16;" :: "r"(d), "l"(s));
}
#define CP_COMMIT asm volatile("cp.async.commit_group;" ::: "memory")
#define CP_WAIT1  asm volatile("cp.async.wait_group 1;"  ::: "memory")
#define CP_WAIT2  asm volatile("cp.async.wait_group 2;"  ::: "memory")

__device__ __forceinline__ void ldsm4(uint32_t* r, uint32_t a) {
    asm volatile("ldmatrix.sync.aligned.m8n8.x4.shared.b16 {%0,%1,%2,%3}, [%4];"
        : "=r"(r[0]), "=r"(r[1]), "=r"(r[2]), "=r"(r[3]) : "r"(a));
}
__device__ __forceinline__ void mma16816(float* c, const uint32_t* a, const uint32_t* b) {
    asm volatile(
        "mma.sync.aligned.m16n8k16.row.col.f32.f16.f16.f32 "
        "{%0,%1,%2,%3}, {%4,%5,%6,%7}, {%8,%9}, {%0,%1,%2,%3};"
        : "+f"(c[0]), "+f"(c[1]), "+f"(c[2]), "+f"(c[3])
        : "r"(a[0]), "r"(a[1]), "r"(a[2]), "r"(a[3]), "r"(b[0]), "r"(b[1]));
}

// ====================== single-term fp16 HMMA GEMM ============================
// (unchanged — known good)
template <int MT, int NTILE>
__device__ __forceinline__ void load_stage(
    uint32_t base, int tid, int m0, int n0, int lda, int K, int c,
    const __half* A, const __half* W)
{
    const int k0 = c * 32;
    #pragma unroll
    for (int e = 0; e < MT * 4 / 256; e++) {
        int t = tid + e * 256;
        int r = t >> 2, g = t & 3;
        cpa16(base + r * 80 + g * 16, A + (size_t)(m0 + r) * lda + k0 + g * 8);
    }
    uint32_t dw = base + (uint32_t)MT * 80;
    #pragma unroll
    for (int e = 0; e < NTILE * 4 / 256; e++) {
        int t = tid + e * 256;
        int r = t >> 2, g = t & 3;
        cpa16(dw + r * 80 + g * 16, W + (size_t)(n0 + r) * K + k0 + g * 8);
    }
}

template <int MT, int NTILE, int WMW, int WNW>
__global__ void __launch_bounds__(256, 2) gemm_fp16(
    const __half* __restrict__ A, int lda,
    const __half* __restrict__ W, int K,
    float* __restrict__ outF, __half* __restrict__ outH,
    const int* __restrict__ scat, int Ntot, int epi,
    const float* __restrict__ p0, const float* __restrict__ p1,
    const float* __restrict__ p2, const float* __restrict__ p3,
    const float* __restrict__ addsrc)
{
    constexpr int WTM = MT / WMW;
    constexpr int WTN = NTILE / WNW;
    constexpr int MTFR = WTM / 16;
    constexpr int NT8 = WTN / 8;
    constexpr int STAGE = (MT + NTILE) * 80;

    extern __shared__ __align__(128) char smraw[];
    const uint32_t sb = smem_u32(smraw);

    const int tid = threadIdx.x;
    const int lane = tid & 31, warp = tid >> 5;
    const int wm = warp % WMW, wn = warp / WMW;
    const int m0 = blockIdx.y * MT;
    const int n0 = blockIdx.x * NTILE;

    float acc[MTFR][NT8][4] = {};

    const int nch = K >> 5;
    #pragma unroll
    for (int s = 0; s < 3; s++) {
        if (s < nch)
            load_stage<MT, NTILE>(sb + s * STAGE, tid, m0, n0, lda, K, s, A, W);
        CP_COMMIT;
    }

    const int lr = lane & 15;
    const int lc = (lane >> 4) << 3;

    for (int c = 0; c < nch; c++) {
        CP_WAIT2;
        __syncthreads();
        {
            int cn = c + 3;
            if (cn < nch)
                load_stage<MT, NTILE>(sb + (cn & 3) * STAGE, tid, m0, n0, lda, K, cn, A, W);
            CP_COMMIT;
        }
        const uint32_t cur = sb + (uint32_t)(c & 3) * STAGE;
        #pragma unroll
        for (int kk = 0; kk < 32; kk += 16) {
            uint32_t af[MTFR][4];
            #pragma unroll
            for (int mt = 0; mt < MTFR; mt++)
                ldsm4(af[mt], cur + (uint32_t)((wm * WTM + mt * 16 + lr) * 80 + (kk + lc) * 2));
            uint32_t wf[NT8][2];
            #pragma unroll
            for (int p = 0; p < NT8 / 2; p++) {
                uint32_t a = cur + (uint32_t)((MT + wn * WTN + p * 16 + lr) * 80 + (kk + lc) * 2);
                uint32_t r4[4];
                ldsm4(r4, a);
                wf[2*p][0] = r4[0]; wf[2*p][1] = r4[2];
                wf[2*p+1][0] = r4[1]; wf[2*p+1][1] = r4[3];
            }
            #pragma unroll
            for (int mt = 0; mt < MTFR; mt++)
                #pragma unroll
                for (int nt = 0; nt < NT8; nt++)
                    mma16816(acc[mt][nt], af[mt], wf[nt]);
        }
    }

    const int g = lane >> 2, tg = lane & 3;
    #pragma unroll
    for (int mt = 0; mt < MTFR; mt++)
        #pragma unroll
        for (int nt = 0; nt < NT8; nt++)
            #pragma unroll
            for (int rr = 0; rr < 2; rr++) {
                int m = m0 + wm * WTM + mt * 16 + g + rr * 8;
                int n = n0 + wn * WTN + nt * 8 + tg * 2;
                int mo = scat ? scat[m] : m;
                float v0 = acc[mt][nt][rr * 2 + 0];
                float v1 = acc[mt][nt][rr * 2 + 1];
                if (epi == 1) {
                    v0 = fmaxf((v0 - p2[n])   * rsqrtf(p3[n]   + EPSBN) * p0[n]   + p1[n],   0.f);
                    v1 = fmaxf((v1 - p2[n+1]) * rsqrtf(p3[n+1] + EPSBN) * p0[n+1] + p1[n+1], 0.f);
                } else if (epi == 2) {
                    v0 += p0[n];   v0 = (v0 > 20.f) ? v0 : __logf(1.f + __expf(v0));
                    v1 += p0[n+1]; v1 = (v1 > 20.f) ? v1 : __logf(1.f + __expf(v1));
                } else if (epi == 3) {
                    v0 = (v0 - p2[n])   * rsqrtf(p3[n]   + EPSBN) * p0[n]   + p1[n];
                    v1 = (v1 - p2[n+1]) * rsqrtf(p3[n+1] + EPSBN) * p0[n+1] + p1[n+1];
                    v0 = fmaxf(v0 + addsrc[(size_t)mo * Ntot + n], 0.f);
                    v1 = fmaxf(v1 + addsrc[(size_t)mo * Ntot + n + 1], 0.f);
                }
                const size_t ob = (size_t)mo * Ntot + n;
                if (outF) *(float2*)&outF[ob] = make_float2(v0, v1);
                if (outH)
                    *(__half2*)&outH[ob] =
                        __halves2half2(__float2half_rn(v0), __float2half_rn(v1));
            }
}

// ====================== prep (x + all weights -> fp16), one launch ============
__global__ void __launch_bounds__(256) prep_all_kernel(
    const float* __restrict__ x,
    const float* __restrict__ Win, const float* __restrict__ ip,
    const float* __restrict__ xp,  const float* __restrict__ dtp,
    const float* __restrict__ op,  const float* __restrict__ Wo,
    __half* __restrict__ dx,
    __half* __restrict__ dWin, __half* __restrict__ dip,
    __half* __restrict__ dxp,  __half* __restrict__ ddtp,
    __half* __restrict__ dop,  __half* __restrict__ dWo)
{
    const int sx = NT * CC, s0 = CC * CC, s1 = 2 * DIN * CC, s2 = 64 * DIN,
              s3 = DIN * DTR, s4 = CC * DIN;
    int i = blockIdx.x * blockDim.x + threadIdx.x;
    if (i < sx) { dx[i]   = __float2half_rn(x[i]);   return; } i -= sx;
    if (i < s0) { dWin[i] = __float2half_rn(Win[i]); return; } i -= s0;
    if (i < s1) { dip[i]  = __float2half_rn(ip[i]);  return; } i -= s1;
    if (i < s2) { dxp[i]  = __float2half_rn(xp[i]);  return; } i -= s2;
    if (i < s3) { ddtp[i] = __float2half_rn(dtp[i]); return; } i -= s3;
    if (i < s4) { dop[i]  = __float2half_rn(op[i]);  return; } i -= s4;
    dWo[i] = __float2half_rn(Wo[i]);
}

// BC pack: db16[row][32+s], db16[row][48+s] -> bc16[row][s] = {B, C}
__global__ void __launch_bounds__(256) pack_bc_kernel(
    const __half* __restrict__ db16, __half2* __restrict__ bc16)
{
    int i = blockIdx.x * blockDim.x + threadIdx.x;   // over NT*DS
    int s = i & (DS - 1), row = i >> 4;
    bc16[i] = __halves2half2(db16[row * 64 + DTR + s], db16[row * 64 + DTR + DS + s]);
}

// ---------- depthwise causal conv: register-blocked 8 rows x 2 channels -------
__global__ void __launch_bounds__(256) conv_silu_kernel(
    const __half2* __restrict__ xz2,   // rows of DIN half2 (= 2*DIN halves)
    const float* __restrict__ cw, const float* __restrict__ cb,
    __half2* __restrict__ xch2, __half2* __restrict__ uz)
{
    int g   = blockIdx.x * blockDim.x + threadIdx.x;  // over (NT/8)*(DIN/2)
    int dp  = g & (DIN / 2 - 1);
    int rg  = g >> 9;
    int row0 = rg * 8;
    int l0   = row0 & (LL - 1);
    int d    = dp * 2;

    const float bx  = cb[d],     by  = cb[d + 1];
    const float c0x = cw[d*4+0], c1x = cw[d*4+1], c2x = cw[d*4+2], c3x = cw[d*4+3];
    const float c0y = cw[d*4+4], c1y = cw[d*4+5], c2y = cw[d*4+6], c3y = cw[d*4+7];

    // sliding window: rows row0-3 .. row0+7 of xm
    float2 w[11];
    #pragma unroll
    for (int j = 0; j < 11; j++) {
        int l = l0 - 3 + j;
        w[j] = (l >= 0)
             ? __half22float2(xz2[(long)(row0 - 3 + j) * DIN + dp])
             : make_float2(0.f, 0.f);
    }

    #pragma unroll
    for (int i = 0; i < 8; i++) {
        const long row = row0 + i;
        float ax = bx, ay = by;
        ax = fmaf(c0x, w[i].x,   ax); ay = fmaf(c0y, w[i].y,   ay);
        ax = fmaf(c1x, w[i+1].x, ax); ay = fmaf(c1y, w[i+1].y, ay);
        ax = fmaf(c2x, w[i+2].x, ax); ay = fmaf(c2y, w[i+2].y, ay);
        ax = fmaf(c3x, w[i+3].x, ax); ay = fmaf(c3y, w[i+3].y, ay);

        float ux = __fdividef(ax, 1.f + __expf(-ax));
        float uy = __fdividef(ay, 1.f + __expf(-ay));
        float2 zf = __half22float2(xz2[row * DIN + DIN / 2 + dp]);
        float gx = __fdividef(zf.x, 1.f + __expf(-zf.x));
        float gy = __fdividef(zf.y, 1.f + __expf(-zf.y));

        xch2[row * (DIN / 2) + dp] =
            __halves2half2(__float2half_rn(ux), __float2half_rn(uy));
        __half2 a = __halves2half2(__float2half_rn(ux), __float2half_rn(gx));
        __half2 b = __halves2half2(__float2half_rn(uy), __float2half_rn(gy));
        uint2 pk = make_uint2(*(uint32_t*)&a, *(uint32_t*)&b);
        *(uint2*)&uz[row * DIN + d] = pk;
    }
}

// ---------------- selective scan: 128-thr blocks, 64-step stages --------------
// Block: 128 thr = 4 warps; warp = 2 d x 16 s; block covers 8 d-channels.
// Reduction: fp16x2-packed butterfly (16 SHFL + 16 HADD2 per 8 steps).
#define SD 8
#define ST 64

__global__ void __launch_bounds__(128) scan_kernel(
    const __half* __restrict__ dtg, const __half2* __restrict__ bcg,
    const __half2* __restrict__ uzg,
    const float* __restrict__ A_log, const float* __restrict__ Dp,
    __half* __restrict__ yh)
{
    __shared__ __align__(16) __half  s_dt[3][ST][SD];
    __shared__ __align__(16) __half2 s_uz[3][ST][SD];
    __shared__ __align__(16) __half2 s_bc[3][ST][DS];
    __shared__ __align__(16) __half  s_y[2][ST][SD];

    const int tid  = threadIdx.x;
    const int warp = tid >> 5, lane = tid & 31;
    const int s    = lane & 15, dh = lane >> 4;
    const int dl   = warp * 2 + dh;
    const int d0   = blockIdx.x * SD;
    const int d    = d0 + dl;
    const long rbase = (long)blockIdx.y * LL;

    const float Aa = -expf(A_log[d * DS + s]);
    const float Dd = Dp[d];

    auto stage_load = [&](int st, int buf) {
        const long row0 = rbase + (long)st * ST;
        for (int j = tid; j < 448; j += 128) {
            if (j < 64) {
                int r = j;
                cpa16(smem_u32(&s_dt[buf][r][0]), dtg + (row0 + r) * DIN + d0);
            } else if (j < 192) {
                int u = j - 64; int r = u >> 1, q = u & 1;
                cpa16(smem_u32(&s_uz[buf][r][q * 4]),
                      uzg + (row0 + r) * DIN + d0 + q * 4);
            } else {
                int v = j - 192; int r = v >> 2, q = v & 3;
                cpa16(smem_u32(&s_bc[buf][r][q * 4]),
                      bcg + (row0 + r) * DS + q * 4);
            }
        }
    };
    auto flush_y = [&](int st, int yb) {
        const long row0 = rbase + (long)st * ST;
        #pragma unroll
        for (int j0 = 0; j0 < 256; j0 += 128) {
            int j = tid + j0;
            int r = j >> 2, w = j & 3;
            uint32_t val = ((const uint32_t*)&s_y[yb][r][0])[w];
            *(uint32_t*)(yh + (row0 + r) * DIN + d0 + w * 2) = val;
        }
    };

    stage_load(0, 0); CP_COMMIT;
    stage_load(1, 1); CP_COMMIT;

    float h = 0.f;
    const int NST = LL / ST;   // 32
    for (int ts = 0; ts < NST; ts++) {
        CP_WAIT1;
        __syncthreads();
        if (ts > 0) flush_y(ts - 1, (ts - 1) & 1);
        const int buf = ts % 3;
        if (ts + 2 < NST) stage_load(ts + 2, (ts + 2) % 3);
        CP_COMMIT;

        const int yb = ts & 1;
        #pragma unroll
        for (int t8 = 0; t8 < ST; t8 += 8) {
            float p8[8], g8[8];
            #pragma unroll
            for (int i = 0; i < 8; i++) {
                const int t = t8 + i;
                float  dtv = __half2float(s_dt[buf][t][dl]);
                float2 uzv = __half22float2(s_uz[buf][t][dl]);
                float2 bcv = __half22float2(s_bc[buf][t][s]);
                float dA = __expf(dtv * Aa);
                h = fmaf(dA, h, dtv * bcv.x * uzv.x);
                float p = h * bcv.y;
                if (s == 0) p = fmaf(uzv.x, Dd, p);
                p8[i] = p;
                g8[i] = uzv.y;
            }
            // fp16x2-packed butterfly reduction over 16 lanes (s)
            #pragma unroll
            for (int i = 0; i < 8; i += 2) {
                __half2 pp = __halves2half2(__float2half_rn(p8[i]),
                                            __float2half_rn(p8[i+1]));
                uint32_t u = *(uint32_t*)&pp;
                #pragma unroll
                for (int k = 8; k >= 1; k >>= 1) {
                    uint32_t v = __shfl_xor_sync(0xffffffffu, u, k, 16);
                    __half2 va = *(__half2*)&u, vb = *(__half2*)&v;
                    va = __hadd2(va, vb);
                    u = *(uint32_t*)&va;
                }
                if (s == 0) {
                    __half2 r = *(__half2*)&u;
                    s_y[yb][t8 + i][dl] =
                        __hmul(__low2half(r),  __float2half_rn(g8[i]));
                    s_y[yb][t8 + i + 1][dl] =
                        __hmul(__high2half(r), __float2half_rn(g8[i+1]));
                }
            }
        }
    }
    __syncthreads();
    flush_y(NST - 1, (NST - 1) & 1);
}

// ---------------- launch -------------------------------------------------------
extern "C" void kernel_launch(void* const* d_in, const int* in_sizes, int n_in,
                              void* d_out, int out_size)
{
    const float* x          = (const float*)d_in[1];
    const int*   order      = (const int*)  d_in[3];
    const int*   inv        = (const int*)  d_in[4];
    const float* W_in       = (const float*)d_in[5];
    const float* bn_in_g    = (const float*)d_in[6];
    const float* bn_in_b    = (const float*)d_in[7];
    const float* bn_in_m    = (const float*)d_in[8];
    const float* bn_in_v    = (const float*)d_in[9];
    const float* in_proj_w  = (const float*)d_in[10];
    const float* conv_w     = (const float*)d_in[11];
    const float* conv_b     = (const float*)d_in[12];
    const float* x_proj_w   = (const float*)d_in[13];
    const float* dt_proj_w  = (const float*)d_in[14];
    const float* dt_proj_b  = (const float*)d_in[15];
    const float* A_log      = (const float*)d_in[16];
    const float* Dp         = (const float*)d_in[17];
    const float* out_proj_w = (const float*)d_in[18];
    const float* W_out      = (const float*)d_in[19];
    const float* bn_o_g     = (const float*)d_in[20];
    const float* bn_o_b     = (const float*)d_in[21];
    const float* bn_o_m     = (const float*)d_in[22];
    const float* bn_o_v     = (const float*)d_in[23];
    float* out = (float*)d_out;

    __half *x16, *hg16, *xz16, *xc16, *db16, *dt16, *y16, *og16;
    __half2 *uz16, *bc16;
    __half *Winh, *iph, *xph, *dtph, *oph, *Woh;
    cudaGetSymbolAddress((void**)&x16,  g_x16);
    cudaGetSymbolAddress((void**)&hg16, g_hg16);
    cudaGetSymbolAddress((void**)&xz16, g_xz16);
    cudaGetSymbolAddress((void**)&xc16, g_xc16);
    cudaGetSymbolAddress((void**)&db16, g_db16);
    cudaGetSymbolAddress((void**)&dt16, g_dt16);
    cudaGetSymbolAddress((void**)&uz16, g_uz16);
    cudaGetSymbolAddress((void**)&bc16, g_bc16);
    cudaGetSymbolAddress((void**)&y16,  g_y16);
    cudaGetSymbolAddress((void**)&og16, g_og16);
    cudaGetSymbolAddress((void**)&Winh, g_Win_h);
    cudaGetSymbolAddress((void**)&iph,  g_ip_h);
    cudaGetSymbolAddress((void**)&xph,  g_xp_h);
    cudaGetSymbolAddress((void**)&dtph, g_dtp_h);
    cudaGetSymbolAddress((void**)&oph,  g_op_h);
    cudaGetSymbolAddress((void**)&Woh,  g_Wo_h);

    const int SMEM_BIG   = 4 * (128 + 128) * 80;   // 81920
    const int SMEM_SMALL = 4 * (64 + 64) * 80;     // 40960
    cudaFuncSetAttribute((const void*)gemm_fp16<128,128,4,2>,
                         cudaFuncAttributeMaxDynamicSharedMemorySize, SMEM_BIG);
    cudaFuncSetAttribute((const void*)gemm_fp16<64,64,2,4>,
                         cudaFuncAttributeMaxDynamicSharedMemorySize, SMEM_SMALL);

    // prep (x + weights) in one launch
    {
        const int total = NT*CC + CC*CC + 2*DIN*CC + 64*DIN + DIN*DTR + CC*DIN + CC*CC;
        prep_all_kernel<<<(total + 255) / 256, 256>>>(
            x, W_in, in_proj_w, x_proj_w, dt_proj_w, out_proj_w, W_out,
            x16, Winh, iph, xph, dtph, oph, Woh);
    }

    // 1) hg = fp16(relu(BN(x @ W_in^T))) scattered by inv  ==  h[order]
    gemm_fp16<128,128,4,2><<<dim3(CC/128, NT/128), 256, SMEM_BIG>>>(
        x16, CC, Winh, CC, nullptr, hg16, inv, CC, 1,
        bn_in_g, bn_in_b, bn_in_m, bn_in_v, nullptr);

    // 2) xz = hg @ in_proj_w^T   (fp16)
    gemm_fp16<128,128,4,2><<<dim3(2*DIN/128, NT/128), 256, SMEM_BIG>>>(
        hg16, CC, iph, CC, nullptr, xz16, nullptr, 2*DIN, 0,
        nullptr, nullptr, nullptr, nullptr, nullptr);

    // 3) xc16 + packed {u, gate}  (register-blocked, 8 rows x 2 ch / thread)
    conv_silu_kernel<<<(NT / 8) * (DIN / 2) / 256, 256>>>(
        (const __half2*)xz16, conv_w, conv_b, (__half2*)xc16, uz16);

    // 4) db16 = fp16(xc @ x_proj_w^T), N=64
    gemm_fp16<64,64,2,4><<<dim3(1, NT/64), 256, SMEM_SMALL>>>(
        xc16, DIN, xph, DIN, nullptr, db16, nullptr, 64, 0,
        nullptr, nullptr, nullptr, nullptr, nullptr);

    // 4b) pack {B,C}
    pack_bc_kernel<<<NT * DS / 256, 256>>>(db16, bc16);

    // 5) dt16 = fp16(softplus(dt_low @ dt_proj_w^T + b)), K=32 (lda=64)
    gemm_fp16<128,128,4,2><<<dim3(DIN/128, NT/128), 256, SMEM_BIG>>>(
        db16, 64, dtph, DTR, nullptr, dt16, nullptr, DIN, 2,
        dt_proj_b, nullptr, nullptr, nullptr, nullptr);

    // 6) selective scan (cp.async staged, balanced grid) -> y (fp16)
    scan_kernel<<<dim3(DIN / SD, NB), 128>>>(dt16, bc16, uz16, A_log, Dp, y16);

    // 7) og = fp16(y @ out_proj_w^T) scattered by order == o1[inv]
    gemm_fp16<128,128,4,2><<<dim3(CC/128, NT/128), 256, SMEM_BIG>>>(
        y16, DIN, oph, DIN, nullptr, og16, order, CC, 0,
        nullptr, nullptr, nullptr, nullptr, nullptr);

    // 8) out = relu(BN(og @ W_out^T) + x)
    gemm_fp16<128,128,4,2><<<dim3(CC/128, NT/128), 256, SMEM_BIG>>>(
        og16, CC, Woh, CC, out, nullptr, nullptr, CC, 3,
        bn_o_g, bn_o_b, bn_o_m, bn_o_v, x);
}

// round 11
// speedup vs baseline: 10.7942x; 1.0103x over previous
#include <cuda_runtime.h>
#include <cuda_fp16.h>
#include <math.h>
#include <stdint.h>

// Problem constants
#define NB 4
#define LL 2048
#define CC 512
#define DIN 1024
#define DS 16
#define DCONV 4
#define DTR 32
#define NT (NB * LL)   // 8192 rows
#define EPSBN 1e-5f

// ---------------- scratch (device globals; no allocation allowed) -------------
__device__ __align__(256) __half  g_x16 [NT * CC];
__device__ __align__(256) __half  g_hg16[NT * CC];
__device__ __align__(256) __half  g_xz16[NT * 2 * DIN];
__device__ __align__(256) __half  g_xc16[NT * DIN];
__device__ __align__(256) __half  g_db16[NT * 64];
__device__ __align__(256) __half  g_dt16[NT * DIN];
__device__ __align__(256) __half2 g_uz16[NT * DIN];   // {silu(u), silu(z)}
__device__ __align__(256) __half2 g_bc16[NT * DS];    // {B_s, C_s}
__device__ __align__(256) __half  g_y16 [NT * DIN];
__device__ __align__(256) __half  g_og16[NT * CC];
// fp16 weights
__device__ __align__(256) __half g_Win_h[CC * CC];
__device__ __align__(256) __half g_ip_h [2 * DIN * CC];
__device__ __align__(256) __half g_xp_h [64 * DIN];
__device__ __align__(256) __half g_dtp_h[DIN * DTR];
__device__ __align__(256) __half g_op_h [CC * DIN];
__device__ __align__(256) __half g_Wo_h [CC * CC];

// ============================ PTX helpers =====================================
__device__ __forceinline__ uint32_t smem_u32(const void* p) {
    uint32_t a;
    asm("{ .reg .u64 t; cvta.to.shared.u64 t, %1; cvt.u32.u64 %0, t; }"
        : "=r"(a) : "l"(p));
    return a;
}
__device__ __forceinline__ void cpa16(uint32_t d, const void* s) {
    asm volatile("cp.async.cg.shared.global [%0], [%1], 16;" :: "r"(d), "l"(s));
}
#define CP_COMMIT asm volatile("cp.async.commit_group;" ::: "memory")
#define CP_WAIT1  asm volatile("cp.async.wait_group 1;"  ::: "memory")
#define CP_WAIT2  asm volatile("cp.async.wait_group 2;"  ::: "memory")

__device__ __forceinline__ void ldsm4(uint32_t* r, uint32_t a) {
    asm volatile("ldmatrix.sync.aligned.m8n8.x4.shared.b16 {%0,%1,%2,%3}, [%4];"
        : "=r"(r[0]), "=r"(r[1]), "=r"(r[2]), "=r"(r[3]) : "r"(a));
}
__device__ __forceinline__ void mma16816(float* c, const uint32_t* a, const uint32_t* b) {
    asm volatile(
        "mma.sync.aligned.m16n8k16.row.col.f32.f16.f16.f32 "
        "{%0,%1,%2,%3}, {%4,%5,%6,%7}, {%8,%9}, {%0,%1,%2,%3};"
        : "+f"(c[0]), "+f"(c[1]), "+f"(c[2]), "+f"(c[3])
        : "r"(a[0]), "r"(a[1]), "r"(a[2]), "r"(a[3]), "r"(b[0]), "r"(b[1]));
}

// ====================== single-term fp16 HMMA GEMM ============================
// (unchanged — known good)
template <int MT, int NTILE>
__device__ __forceinline__ void load_stage(
    uint32_t base, int tid, int m0, int n0, int lda, int K, int c,
    const __half* A, const __half* W)
{
    const int k0 = c * 32;
    #pragma unroll
    for (int e = 0; e < MT * 4 / 256; e++) {
        int t = tid + e * 256;
        int r = t >> 2, g = t & 3;
        cpa16(base + r * 80 + g * 16, A + (size_t)(m0 + r) * lda + k0 + g * 8);
    }
    uint32_t dw = base + (uint32_t)MT * 80;
    #pragma unroll
    for (int e = 0; e < NTILE * 4 / 256; e++) {
        int t = tid + e * 256;
        int r = t >> 2, g = t & 3;
        cpa16(dw + r * 80 + g * 16, W + (size_t)(n0 + r) * K + k0 + g * 8);
    }
}

template <int MT, int NTILE, int WMW, int WNW>
__global__ void __launch_bounds__(256, 2) gemm_fp16(
    const __half* __restrict__ A, int lda,
    const __half* __restrict__ W, int K,
    float* __restrict__ outF, __half* __restrict__ outH,
    const int* __restrict__ scat, int Ntot, int epi,
    const float* __restrict__ p0, const float* __restrict__ p1,
    const float* __restrict__ p2, const float* __restrict__ p3,
    const float* __restrict__ addsrc)
{
    constexpr int WTM = MT / WMW;
    constexpr int WTN = NTILE / WNW;
    constexpr int MTFR = WTM / 16;
    constexpr int NT8 = WTN / 8;
    constexpr int STAGE = (MT + NTILE) * 80;

    extern __shared__ __align__(128) char smraw[];
    const uint32_t sb = smem_u32(smraw);

    const int tid = threadIdx.x;
    const int lane = tid & 31, warp = tid >> 5;
    const int wm = warp % WMW, wn = warp / WMW;
    const int m0 = blockIdx.y * MT;
    const int n0 = blockIdx.x * NTILE;

    float acc[MTFR][NT8][4] = {};

    const int nch = K >> 5;
    #pragma unroll
    for (int s = 0; s < 3; s++) {
        if (s < nch)
            load_stage<MT, NTILE>(sb + s * STAGE, tid, m0, n0, lda, K, s, A, W);
        CP_COMMIT;
    }

    const int lr = lane & 15;
    const int lc = (lane >> 4) << 3;

    for (int c = 0; c < nch; c++) {
        CP_WAIT2;
        __syncthreads();
        {
            int cn = c + 3;
            if (cn < nch)
                load_stage<MT, NTILE>(sb + (cn & 3) * STAGE, tid, m0, n0, lda, K, cn, A, W);
            CP_COMMIT;
        }
        const uint32_t cur = sb + (uint32_t)(c & 3) * STAGE;
        #pragma unroll
        for (int kk = 0; kk < 32; kk += 16) {
            uint32_t af[MTFR][4];
            #pragma unroll
            for (int mt = 0; mt < MTFR; mt++)
                ldsm4(af[mt], cur + (uint32_t)((wm * WTM + mt * 16 + lr) * 80 + (kk + lc) * 2));
            uint32_t wf[NT8][2];
            #pragma unroll
            for (int p = 0; p < NT8 / 2; p++) {
                uint32_t a = cur + (uint32_t)((MT + wn * WTN + p * 16 + lr) * 80 + (kk + lc) * 2);
                uint32_t r4[4];
                ldsm4(r4, a);
                wf[2*p][0] = r4[0]; wf[2*p][1] = r4[2];
                wf[2*p+1][0] = r4[1]; wf[2*p+1][1] = r4[3];
            }
            #pragma unroll
            for (int mt = 0; mt < MTFR; mt++)
                #pragma unroll
                for (int nt = 0; nt < NT8; nt++)
                    mma16816(acc[mt][nt], af[mt], wf[nt]);
        }
    }

    const int g = lane >> 2, tg = lane & 3;
    #pragma unroll
    for (int mt = 0; mt < MTFR; mt++)
        #pragma unroll
        for (int nt = 0; nt < NT8; nt++)
            #pragma unroll
            for (int rr = 0; rr < 2; rr++) {
                int m = m0 + wm * WTM + mt * 16 + g + rr * 8;
                int n = n0 + wn * WTN + nt * 8 + tg * 2;
                int mo = scat ? scat[m] : m;
                float v0 = acc[mt][nt][rr * 2 + 0];
                float v1 = acc[mt][nt][rr * 2 + 1];
                if (epi == 1) {
                    v0 = fmaxf((v0 - p2[n])   * rsqrtf(p3[n]   + EPSBN) * p0[n]   + p1[n],   0.f);
                    v1 = fmaxf((v1 - p2[n+1]) * rsqrtf(p3[n+1] + EPSBN) * p0[n+1] + p1[n+1], 0.f);
                } else if (epi == 2) {
                    v0 += p0[n];   v0 = (v0 > 20.f) ? v0 : __logf(1.f + __expf(v0));
                    v1 += p0[n+1]; v1 = (v1 > 20.f) ? v1 : __logf(1.f + __expf(v1));
                } else if (epi == 3) {
                    v0 = (v0 - p2[n])   * rsqrtf(p3[n]   + EPSBN) * p0[n]   + p1[n];
                    v1 = (v1 - p2[n+1]) * rsqrtf(p3[n+1] + EPSBN) * p0[n+1] + p1[n+1];
                    v0 = fmaxf(v0 + addsrc[(size_t)mo * Ntot + n], 0.f);
                    v1 = fmaxf(v1 + addsrc[(size_t)mo * Ntot + n + 1], 0.f);
                }
                const size_t ob = (size_t)mo * Ntot + n;
                if (outF) *(float2*)&outF[ob] = make_float2(v0, v1);
                if (outH)
                    *(__half2*)&outH[ob] =
                        __halves2half2(__float2half_rn(v0), __float2half_rn(v1));
            }
}

// ====================== prep (x + all weights -> fp16), one launch ============
__global__ void __launch_bounds__(256) prep_all_kernel(
    const float* __restrict__ x,
    const float* __restrict__ Win, const float* __restrict__ ip,
    const float* __restrict__ xp,  const float* __restrict__ dtp,
    const float* __restrict__ op,  const float* __restrict__ Wo,
    __half* __restrict__ dx,
    __half* __restrict__ dWin, __half* __restrict__ dip,
    __half* __restrict__ dxp,  __half* __restrict__ ddtp,
    __half* __restrict__ dop,  __half* __restrict__ dWo)
{
    const int sx = NT * CC, s0 = CC * CC, s1 = 2 * DIN * CC, s2 = 64 * DIN,
              s3 = DIN * DTR, s4 = CC * DIN;
    int i = blockIdx.x * blockDim.x + threadIdx.x;
    if (i < sx) { dx[i]   = __float2half_rn(x[i]);   return; } i -= sx;
    if (i < s0) { dWin[i] = __float2half_rn(Win[i]); return; } i -= s0;
    if (i < s1) { dip[i]  = __float2half_rn(ip[i]);  return; } i -= s1;
    if (i < s2) { dxp[i]  = __float2half_rn(xp[i]);  return; } i -= s2;
    if (i < s3) { ddtp[i] = __float2half_rn(dtp[i]); return; } i -= s3;
    if (i < s4) { dop[i]  = __float2half_rn(op[i]);  return; } i -= s4;
    dWo[i] = __float2half_rn(Wo[i]);
}

// BC pack: db16[row][32+s], db16[row][48+s] -> bc16[row][s] = {B, C}
__global__ void __launch_bounds__(256) pack_bc_kernel(
    const __half* __restrict__ db16, __half2* __restrict__ bc16)
{
    int i = blockIdx.x * blockDim.x + threadIdx.x;   // over NT*DS
    int s = i & (DS - 1), row = i >> 4;
    bc16[i] = __halves2half2(db16[row * 64 + DTR + s], db16[row * 64 + DTR + DS + s]);
}

// ---------- depthwise causal conv: register-blocked 8 rows x 2 channels -------
__global__ void __launch_bounds__(256) conv_silu_kernel(
    const __half2* __restrict__ xz2,   // rows of DIN half2 (= 2*DIN halves)
    const float* __restrict__ cw, const float* __restrict__ cb,
    __half2* __restrict__ xch2, __half2* __restrict__ uz)
{
    int g   = blockIdx.x * blockDim.x + threadIdx.x;  // over (NT/8)*(DIN/2)
    int dp  = g & (DIN / 2 - 1);
    int rg  = g >> 9;
    int row0 = rg * 8;
    int l0   = row0 & (LL - 1);
    int d    = dp * 2;

    const float bx  = cb[d],     by  = cb[d + 1];
    const float c0x = cw[d*4+0], c1x = cw[d*4+1], c2x = cw[d*4+2], c3x = cw[d*4+3];
    const float c0y = cw[d*4+4], c1y = cw[d*4+5], c2y = cw[d*4+6], c3y = cw[d*4+7];

    // sliding window: rows row0-3 .. row0+7 of xm
    float2 w[11];
    #pragma unroll
    for (int j = 0; j < 11; j++) {
        int l = l0 - 3 + j;
        w[j] = (l >= 0)
             ? __half22float2(xz2[(long)(row0 - 3 + j) * DIN + dp])
             : make_float2(0.f, 0.f);
    }

    #pragma unroll
    for (int i = 0; i < 8; i++) {
        const long row = row0 + i;
        float ax = bx, ay = by;
        ax = fmaf(c0x, w[i].x,   ax); ay = fmaf(c0y, w[i].y,   ay);
        ax = fmaf(c1x, w[i+1].x, ax); ay = fmaf(c1y, w[i+1].y, ay);
        ax = fmaf(c2x, w[i+2].x, ax); ay = fmaf(c2y, w[i+2].y, ay);
        ax = fmaf(c3x, w[i+3].x, ax); ay = fmaf(c3y, w[i+3].y, ay);

        float ux = __fdividef(ax, 1.f + __expf(-ax));
        float uy = __fdividef(ay, 1.f + __expf(-ay));
        float2 zf = __half22float2(xz2[row * DIN + DIN / 2 + dp]);
        float gx = __fdividef(zf.x, 1.f + __expf(-zf.x));
        float gy = __fdividef(zf.y, 1.f + __expf(-zf.y));

        xch2[row * (DIN / 2) + dp] =
            __halves2half2(__float2half_rn(ux), __float2half_rn(uy));
        __half2 a = __halves2half2(__float2half_rn(ux), __float2half_rn(gx));
        __half2 b = __halves2half2(__float2half_rn(uy), __float2half_rn(gy));
        uint2 pk = make_uint2(*(uint32_t*)&a, *(uint32_t*)&b);
        *(uint2*)&uz[row * DIN + d] = pk;
    }
}

// ---------------- selective scan: 16 d / block, 64-step stages ----------------
// Block: 256 thr = 8 warps; warp = 2 d x 16 s; block covers 16 d-channels.
// Grid (DIN/16=64, NB) = 256 blocks. bc cp.async share halves vs SD=8.
#define SD 16
#define ST 64

__global__ void __launch_bounds__(256) scan_kernel(
    const __half* __restrict__ dtg, const __half2* __restrict__ bcg,
    const __half2* __restrict__ uzg,
    const float* __restrict__ A_log, const float* __restrict__ Dp,
    __half* __restrict__ yh)
{
    __shared__ __align__(16) __half  s_dt[3][ST][SD];
    __shared__ __align__(16) __half2 s_uz[3][ST][SD];
    __shared__ __align__(16) __half2 s_bc[3][ST][DS];
    __shared__ __align__(16) __half  s_y[2][ST][SD];

    const int tid  = threadIdx.x;
    const int warp = tid >> 5, lane = tid & 31;
    const int s    = lane & 15, dh = lane >> 4;
    const int dl   = warp * 2 + dh;
    const int d0   = blockIdx.x * SD;
    const int d    = d0 + dl;
    const long rbase = (long)blockIdx.y * LL;

    const float Aa = -expf(A_log[d * DS + s]);
    const float Dd = Dp[d];

    auto stage_load = [&](int st, int buf) {
        const long row0 = rbase + (long)st * ST;
        // dt: 64 rows x 32B (128 ops), uz: 64 x 64B (256), bc: 64 x 64B (256)
        for (int j = tid; j < 640; j += 256) {
            if (j < 128) {
                int r = j >> 1, q = j & 1;
                cpa16(smem_u32(&s_dt[buf][r][q * 8]),
                      dtg + (row0 + r) * DIN + d0 + q * 8);
            } else if (j < 384) {
                int u = j - 128; int r = u >> 2, q = u & 3;
                cpa16(smem_u32(&s_uz[buf][r][q * 4]),
                      uzg + (row0 + r) * DIN + d0 + q * 4);
            } else {
                int v = j - 384; int r = v >> 2, q = v & 3;
                cpa16(smem_u32(&s_bc[buf][r][q * 4]),
                      bcg + (row0 + r) * DS + q * 4);
            }
        }
    };
    auto flush_y = [&](int st, int yb) {
        const long row0 = rbase + (long)st * ST;
        // 64 rows x 32B = 512 u32
        #pragma unroll
        for (int j0 = 0; j0 < 512; j0 += 256) {
            int j = tid + j0;
            int r = j >> 3, w = j & 7;
            uint32_t val = ((const uint32_t*)&s_y[yb][r][0])[w];
            *(uint32_t*)(yh + (row0 + r) * DIN + d0 + w * 2) = val;
        }
    };

    stage_load(0, 0); CP_COMMIT;
    stage_load(1, 1); CP_COMMIT;

    float h = 0.f;
    const int NST = LL / ST;   // 32
    for (int ts = 0; ts < NST; ts++) {
        CP_WAIT1;
        __syncthreads();
        if (ts > 0) flush_y(ts - 1, (ts - 1) & 1);
        const int buf = ts % 3;
        if (ts + 2 < NST) stage_load(ts + 2, (ts + 2) % 3);
        CP_COMMIT;

        const int yb = ts & 1;
        #pragma unroll
        for (int t8 = 0; t8 < ST; t8 += 8) {
            float p8[8], g8[8];
            #pragma unroll
            for (int i = 0; i < 8; i++) {
                const int t = t8 + i;
                float  dtv = __half2float(s_dt[buf][t][dl]);
                float2 uzv = __half22float2(s_uz[buf][t][dl]);
                float2 bcv = __half22float2(s_bc[buf][t][s]);
                float dA = __expf(dtv * Aa);
                h = fmaf(dA, h, dtv * bcv.x * uzv.x);
                float p = h * bcv.y;
                if (s == 0) p = fmaf(uzv.x, Dd, p);
                p8[i] = p;
                g8[i] = uzv.y;
            }
            // fp16x2-packed butterfly reduction over 16 lanes (s)
            #pragma unroll
            for (int i = 0; i < 8; i += 2) {
                __half2 pp = __halves2half2(__float2half_rn(p8[i]),
                                            __float2half_rn(p8[i+1]));
                uint32_t u = *(uint32_t*)&pp;
                #pragma unroll
                for (int k = 8; k >= 1; k >>= 1) {
                    uint32_t v = __shfl_xor_sync(0xffffffffu, u, k, 16);
                    __half2 va = *(__half2*)&u, vb = *(__half2*)&v;
                    va = __hadd2(va, vb);
                    u = *(uint32_t*)&va;
                }
                if (s == 0) {
                    __half2 r = *(__half2*)&u;
                    s_y[yb][t8 + i][dl] =
                        __hmul(__low2half(r),  __float2half_rn(g8[i]));
                    s_y[yb][t8 + i + 1][dl] =
                        __hmul(__high2half(r), __float2half_rn(g8[i+1]));
                }
            }
        }
    }
    __syncthreads();
    flush_y(NST - 1, (NST - 1) & 1);
}

// ---------------- launch -------------------------------------------------------
extern "C" void kernel_launch(void* const* d_in, const int* in_sizes, int n_in,
                              void* d_out, int out_size)
{
    const float* x          = (const float*)d_in[1];
    const int*   order      = (const int*)  d_in[3];
    const int*   inv        = (const int*)  d_in[4];
    const float* W_in       = (const float*)d_in[5];
    const float* bn_in_g    = (const float*)d_in[6];
    const float* bn_in_b    = (const float*)d_in[7];
    const float* bn_in_m    = (const float*)d_in[8];
    const float* bn_in_v    = (const float*)d_in[9];
    const float* in_proj_w  = (const float*)d_in[10];
    const float* conv_w     = (const float*)d_in[11];
    const float* conv_b     = (const float*)d_in[12];
    const float* x_proj_w   = (const float*)d_in[13];
    const float* dt_proj_w  = (const float*)d_in[14];
    const float* dt_proj_b  = (const float*)d_in[15];
    const float* A_log      = (const float*)d_in[16];
    const float* Dp         = (const float*)d_in[17];
    const float* out_proj_w = (const float*)d_in[18];
    const float* W_out      = (const float*)d_in[19];
    const float* bn_o_g     = (const float*)d_in[20];
    const float* bn_o_b     = (const float*)d_in[21];
    const float* bn_o_m     = (const float*)d_in[22];
    const float* bn_o_v     = (const float*)d_in[23];
    float* out = (float*)d_out;

    __half *x16, *hg16, *xz16, *xc16, *db16, *dt16, *y16, *og16;
    __half2 *uz16, *bc16;
    __half *Winh, *iph, *xph, *dtph, *oph, *Woh;
    cudaGetSymbolAddress((void**)&x16,  g_x16);
    cudaGetSymbolAddress((void**)&hg16, g_hg16);
    cudaGetSymbolAddress((void**)&xz16, g_xz16);
    cudaGetSymbolAddress((void**)&xc16, g_xc16);
    cudaGetSymbolAddress((void**)&db16, g_db16);
    cudaGetSymbolAddress((void**)&dt16, g_dt16);
    cudaGetSymbolAddress((void**)&uz16, g_uz16);
    cudaGetSymbolAddress((void**)&bc16, g_bc16);
    cudaGetSymbolAddress((void**)&y16,  g_y16);
    cudaGetSymbolAddress((void**)&og16, g_og16);
    cudaGetSymbolAddress((void**)&Winh, g_Win_h);
    cudaGetSymbolAddress((void**)&iph,  g_ip_h);
    cudaGetSymbolAddress((void**)&xph,  g_xp_h);
    cudaGetSymbolAddress((void**)&dtph, g_dtp_h);
    cudaGetSymbolAddress((void**)&oph,  g_op_h);
    cudaGetSymbolAddress((void**)&Woh,  g_Wo_h);

    const int SMEM_BIG   = 4 * (128 + 128) * 80;   // 81920
    const int SMEM_SMALL = 4 * (64 + 64) * 80;     // 40960
    cudaFuncSetAttribute((const void*)gemm_fp16<128,128,4,2>,
                         cudaFuncAttributeMaxDynamicSharedMemorySize, SMEM_BIG);
    cudaFuncSetAttribute((const void*)gemm_fp16<64,64,2,4>,
                         cudaFuncAttributeMaxDynamicSharedMemorySize, SMEM_SMALL);

    // prep (x + weights) in one launch
    {
        const int total = NT*CC + CC*CC + 2*DIN*CC + 64*DIN + DIN*DTR + CC*DIN + CC*CC;
        prep_all_kernel<<<(total + 255) / 256, 256>>>(
            x, W_in, in_proj_w, x_proj_w, dt_proj_w, out_proj_w, W_out,
            x16, Winh, iph, xph, dtph, oph, Woh);
    }

    // 1) hg = fp16(relu(BN(x @ W_in^T))) scattered by inv  ==  h[order]
    gemm_fp16<128,128,4,2><<<dim3(CC/128, NT/128), 256, SMEM_BIG>>>(
        x16, CC, Winh, CC, nullptr, hg16, inv, CC, 1,
        bn_in_g, bn_in_b, bn_in_m, bn_in_v, nullptr);

    // 2) xz = hg @ in_proj_w^T   (fp16)
    gemm_fp16<128,128,4,2><<<dim3(2*DIN/128, NT/128), 256, SMEM_BIG>>>(
        hg16, CC, iph, CC, nullptr, xz16, nullptr, 2*DIN, 0,
        nullptr, nullptr, nullptr, nullptr, nullptr);

    // 3) xc16 + packed {u, gate}  (register-blocked, 8 rows x 2 ch / thread)
    conv_silu_kernel<<<(NT / 8) * (DIN / 2) / 256, 256>>>(
        (const __half2*)xz16, conv_w, conv_b, (__half2*)xc16, uz16);

    // 4) db16 = fp16(xc @ x_proj_w^T), N=64
    gemm_fp16<64,64,2,4><<<dim3(1, NT/64), 256, SMEM_SMALL>>>(
        xc16, DIN, xph, DIN, nullptr, db16, nullptr, 64, 0,
        nullptr, nullptr, nullptr, nullptr, nullptr);

    // 4b) pack {B,C}
    pack_bc_kernel<<<NT * DS / 256, 256>>>(db16, bc16);

    // 5) dt16 = fp16(softplus(dt_low @ dt_proj_w^T + b)), K=32 (lda=64)
    gemm_fp16<128,128,4,2><<<dim3(DIN/128, NT/128), 256, SMEM_BIG>>>(
        db16, 64, dtph, DTR, nullptr, dt16, nullptr, DIN, 2,
        dt_proj_b, nullptr, nullptr, nullptr, nullptr);

    // 6) selective scan (16 d / block) -> y (fp16)
    scan_kernel<<<dim3(DIN / SD, NB), 256>>>(dt16, bc16, uz16, A_log, Dp, y16);

    // 7) og = fp16(y @ out_proj_w^T) scattered by order == o1[inv]
    gemm_fp16<128,128,4,2><<<dim3(CC/128, NT/128), 256, SMEM_BIG>>>(
        y16, DIN, oph, DIN, nullptr, og16, order, CC, 0,
        nullptr, nullptr, nullptr, nullptr, nullptr);

    // 8) out = relu(BN(og @ W_out^T) + x)
    gemm_fp16<128,128,4,2><<<dim3(CC/128, NT/128), 256, SMEM_BIG>>>(
        og16, CC, Woh, CC, out, nullptr, nullptr, CC, 3,
        bn_o_g, bn_o_b, bn_o_m, bn_o_v, x);
}

// round 12
// speedup vs baseline: 11.5666x; 1.0716x over previous
#include <cuda_runtime.h>
#include <cuda_fp16.h>
#include <math.h>
#include <stdint.h>

// Problem constants
#define NB 4
#define LL 2048
#define CC 512
#define DIN 1024
#define DS 16
#define DCONV 4
#define DTR 32
#define NT (NB * LL)   // 8192 rows
#define EPSBN 1e-5f

// ---------------- scratch (device globals; no allocation allowed) -------------
__device__ __align__(256) __half  g_x16 [NT * CC];
__device__ __align__(256) __half  g_hg16[NT * CC];
__device__ __align__(256) __half  g_xz16[NT * 2 * DIN];
__device__ __align__(256) __half  g_xc16[NT * DIN];
__device__ __align__(256) __half  g_db16[NT * 64];
__device__ __align__(256) __half  g_dt16[NT * DIN];
__device__ __align__(256) __half2 g_uz16[NT * DIN];   // {silu(u), silu(z)}
__device__ __align__(256) float2  g_bq  [NT * 8];     // {B_2sl, B_2sl+1}
__device__ __align__(256) float2  g_cq  [NT * 8];     // {C_2sl, C_2sl+1}
__device__ __align__(256) __half  g_y16 [NT * DIN];
__device__ __align__(256) __half  g_og16[NT * CC];
// fp16 weights
__device__ __align__(256) __half g_Win_h[CC * CC];
__device__ __align__(256) __half g_ip_h [2 * DIN * CC];
__device__ __align__(256) __half g_xp_h [64 * DIN];
__device__ __align__(256) __half g_dtp_h[DIN * DTR];
__device__ __align__(256) __half g_op_h [CC * DIN];
__device__ __align__(256) __half g_Wo_h [CC * CC];

// ============================ PTX helpers =====================================
__device__ __forceinline__ uint32_t smem_u32(const void* p) {
    uint32_t a;
    asm("{ .reg .u64 t; cvta.to.shared.u64 t, %1; cvt.u32.u64 %0, t; }"
        : "=r"(a) : "l"(p));
    return a;
}
__device__ __forceinline__ void cpa16(uint32_t d, const void* s) {
    asm volatile("cp.async.cg.shared.global [%0], [%1], 16;" :: "r"(d), "l"(s));
}
#define CP_COMMIT asm volatile("cp.async.commit_group;" ::: "memory")
#define CP_WAIT1  asm volatile("cp.async.wait_group 1;"  ::: "memory")
#define CP_WAIT2  asm volatile("cp.async.wait_group 2;"  ::: "memory")

__device__ __forceinline__ void ldsm4(uint32_t* r, uint32_t a) {
    asm volatile("ldmatrix.sync.aligned.m8n8.x4.shared.b16 {%0,%1,%2,%3}, [%4];"
        : "=r"(r[0]), "=r"(r[1]), "=r"(r[2]), "=r"(r[3]) : "r"(a));
}
__device__ __forceinline__ void mma16816(float* c, const uint32_t* a, const uint32_t* b) {
    asm volatile(
        "mma.sync.aligned.m16n8k16.row.col.f32.f16.f16.f32 "
        "{%0,%1,%2,%3}, {%4,%5,%6,%7}, {%8,%9}, {%0,%1,%2,%3};"
        : "+f"(c[0]), "+f"(c[1]), "+f"(c[2]), "+f"(c[3])
        : "r"(a[0]), "r"(a[1]), "r"(a[2]), "r"(a[3]), "r"(b[0]), "r"(b[1]));
}

// ====================== single-term fp16 HMMA GEMM ============================
// (unchanged — known good)
template <int MT, int NTILE>
__device__ __forceinline__ void load_stage(
    uint32_t base, int tid, int m0, int n0, int lda, int K, int c,
    const __half* A, const __half* W)
{
    const int k0 = c * 32;
    #pragma unroll
    for (int e = 0; e < MT * 4 / 256; e++) {
        int t = tid + e * 256;
        int r = t >> 2, g = t & 3;
        cpa16(base + r * 80 + g * 16, A + (size_t)(m0 + r) * lda + k0 + g * 8);
    }
    uint32_t dw = base + (uint32_t)MT * 80;
    #pragma unroll
    for (int e = 0; e < NTILE * 4 / 256; e++) {
        int t = tid + e * 256;
        int r = t >> 2, g = t & 3;
        cpa16(dw + r * 80 + g * 16, W + (size_t)(n0 + r) * K + k0 + g * 8);
    }
}

template <int MT, int NTILE, int WMW, int WNW>
__global__ void __launch_bounds__(256, 2) gemm_fp16(
    const __half* __restrict__ A, int lda,
    const __half* __restrict__ W, int K,
    float* __restrict__ outF, __half* __restrict__ outH,
    const int* __restrict__ scat, int Ntot, int epi,
    const float* __restrict__ p0, const float* __restrict__ p1,
    const float* __restrict__ p2, const float* __restrict__ p3,
    const float* __restrict__ addsrc)
{
    constexpr int WTM = MT / WMW;
    constexpr int WTN = NTILE / WNW;
    constexpr int MTFR = WTM / 16;
    constexpr int NT8 = WTN / 8;
    constexpr int STAGE = (MT + NTILE) * 80;

    extern __shared__ __align__(128) char smraw[];
    const uint32_t sb = smem_u32(smraw);

    const int tid = threadIdx.x;
    const int lane = tid & 31, warp = tid >> 5;
    const int wm = warp % WMW, wn = warp / WMW;
    const int m0 = blockIdx.y * MT;
    const int n0 = blockIdx.x * NTILE;

    float acc[MTFR][NT8][4] = {};

    const int nch = K >> 5;
    #pragma unroll
    for (int s = 0; s < 3; s++) {
        if (s < nch)
            load_stage<MT, NTILE>(sb + s * STAGE, tid, m0, n0, lda, K, s, A, W);
        CP_COMMIT;
    }

    const int lr = lane & 15;
    const int lc = (lane >> 4) << 3;

    for (int c = 0; c < nch; c++) {
        CP_WAIT2;
        __syncthreads();
        {
            int cn = c + 3;
            if (cn < nch)
                load_stage<MT, NTILE>(sb + (cn & 3) * STAGE, tid, m0, n0, lda, K, cn, A, W);
            CP_COMMIT;
        }
        const uint32_t cur = sb + (uint32_t)(c & 3) * STAGE;
        #pragma unroll
        for (int kk = 0; kk < 32; kk += 16) {
            uint32_t af[MTFR][4];
            #pragma unroll
            for (int mt = 0; mt < MTFR; mt++)
                ldsm4(af[mt], cur + (uint32_t)((wm * WTM + mt * 16 + lr) * 80 + (kk + lc) * 2));
            uint32_t wf[NT8][2];
            #pragma unroll
            for (int p = 0; p < NT8 / 2; p++) {
                uint32_t a = cur + (uint32_t)((MT + wn * WTN + p * 16 + lr) * 80 + (kk + lc) * 2);
                uint32_t r4[4];
                ldsm4(r4, a);
                wf[2*p][0] = r4[0]; wf[2*p][1] = r4[2];
                wf[2*p+1][0] = r4[1]; wf[2*p+1][1] = r4[3];
            }
            #pragma unroll
            for (int mt = 0; mt < MTFR; mt++)
                #pragma unroll
                for (int nt = 0; nt < NT8; nt++)
                    mma16816(acc[mt][nt], af[mt], wf[nt]);
        }
    }

    const int g = lane >> 2, tg = lane & 3;
    #pragma unroll
    for (int mt = 0; mt < MTFR; mt++)
        #pragma unroll
        for (int nt = 0; nt < NT8; nt++)
            #pragma unroll
            for (int rr = 0; rr < 2; rr++) {
                int m = m0 + wm * WTM + mt * 16 + g + rr * 8;
                int n = n0 + wn * WTN + nt * 8 + tg * 2;
                int mo = scat ? scat[m] : m;
                float v0 = acc[mt][nt][rr * 2 + 0];
                float v1 = acc[mt][nt][rr * 2 + 1];
                if (epi == 1) {
                    v0 = fmaxf((v0 - p2[n])   * rsqrtf(p3[n]   + EPSBN) * p0[n]   + p1[n],   0.f);
                    v1 = fmaxf((v1 - p2[n+1]) * rsqrtf(p3[n+1] + EPSBN) * p0[n+1] + p1[n+1], 0.f);
                } else if (epi == 2) {
                    v0 += p0[n];   v0 = (v0 > 20.f) ? v0 : __logf(1.f + __expf(v0));
                    v1 += p0[n+1]; v1 = (v1 > 20.f) ? v1 : __logf(1.f + __expf(v1));
                } else if (epi == 3) {
                    v0 = (v0 - p2[n])   * rsqrtf(p3[n]   + EPSBN) * p0[n]   + p1[n];
                    v1 = (v1 - p2[n+1]) * rsqrtf(p3[n+1] + EPSBN) * p0[n+1] + p1[n+1];
                    v0 = fmaxf(v0 + addsrc[(size_t)mo * Ntot + n], 0.f);
                    v1 = fmaxf(v1 + addsrc[(size_t)mo * Ntot + n + 1], 0.f);
                }
                const size_t ob = (size_t)mo * Ntot + n;
                if (outF) *(float2*)&outF[ob] = make_float2(v0, v1);
                if (outH)
                    *(__half2*)&outH[ob] =
                        __halves2half2(__float2half_rn(v0), __float2half_rn(v1));
            }
}

// ====================== prep (x + all weights -> fp16), one launch ============
__global__ void __launch_bounds__(256) prep_all_kernel(
    const float* __restrict__ x,
    const float* __restrict__ Win, const float* __restrict__ ip,
    const float* __restrict__ xp,  const float* __restrict__ dtp,
    const float* __restrict__ op,  const float* __restrict__ Wo,
    __half* __restrict__ dx,
    __half* __restrict__ dWin, __half* __restrict__ dip,
    __half* __restrict__ dxp,  __half* __restrict__ ddtp,
    __half* __restrict__ dop,  __half* __restrict__ dWo)
{
    const int sx = NT * CC, s0 = CC * CC, s1 = 2 * DIN * CC, s2 = 64 * DIN,
              s3 = DIN * DTR, s4 = CC * DIN;
    int i = blockIdx.x * blockDim.x + threadIdx.x;
    if (i < sx) { dx[i]   = __float2half_rn(x[i]);   return; } i -= sx;
    if (i < s0) { dWin[i] = __float2half_rn(Win[i]); return; } i -= s0;
    if (i < s1) { dip[i]  = __float2half_rn(ip[i]);  return; } i -= s1;
    if (i < s2) { dxp[i]  = __float2half_rn(xp[i]);  return; } i -= s2;
    if (i < s3) { ddtp[i] = __float2half_rn(dtp[i]); return; } i -= s3;
    if (i < s4) { dop[i]  = __float2half_rn(op[i]);  return; } i -= s4;
    dWo[i] = __float2half_rn(Wo[i]);
}

// BC pack: db16[row][32+2sl..] -> bq[row][sl] = {B_2sl, B_2sl+1} (fp32), cq same
__global__ void __launch_bounds__(256) pack_bc_kernel(
    const __half* __restrict__ db16, float2* __restrict__ bq,
    float2* __restrict__ cq)
{
    int i = blockIdx.x * blockDim.x + threadIdx.x;   // over NT*8
    int sl = i & 7, row = i >> 3;
    const __half* p = db16 + (size_t)row * 64 + DTR;
    bq[i] = make_float2(__half2float(p[2*sl]),      __half2float(p[2*sl + 1]));
    cq[i] = make_float2(__half2float(p[DS + 2*sl]), __half2float(p[DS + 2*sl + 1]));
}

// ---------- depthwise causal conv: register-blocked 8 rows x 2 channels -------
__global__ void __launch_bounds__(256) conv_silu_kernel(
    const __half2* __restrict__ xz2,
    const float* __restrict__ cw, const float* __restrict__ cb,
    __half2* __restrict__ xch2, __half2* __restrict__ uz)
{
    int g   = blockIdx.x * blockDim.x + threadIdx.x;  // over (NT/8)*(DIN/2)
    int dp  = g & (DIN / 2 - 1);
    int rg  = g >> 9;
    int row0 = rg * 8;
    int l0   = row0 & (LL - 1);
    int d    = dp * 2;

    const float bx  = cb[d],     by  = cb[d + 1];
    const float c0x = cw[d*4+0], c1x = cw[d*4+1], c2x = cw[d*4+2], c3x = cw[d*4+3];
    const float c0y = cw[d*4+4], c1y = cw[d*4+5], c2y = cw[d*4+6], c3y = cw[d*4+7];

    float2 w[11];
    #pragma unroll
    for (int j = 0; j < 11; j++) {
        int l = l0 - 3 + j;
        w[j] = (l >= 0)
             ? __half22float2(xz2[(long)(row0 - 3 + j) * DIN + dp])
             : make_float2(0.f, 0.f);
    }

    #pragma unroll
    for (int i = 0; i < 8; i++) {
        const long row = row0 + i;
        float ax = bx, ay = by;
        ax = fmaf(c0x, w[i].x,   ax); ay = fmaf(c0y, w[i].y,   ay);
        ax = fmaf(c1x, w[i+1].x, ax); ay = fmaf(c1y, w[i+1].y, ay);
        ax = fmaf(c2x, w[i+2].x, ax); ay = fmaf(c2y, w[i+2].y, ay);
        ax = fmaf(c3x, w[i+3].x, ax); ay = fmaf(c3y, w[i+3].y, ay);

        float ux = __fdividef(ax, 1.f + __expf(-ax));
        float uy = __fdividef(ay, 1.f + __expf(-ay));
        float2 zf = __half22float2(xz2[row * DIN + DIN / 2 + dp]);
        float gx = __fdividef(zf.x, 1.f + __expf(-zf.x));
        float gy = __fdividef(zf.y, 1.f + __expf(-zf.y));

        xch2[row * (DIN / 2) + dp] =
            __halves2half2(__float2half_rn(ux), __float2half_rn(uy));
        __half2 a = __halves2half2(__float2half_rn(ux), __float2half_rn(gx));
        __half2 b = __halves2half2(__float2half_rn(uy), __float2half_rn(gy));
        uint2 pk = make_uint2(*(uint32_t*)&a, *(uint32_t*)&b);
        *(uint2*)&uz[row * DIN + d] = pk;
    }
}

// ---------------- selective scan: 2 states/lane, 4 d/warp ---------------------
// Block: 64 thr = 2 warps; warp = 4 d x 8 s-lanes; each lane owns 2 fp32 states.
// Block covers 8 d. Grid (DIN/8=128, NB) = 512 blocks.
#define SD 8
#define ST 64

__global__ void __launch_bounds__(64) scan_kernel(
    const __half* __restrict__ dtg, const float2* __restrict__ bqg,
    const float2* __restrict__ cqg, const __half2* __restrict__ uzg,
    const float* __restrict__ A_log, const float* __restrict__ Dp,
    __half* __restrict__ yh)
{
    __shared__ __align__(16) __half  s_dt[3][ST][SD];
    __shared__ __align__(16) __half2 s_uz[3][ST][SD];
    __shared__ __align__(16) float2  s_b[3][ST][8];
    __shared__ __align__(16) float2  s_c[3][ST][8];
    __shared__ __align__(16) __half  s_y[2][ST][SD];

    const int tid  = threadIdx.x;
    const int warp = tid >> 5, lane = tid & 31;
    const int sl   = lane & 7, dl = lane >> 3;     // dl in 0..3
    const int dg   = warp * 4 + dl;                // 0..7 in block
    const int d0   = blockIdx.x * SD;
    const int d    = d0 + dg;
    const long rbase = (long)blockIdx.y * LL;

    const float A0 = -expf(A_log[d * DS + 2 * sl]);
    const float A1 = -expf(A_log[d * DS + 2 * sl + 1]);
    const float Dd = Dp[d];

    auto stage_load = [&](int st, int buf) {
        const long row0 = rbase + (long)st * ST;
        for (int j = tid; j < 704; j += 64) {
            if (j < 64) {                        // dt: 64 rows x 16B
                cpa16(smem_u32(&s_dt[buf][j][0]), dtg + (row0 + j) * DIN + d0);
            } else if (j < 192) {                // uz: 64 rows x 32B
                int u = j - 64, r = u >> 1, q = u & 1;
                cpa16(smem_u32(&s_uz[buf][r][q * 4]),
                      uzg + (row0 + r) * DIN + d0 + q * 4);
            } else if (j < 448) {                // b: 64 rows x 64B
                int v = j - 192, r = v >> 2, q = v & 3;
                cpa16(smem_u32(&s_b[buf][r][q * 2]), bqg + (row0 + r) * 8 + q * 2);
            } else {                             // c: 64 rows x 64B
                int v = j - 448, r = v >> 2, q = v & 3;
                cpa16(smem_u32(&s_c[buf][r][q * 2]), cqg + (row0 + r) * 8 + q * 2);
            }
        }
    };
    auto flush_y = [&](int st, int yb) {
        const long row0 = rbase + (long)st * ST;
        // 64 rows x 16B = 256 u32 / 64 thr
        #pragma unroll
        for (int j0 = 0; j0 < 256; j0 += 64) {
            int j = tid + j0;
            int r = j >> 2, w = j & 3;
            uint32_t val = ((const uint32_t*)&s_y[yb][r][0])[w];
            *(uint32_t*)(yh + (row0 + r) * DIN + d0 + w * 2) = val;
        }
    };

    stage_load(0, 0); CP_COMMIT;
    stage_load(1, 1); CP_COMMIT;

    float h0 = 0.f, h1 = 0.f;
    const int NST = LL / ST;   // 32
    for (int ts = 0; ts < NST; ts++) {
        CP_WAIT1;
        __syncthreads();
        if (ts > 0) flush_y(ts - 1, (ts - 1) & 1);
        const int buf = ts % 3;
        if (ts + 2 < NST) stage_load(ts + 2, (ts + 2) % 3);
        CP_COMMIT;

        const int yb = ts & 1;
        #pragma unroll
        for (int t8 = 0; t8 < ST; t8 += 8) {
            float p8[8], g8[8];
            #pragma unroll
            for (int i = 0; i < 8; i++) {
                const int t = t8 + i;
                float  dtv = __half2float(s_dt[buf][t][dg]);
                float2 uzv = __half22float2(s_uz[buf][t][dg]);
                float2 bv  = s_b[buf][t][sl];
                float2 cv  = s_c[buf][t][sl];
                float dA0 = __expf(dtv * A0);
                float dA1 = __expf(dtv * A1);
                float cx = dtv * uzv.x;
                h0 = fmaf(dA0, h0, cx * bv.x);
                h1 = fmaf(dA1, h1, cx * bv.y);
                float p = fmaf(h1, cv.y, h0 * cv.x);
                if (sl == 0) p = fmaf(uzv.x, Dd, p);
                p8[i] = p;
                g8[i] = uzv.y;
            }
            // fp16x2-packed butterfly reduction over 8 lanes (sl)
            #pragma unroll
            for (int i = 0; i < 8; i += 2) {
                __half2 pp = __halves2half2(__float2half_rn(p8[i]),
                                            __float2half_rn(p8[i+1]));
                uint32_t u = *(uint32_t*)&pp;
                #pragma unroll
                for (int k = 4; k >= 1; k >>= 1) {
                    uint32_t v = __shfl_xor_sync(0xffffffffu, u, k, 8);
                    __half2 va = *(__half2*)&u, vb = *(__half2*)&v;
                    va = __hadd2(va, vb);
                    u = *(uint32_t*)&va;
                }
                if (sl == 0) {
                    __half2 r = *(__half2*)&u;
                    s_y[yb][t8 + i][dg] =
                        __hmul(__low2half(r),  __float2half_rn(g8[i]));
                    s_y[yb][t8 + i + 1][dg] =
                        __hmul(__high2half(r), __float2half_rn(g8[i+1]));
                }
            }
        }
    }
    __syncthreads();
    flush_y(NST - 1, (NST - 1) & 1);
}

// ---------------- launch -------------------------------------------------------
extern "C" void kernel_launch(void* const* d_in, const int* in_sizes, int n_in,
                              void* d_out, int out_size)
{
    const float* x          = (const float*)d_in[1];
    const int*   order      = (const int*)  d_in[3];
    const int*   inv        = (const int*)  d_in[4];
    const float* W_in       = (const float*)d_in[5];
    const float* bn_in_g    = (const float*)d_in[6];
    const float* bn_in_b    = (const float*)d_in[7];
    const float* bn_in_m    = (const float*)d_in[8];
    const float* bn_in_v    = (const float*)d_in[9];
    const float* in_proj_w  = (const float*)d_in[10];
    const float* conv_w     = (const float*)d_in[11];
    const float* conv_b     = (const float*)d_in[12];
    const float* x_proj_w   = (const float*)d_in[13];
    const float* dt_proj_w  = (const float*)d_in[14];
    const float* dt_proj_b  = (const float*)d_in[15];
    const float* A_log      = (const float*)d_in[16];
    const float* Dp         = (const float*)d_in[17];
    const float* out_proj_w = (const float*)d_in[18];
    const float* W_out      = (const float*)d_in[19];
    const float* bn_o_g     = (const float*)d_in[20];
    const float* bn_o_b     = (const float*)d_in[21];
    const float* bn_o_m     = (const float*)d_in[22];
    const float* bn_o_v     = (const float*)d_in[23];
    float* out = (float*)d_out;

    __half *x16, *hg16, *xz16, *xc16, *db16, *dt16, *y16, *og16;
    __half2 *uz16;
    float2 *bq, *cq;
    __half *Winh, *iph, *xph, *dtph, *oph, *Woh;
    cudaGetSymbolAddress((void**)&x16,  g_x16);
    cudaGetSymbolAddress((void**)&hg16, g_hg16);
    cudaGetSymbolAddress((void**)&xz16, g_xz16);
    cudaGetSymbolAddress((void**)&xc16, g_xc16);
    cudaGetSymbolAddress((void**)&db16, g_db16);
    cudaGetSymbolAddress((void**)&dt16, g_dt16);
    cudaGetSymbolAddress((void**)&uz16, g_uz16);
    cudaGetSymbolAddress((void**)&bq,   g_bq);
    cudaGetSymbolAddress((void**)&cq,   g_cq);
    cudaGetSymbolAddress((void**)&y16,  g_y16);
    cudaGetSymbolAddress((void**)&og16, g_og16);
    cudaGetSymbolAddress((void**)&Winh, g_Win_h);
    cudaGetSymbolAddress((void**)&iph,  g_ip_h);
    cudaGetSymbolAddress((void**)&xph,  g_xp_h);
    cudaGetSymbolAddress((void**)&dtph, g_dtp_h);
    cudaGetSymbolAddress((void**)&oph,  g_op_h);
    cudaGetSymbolAddress((void**)&Woh,  g_Wo_h);

    const int SMEM_BIG   = 4 * (128 + 128) * 80;   // 81920
    const int SMEM_SMALL = 4 * (64 + 64) * 80;     // 40960
    cudaFuncSetAttribute((const void*)gemm_fp16<128,128,4,2>,
                         cudaFuncAttributeMaxDynamicSharedMemorySize, SMEM_BIG);
    cudaFuncSetAttribute((const void*)gemm_fp16<64,64,2,4>,
                         cudaFuncAttributeMaxDynamicSharedMemorySize, SMEM_SMALL);

    // prep (x + weights) in one launch
    {
        const int total = NT*CC + CC*CC + 2*DIN*CC + 64*DIN + DIN*DTR + CC*DIN + CC*CC;
        prep_all_kernel<<<(total + 255) / 256, 256>>>(
            x, W_in, in_proj_w, x_proj_w, dt_proj_w, out_proj_w, W_out,
            x16, Winh, iph, xph, dtph, oph, Woh);
    }

    // 1) hg = fp16(relu(BN(x @ W_in^T))) scattered by inv  ==  h[order]
    gemm_fp16<128,128,4,2><<<dim3(CC/128, NT/128), 256, SMEM_BIG>>>(
        x16, CC, Winh, CC, nullptr, hg16, inv, CC, 1,
        bn_in_g, bn_in_b, bn_in_m, bn_in_v, nullptr);

    // 2) xz = hg @ in_proj_w^T   (fp16)
    gemm_fp16<128,128,4,2><<<dim3(2*DIN/128, NT/128), 256, SMEM_BIG>>>(
        hg16, CC, iph, CC, nullptr, xz16, nullptr, 2*DIN, 0,
        nullptr, nullptr, nullptr, nullptr, nullptr);

    // 3) xc16 + packed {u, gate}
    conv_silu_kernel<<<(NT / 8) * (DIN / 2) / 256, 256>>>(
        (const __half2*)xz16, conv_w, conv_b, (__half2*)xc16, uz16);

    // 4) db16 = fp16(xc @ x_proj_w^T), N=64
    gemm_fp16<64,64,2,4><<<dim3(1, NT/64), 256, SMEM_SMALL>>>(
        xc16, DIN, xph, DIN, nullptr, db16, nullptr, 64, 0,
        nullptr, nullptr, nullptr, nullptr, nullptr);

    // 4b) pack {B,C} pairs (fp32)
    pack_bc_kernel<<<NT * 8 / 256, 256>>>(db16, bq, cq);

    // 5) dt16 = fp16(softplus(dt_low @ dt_proj_w^T + b)), K=32 (lda=64)
    gemm_fp16<128,128,4,2><<<dim3(DIN/128, NT/128), 256, SMEM_BIG>>>(
        db16, 64, dtph, DTR, nullptr, dt16, nullptr, DIN, 2,
        dt_proj_b, nullptr, nullptr, nullptr, nullptr);

    // 6) selective scan (2 states/lane, 4 d/warp) -> y (fp16)
    scan_kernel<<<dim3(DIN / SD, NB), 64>>>(dt16, bq, cq, uz16, A_log, Dp, y16);

    // 7) og = fp16(y @ out_proj_w^T) scattered by order == o1[inv]
    gemm_fp16<128,128,4,2><<<dim3(CC/128, NT/128), 256, SMEM_BIG>>>(
        y16, DIN, oph, DIN, nullptr, og16, order, CC, 0,
        nullptr, nullptr, nullptr, nullptr, nullptr);

    // 8) out = relu(BN(og @ W_out^T) + x)
    gemm_fp16<128,128,4,2><<<dim3(CC/128, NT/128), 256, SMEM_BIG>>>(
        og16, CC, Woh, CC, out, nullptr, nullptr, CC, 3,
        bn_o_g, bn_o_b, bn_o_m, bn_o_v, x);
}